// round 2
// baseline (speedup 1.0000x reference)
#include <cuda_runtime.h>

// Problem constants (fixed by setup_inputs)
#define BQ   33
#define BBSZ 1089
#define NS   8
#define NH   8
#define NL   8
#define NCOL 512        // NL*NH*NS
#define MROW 272
#define HP   264        // NH*33 == NL*33
#define IMGPIX (NS*HP*HP)   // 557568 == BBSZ*NCOL

// ---------------- scratch (device globals; no allocation allowed) -----------
__device__ float g_X[BBSZ * NCOL];
__device__ float g_y[MROW * NCOL];
__device__ float g_r[MROW * NCOL];
__device__ float g_z[BBSZ * NCOL];       // also used as Xb and deblock output
__device__ float g_noise[BBSZ * NCOL];
__device__ float g_AtA[BBSZ * BBSZ];
__device__ float g_im[IMGPIX];
__device__ float g_t1[(size_t)NCOL * 32 * BBSZ];  // 17,842,176 floats
__device__ float g_t2[(size_t)NCOL * 32 * BBSZ];

// ---------------- blockify / unblockify -------------------------------------
// Xb[r,n] = img[s, h*33+i, l*33+j],  r=i*33+j, n=l*64+h*8+s
__global__ void blockify_input_kernel(const float* __restrict__ in, float* __restrict__ Xb) {
    int idx = blockIdx.x * blockDim.x + threadIdx.x;
    if (idx >= BBSZ * NCOL) return;
    int r = idx / NCOL, n = idx % NCOL;
    int i = r / BQ, j = r % BQ;
    int l = n / (NH * NS), h = (n / NS) % NH, s = n % NS;
    Xb[idx] = in[(s * HP + h * BQ + i) * HP + l * BQ + j];
}

__global__ void unblockify_kernel(const float* __restrict__ X, float* __restrict__ img) {
    int idx = blockIdx.x * blockDim.x + threadIdx.x;
    if (idx >= IMGPIX) return;
    int s = idx / (HP * HP);
    int rem = idx % (HP * HP);
    int R = rem / HP, C = rem % HP;
    int h = R / BQ, i = R % BQ, l = C / BQ, j = C % BQ;
    img[idx] = X[(i * BQ + j) * NCOL + (l * (NH * NS) + h * NS + s)];
}

// X = blockify(img - db)
__global__ void blockify_sub_kernel(const float* __restrict__ img,
                                    const float* __restrict__ db,
                                    float* __restrict__ X) {
    int idx = blockIdx.x * blockDim.x + threadIdx.x;
    if (idx >= IMGPIX) return;
    int s = idx / (HP * HP);
    int rem = idx % (HP * HP);
    int R = rem / HP, C = rem % HP;
    int h = R / BQ, i = R % BQ, l = C / BQ, j = C % BQ;
    X[(i * BQ + j) * NCOL + (l * (NH * NS) + h * NS + s)] = img[idx] - db[idx];
}

// ---------------- generic tiled fp32 GEMM with fused epilogues --------------
// C[M,N] = epilogue(acc)  where acc = opA(A) @ B
//  transA=0: A is [M,K] row-major with lda
//  transA=1: A element (m,k) = A[k*lda + m]
//  B is [K,N] row-major (ldb = N), C is [M,N] (ldc = N)
// epi: 0: C = acc
//      1: C = E1 - acc
//      2: C = step*acc + E1
//      3: C = E1 - step*acc + E2
#define GBM 64
#define GBN 64
#define GBK 16
__global__ void gemm_kernel(const float* __restrict__ A, const float* __restrict__ B,
                            float* __restrict__ C,
                            int M, int N, int K, int lda, int transA,
                            int epi, const float* __restrict__ E1,
                            const float* __restrict__ E2,
                            const float* __restrict__ stepsPtr, int stepIdx) {
    __shared__ float As[GBK][GBM];
    __shared__ float Bs[GBK][GBN + 1];
    int bm = blockIdx.y * GBM, bn = blockIdx.x * GBN;
    int tid = threadIdx.x;
    int tx = tid % 16, ty = tid / 16;

    float acc[4][4];
#pragma unroll
    for (int i = 0; i < 4; i++)
#pragma unroll
        for (int j = 0; j < 4; j++) acc[i][j] = 0.f;

    for (int k0 = 0; k0 < K; k0 += GBK) {
        if (transA) {
            for (int e = tid; e < GBM * GBK; e += 256) {
                int k = e / GBM, m = e % GBM;
                int gm = bm + m, gk = k0 + k;
                As[k][m] = (gm < M && gk < K) ? A[(size_t)gk * lda + gm] : 0.f;
            }
        } else {
            for (int e = tid; e < GBM * GBK; e += 256) {
                int m = e / GBK, k = e % GBK;
                int gm = bm + m, gk = k0 + k;
                As[k][m] = (gm < M && gk < K) ? A[(size_t)gm * lda + gk] : 0.f;
            }
        }
        for (int e = tid; e < GBK * GBN; e += 256) {
            int k = e / GBN, n = e % GBN;
            int gk = k0 + k, gn = bn + n;
            Bs[k][n] = (gk < K && gn < N) ? B[(size_t)gk * N + gn] : 0.f;
        }
        __syncthreads();
#pragma unroll
        for (int k = 0; k < GBK; k++) {
            float a[4], b[4];
#pragma unroll
            for (int i = 0; i < 4; i++) a[i] = As[k][ty * 4 + i];
#pragma unroll
            for (int j = 0; j < 4; j++) b[j] = Bs[k][tx * 4 + j];
#pragma unroll
            for (int i = 0; i < 4; i++)
#pragma unroll
                for (int j = 0; j < 4; j++) acc[i][j] += a[i] * b[j];
        }
        __syncthreads();
    }

    float step = (stepsPtr != nullptr) ? stepsPtr[stepIdx] : 0.f;
#pragma unroll
    for (int i = 0; i < 4; i++) {
        int gm = bm + ty * 4 + i;
        if (gm >= M) continue;
#pragma unroll
        for (int j = 0; j < 4; j++) {
            int gn = bn + tx * 4 + j;
            if (gn >= N) continue;
            size_t idx = (size_t)gm * N + gn;
            float v = acc[i][j];
            float o;
            if (epi == 0)      o = v;
            else if (epi == 1) o = E1[idx] - v;
            else if (epi == 2) o = step * v + E1[idx];
            else               o = E1[idx] - step * v + E2[idx];
            C[idx] = o;
        }
    }
}

// ---------------- generic 3x3 SAME conv, 33x33 tiles -------------------------
// Block: one 33x33 output tile of one image, COPB output channels.
// 363 threads, 3 pixels each. Input channel staged in smem (35x35 halo).
// inTrans: input is single-channel, stored column-major [pix, NCOL] (denoise in)
// outTrans: output is single-channel, stored column-major (denoise noise out)
template <int COPB>
__global__ void conv3x3_kernel(const float* __restrict__ in,
                               const float* __restrict__ wt,
                               const float* __restrict__ bias,
                               float* __restrict__ out,
                               int Cin, int Cout,
                               int Himg, int Wimg, int tilesX, int tilesY,
                               int relu, int inTrans, int outTrans) {
    __shared__ float s_in[35 * 35];
    __shared__ float s_w[COPB * 9];

    int tpi = tilesX * tilesY;
    int n    = blockIdx.x / tpi;
    int trem = blockIdx.x % tpi;
    int ty0 = (trem / tilesX) * BQ;
    int tx0 = (trem % tilesX) * BQ;
    int ocBase = blockIdx.y * COPB;
    int tid = threadIdx.x;

    float acc[3][COPB];
#pragma unroll
    for (int pp = 0; pp < 3; pp++)
#pragma unroll
        for (int oc = 0; oc < COPB; oc++) acc[pp][oc] = 0.f;

    for (int c = 0; c < Cin; c++) {
        __syncthreads();
        for (int q = tid; q < 35 * 35; q += 363) {
            int gi = ty0 + q / 35 - 1;
            int gj = tx0 + q % 35 - 1;
            float v = 0.f;
            if (gi >= 0 && gi < Himg && gj >= 0 && gj < Wimg) {
                if (inTrans) v = in[(size_t)(gi * Wimg + gj) * NCOL + n];
                else         v = in[((size_t)(n * Cin + c) * Himg + gi) * Wimg + gj];
            }
            s_in[q] = v;
        }
        for (int q = tid; q < COPB * 9; q += 363)
            s_w[q] = wt[((size_t)(ocBase + q / 9) * Cin + c) * 9 + (q % 9)];
        __syncthreads();

        float v[3][9];
#pragma unroll
        for (int pp = 0; pp < 3; pp++) {
            int p = tid + pp * 363;
            int i = p / BQ, j = p % BQ;
#pragma unroll
            for (int di = 0; di < 3; di++)
#pragma unroll
                for (int dj = 0; dj < 3; dj++)
                    v[pp][di * 3 + dj] = s_in[(i + di) * 35 + (j + dj)];
        }
#pragma unroll
        for (int oc = 0; oc < COPB; oc++) {
            float w[9];
#pragma unroll
            for (int r = 0; r < 9; r++) w[r] = s_w[oc * 9 + r];
#pragma unroll
            for (int pp = 0; pp < 3; pp++) {
                float s = 0.f;
#pragma unroll
                for (int r = 0; r < 9; r++) s += v[pp][r] * w[r];
                acc[pp][oc] += s;
            }
        }
    }

#pragma unroll
    for (int pp = 0; pp < 3; pp++) {
        int p = tid + pp * 363;
        int i = p / BQ, j = p % BQ;
        int gi = ty0 + i, gj = tx0 + j;
#pragma unroll
        for (int oc = 0; oc < COPB; oc++) {
            float bv = (bias != nullptr) ? bias[ocBase + oc] : 0.f;
            float v = acc[pp][oc] + bv;
            if (relu) v = fmaxf(v, 0.f);
            if (outTrans)
                out[(size_t)(gi * Wimg + gj) * NCOL + n] = v;
            else
                out[((size_t)(n * Cout + ocBase + oc) * Himg + gi) * Wimg + gj] = v;
        }
    }
}

// ---------------- host driver ------------------------------------------------
extern "C" void kernel_launch(void* const* d_in, const int* in_sizes, int n_in,
                              void* d_out, int out_size) {
    const float* inputs = (const float*)d_in[0];
    const float* A      = (const float*)d_in[1];
    const float* Q      = (const float*)d_in[2];
    const float* steps  = (const float*)d_in[3];
    const float* den_w1 = (const float*)d_in[4];
    const float* den_b1 = (const float*)d_in[5];
    const float* den_w2 = (const float*)d_in[6];
    const float* den_b2 = (const float*)d_in[7];
    const float* den_w3 = (const float*)d_in[8];
    const float* den_b3 = (const float*)d_in[9];
    const float* den_w4 = (const float*)d_in[10];
    const float* deb_w1 = (const float*)d_in[11];
    const float* deb_b1 = (const float*)d_in[12];
    const float* deb_w2 = (const float*)d_in[13];
    const float* deb_b2 = (const float*)d_in[14];
    const float* deb_w3 = (const float*)d_in[15];
    const float* deb_b3 = (const float*)d_in[16];
    const float* deb_w4 = (const float*)d_in[17];
    int layers = in_sizes[3];  // steps element count == output_layers in setup

    float *pX, *pY, *pR, *pZ, *pN, *pAtA, *pIm, *pT1, *pT2;
    cudaGetSymbolAddress((void**)&pX, g_X);
    cudaGetSymbolAddress((void**)&pY, g_y);
    cudaGetSymbolAddress((void**)&pR, g_r);
    cudaGetSymbolAddress((void**)&pZ, g_z);
    cudaGetSymbolAddress((void**)&pN, g_noise);
    cudaGetSymbolAddress((void**)&pAtA, g_AtA);
    cudaGetSymbolAddress((void**)&pIm, g_im);
    cudaGetSymbolAddress((void**)&pT1, g_t1);
    cudaGetSymbolAddress((void**)&pT2, g_t2);

    const int EW = 256;
    const int EG = (IMGPIX + EW - 1) / EW;

    dim3 gN512M272((NCOL + GBN - 1) / GBN, (MROW + GBM - 1) / GBM);   // (8,5)
    dim3 gN512M1089((NCOL + GBN - 1) / GBN, (BBSZ + GBM - 1) / GBM);  // (8,18)
    dim3 gAtA((BBSZ + GBN - 1) / GBN, (BBSZ + GBM - 1) / GBM);        // (18,18)

    // ---- init: Xb, y = A@Xb, X = Q@y, AtA = A^T@A ----
    blockify_input_kernel<<<EG, EW>>>(inputs, pZ);
    gemm_kernel<<<gN512M272, 256>>>(A, pZ, pY, MROW, NCOL, BBSZ, BBSZ, 0, 0,
                                    nullptr, nullptr, nullptr, 0);
    gemm_kernel<<<gN512M1089, 256>>>(Q, pY, pX, BBSZ, NCOL, MROW, MROW, 0, 0,
                                     nullptr, nullptr, nullptr, 0);
    gemm_kernel<<<gAtA, 256>>>(A, A, pAtA, BBSZ, BBSZ, MROW, BBSZ, 1, 0,
                               nullptr, nullptr, nullptr, 0);

    dim3 cgrid32(NCOL, 4);   // 512 tiles x 4 oc-groups of 8
    dim3 cgrid1(NCOL, 1);

    for (int n = 0; n < layers; n++) {
        // r = y - A@X
        gemm_kernel<<<gN512M272, 256>>>(A, pX, pR, MROW, NCOL, BBSZ, BBSZ, 0, 1,
                                        pY, nullptr, nullptr, 0);
        // z = step*(A^T@r) + X
        gemm_kernel<<<gN512M1089, 256>>>(A, pR, pZ, BBSZ, NCOL, MROW, BBSZ, 1, 2,
                                         pX, nullptr, steps, n);
        // denoise CNN on X (column-layout input, 512 images of 33x33)
        conv3x3_kernel<8><<<cgrid32, 363>>>(pX, den_w1 + (size_t)n * 32 * 9,
                                            den_b1 + n * 32, pT1, 1, 32,
                                            BQ, BQ, 1, 1, 1, 1, 0);
        conv3x3_kernel<8><<<cgrid32, 363>>>(pT1, den_w2 + (size_t)n * 32 * 32 * 9,
                                            den_b2 + n * 32, pT2, 32, 32,
                                            BQ, BQ, 1, 1, 1, 0, 0);
        conv3x3_kernel<8><<<cgrid32, 363>>>(pT2, den_w3 + (size_t)n * 32 * 32 * 9,
                                            den_b3 + n * 32, pT1, 32, 32,
                                            BQ, BQ, 1, 1, 1, 0, 0);
        conv3x3_kernel<1><<<cgrid1, 363>>>(pT1, den_w4 + (size_t)n * 32 * 9,
                                           nullptr, pN, 32, 1,
                                           BQ, BQ, 1, 1, 0, 0, 1);
        // X = z - step*(AtA@noise) + noise
        gemm_kernel<<<gN512M1089, 256>>>(pAtA, pN, pX, BBSZ, NCOL, BBSZ, BBSZ, 0, 3,
                                         pZ, pN, steps, n);
        // img = unblockify(X)
        unblockify_kernel<<<EG, EW>>>(pX, pIm);
        // deblock CNN on img (8 images of 264x264, 8x8 tiles of 33x33)
        conv3x3_kernel<8><<<cgrid32, 363>>>(pIm, deb_w1 + (size_t)n * 32 * 9,
                                            deb_b1 + n * 32, pT1, 1, 32,
                                            HP, HP, 8, 8, 1, 0, 0);
        conv3x3_kernel<8><<<cgrid32, 363>>>(pT1, deb_w2 + (size_t)n * 32 * 32 * 9,
                                            deb_b2 + n * 32, pT2, 32, 32,
                                            HP, HP, 8, 8, 1, 0, 0);
        conv3x3_kernel<8><<<cgrid32, 363>>>(pT2, deb_w3 + (size_t)n * 32 * 32 * 9,
                                            deb_b3 + n * 32, pT1, 32, 32,
                                            HP, HP, 8, 8, 1, 0, 0);
        conv3x3_kernel<1><<<cgrid1, 363>>>(pT1, deb_w4 + (size_t)n * 32 * 9,
                                           nullptr, pZ, 32, 1,
                                           HP, HP, 8, 8, 0, 0, 0);
        // X = blockify(img - deblock_out)
        blockify_sub_kernel<<<EG, EW>>>(pIm, pZ, pX);
    }

    unblockify_kernel<<<EG, EW>>>(pX, (float*)d_out);
}

// round 4
// speedup vs baseline: 1.3749x; 1.3749x over previous
#include <cuda_runtime.h>
#include <cuda_fp16.h>
#include <cstdint>

#define BQ   33
#define BBSZ 1089
#define NS   8
#define NH   8
#define NL   8
#define NCOL 512
#define MROW 272
#define HP   264
#define IMGPIX (NS*HP*HP)

// ---------------- scratch ----------------------------------------------------
__device__ float g_X[BBSZ * NCOL];
__device__ float g_y[MROW * NCOL];
__device__ float g_r[MROW * NCOL];
__device__ float g_z[BBSZ * NCOL];
__device__ float g_noise[BBSZ * NCOL];
__device__ float g_AtA[BBSZ * BBSZ];
__device__ float g_im[IMGPIX];
__device__ float g_t1[(size_t)NCOL * 32 * BBSZ];
__device__ float g_t2[(size_t)NCOL * 32 * BBSZ];

// ---------------- HMMA helpers ------------------------------------------------
#define HMMA16816(c, a0, a1, a2, a3, b0, b1) \
    asm volatile("mma.sync.aligned.m16n8k16.row.col.f32.f16.f16.f32 " \
        "{%0,%1,%2,%3}, {%4,%5,%6,%7}, {%8,%9}, {%0,%1,%2,%3};" \
        : "+f"((c)[0]), "+f"((c)[1]), "+f"((c)[2]), "+f"((c)[3]) \
        : "r"(a0), "r"(a1), "r"(a2), "r"(a3), "r"(b0), "r"(b1))

__device__ __forceinline__ uint32_t h2bits(__half2 h) {
    return *reinterpret_cast<uint32_t*>(&h);
}
// pack (x,y) into fp16 hi pair; lo pair = residuals
__device__ __forceinline__ uint32_t pack_split(float x, float y, uint32_t& lo) {
    __half2 h = __floats2half2_rn(x, y);
    __half2 l = __floats2half2_rn(x - __low2float(h), y - __high2float(h));
    lo = h2bits(l);
    return h2bits(h);
}

// ---------------- HMMA implicit-GEMM conv: 32ch in -> 32 (or 1) ch out --------
// MODE 0: 512 imgs 33x33, tile = 128 linear pixels (9 tiles/img)
// MODE 1: 8 imgs 264x264, tile = 16x8 px (17x33 tiles/img)
// OUTM 0: 32ch NCHW + bias + relu
// OUTM 1: 1ch col-major out[p*NCOL + n]      (denoise conv4)
// OUTM 2: 1ch image  out[n*HP*HP + oy*HP+ox] (deblock conv4)
// D[128 px, OC] = sum_k A[px,k] * W[oc,k],  k = tap*32 + ic, K = 288 = 18 x k16.
// fp16 hi/lo split on both operands (3 MMAs) -> ~fp32 accuracy.
#define WPK (144 * 33)          // u32 entries for packed weights (kp-major, pad 33)
#define SM_HALO 38016           // byte offset of halo region ( = 2*WPK*4 )

template<int MODE, int OUTM>
__global__ void conv_hmma_kernel(const float* __restrict__ in,
                                 const float* __restrict__ wt,
                                 const float* __restrict__ bias,
                                 float* __restrict__ out) {
    extern __shared__ char smem[];
    uint32_t* wh = (uint32_t*)smem;          // [144][33] half2 hi
    uint32_t* wl = wh + WPK;                 // [144][33] half2 lo
    constexpr int HSTR = (MODE == 0) ? 231 : 180;
    float* hsm = (float*)(smem + SM_HALO);   // [32][HSTR]
    constexpr int NT = (OUTM == 0) ? 4 : 1;

    const int tid = threadIdx.x;             // 256
    const int wid = tid >> 5;
    const int lane = tid & 31;
    const int rg = lane >> 2;                // group id 0..7
    const int kq = (lane & 3) * 2;           // 0,2,4,6

    int n_img, p0 = 0, y_first = 0, y0t = 0, x0t = 0;
    if (MODE == 0) {
        n_img = blockIdx.x / 9;
        p0 = (blockIdx.x % 9) * 128;
        y_first = p0 / 33;
    } else {
        int b = blockIdx.x;
        int tx = b % 33; b /= 33;
        int ty = b % 17; b /= 17;
        n_img = b; y0t = ty * 16; x0t = tx * 8;
    }

    // ---- pre-pack weights: wh/wl[kp*33 + oc] = half2(w[2kp], w[2kp+1]) ----
    constexpr int COUTR = (OUTM == 0) ? 32 : 1;
    for (int e = tid; e < 144 * 32; e += 256) {
        int kp = e >> 5, oc = e & 31;
        int k0 = 2 * kp;
        int tap = k0 >> 5, ic = k0 & 31;     // k0 even -> k0,k0+1 same tap
        float w0 = 0.f, w1 = 0.f;
        if (oc < COUTR) {
            w0 = wt[(oc * 32 + ic) * 9 + tap];
            w1 = wt[(oc * 32 + ic + 1) * 9 + tap];
        }
        uint32_t lo;
        uint32_t hi = pack_split(w0, w1, lo);
        wh[kp * 33 + oc] = hi;
        wl[kp * 33 + oc] = lo;
    }

    // ---- halo load (fp32, zero-filled at borders) ----
    if (MODE == 0) {
        for (int e = tid; e < 32 * 231; e += 256) {
            int ic = e / 231, rem = e % 231;
            int gy = y_first - 1 + rem / 33;
            float v = (gy >= 0 && gy < 33)
                ? in[(size_t)(n_img * 32 + ic) * BBSZ + gy * 33 + rem % 33] : 0.f;
            hsm[e] = v;
        }
    } else {
        for (int e = tid; e < 32 * 180; e += 256) {
            int ic = e / 180, rem = e % 180;
            int gy = y0t - 1 + rem / 10, gx = x0t - 1 + rem % 10;
            float v = (gy >= 0 && gy < 264 && gx >= 0 && gx < 264)
                ? in[((size_t)(n_img * 32 + ic) * 264 + gy) * 264 + gx] : 0.f;
            hsm[e] = v;
        }
    }
    __syncthreads();

    // ---- per-thread pixel precompute (rows m_lo, m_hi = m_lo+8) ----
    int m_lo = wid * 16 + rg;
    int m_hi = m_lo + 8;
    int ylo = 0, xlo = 0, yhi = 0, xhi = 0;
    bool pvlo = true, pvhi = true;
    if (MODE == 0) {
        int pl = p0 + m_lo, ph = p0 + m_hi;
        pvlo = pl < BBSZ; pvhi = ph < BBSZ;
        int yl = pl / 33, yh = ph / 33;
        xlo = pl - yl * 33; xhi = ph - yh * 33;
        ylo = yl - y_first; yhi = yh - y_first;   // halo row base (add di)
    } else {
        ylo = m_lo >> 3; xlo = m_lo & 7;
        yhi = m_hi >> 3; xhi = m_hi & 7;
    }

    float acc[NT][4];
#pragma unroll
    for (int nt = 0; nt < NT; nt++)
#pragma unroll
        for (int i = 0; i < 4; i++) acc[nt][i] = 0.f;

    // gather helper
    auto gA = [&](int yb, int x, bool pv, int k) -> float {
        int tap = k >> 5, ic = k & 31;
        int di = tap / 3, dj = tap - 3 * di;
        if (MODE == 0) {
            int xt = x + dj - 1;
            bool ok = pv && ((unsigned)xt < 33u);
            float v = hsm[ic * 231 + (yb + di) * 33 + (ok ? xt : 0)];
            return ok ? v : 0.f;
        } else {
            return hsm[ic * 180 + (yb + di) * 10 + (x + dj)];
        }
    };

    for (int c = 0; c < 18; c++) {
        int k0 = c * 16 + kq;
        // A fragments (hi/lo)
        uint32_t a0l, a1l, a2l, a3l;
        uint32_t a0h = pack_split(gA(ylo, xlo, pvlo, k0),     gA(ylo, xlo, pvlo, k0 + 1), a0l);
        uint32_t a1h = pack_split(gA(yhi, xhi, pvhi, k0),     gA(yhi, xhi, pvhi, k0 + 1), a1l);
        uint32_t a2h = pack_split(gA(ylo, xlo, pvlo, k0 + 8), gA(ylo, xlo, pvlo, k0 + 9), a2l);
        uint32_t a3h = pack_split(gA(yhi, xhi, pvhi, k0 + 8), gA(yhi, xhi, pvhi, k0 + 9), a3l);

        int kp0 = c * 8 + (lane & 3);
#pragma unroll
        for (int nt = 0; nt < NT; nt++) {
            int ocb = nt * 8 + rg;
            uint32_t bh0 = wh[kp0 * 33 + ocb];
            uint32_t bh1 = wh[(kp0 + 4) * 33 + ocb];
            uint32_t bl0 = wl[kp0 * 33 + ocb];
            uint32_t bl1 = wl[(kp0 + 4) * 33 + ocb];
            HMMA16816(acc[nt], a0h, a1h, a2h, a3h, bh0, bh1);
            HMMA16816(acc[nt], a0h, a1h, a2h, a3h, bl0, bl1);
            HMMA16816(acc[nt], a0l, a1l, a2l, a3l, bh0, bh1);
        }
    }

    // ---- epilogue ----
    if (OUTM == 0) {
        __syncthreads();                 // weights no longer needed
        float* sbuf = (float*)smem;      // [32][132]
#pragma unroll
        for (int nt = 0; nt < NT; nt++) {
            int oc = nt * 8 + kq;
            sbuf[oc * 132 + m_lo]       = acc[nt][0];
            sbuf[(oc + 1) * 132 + m_lo] = acc[nt][1];
            sbuf[oc * 132 + m_hi]       = acc[nt][2];
            sbuf[(oc + 1) * 132 + m_hi] = acc[nt][3];
        }
        __syncthreads();
        int oc = tid >> 3;
        float bv = bias[oc];
#pragma unroll
        for (int i = 0; i < 16; i++) {
            int m = (tid & 7) + 8 * i;
            float v = fmaxf(sbuf[oc * 132 + m] + bv, 0.f);
            if (MODE == 0) {
                int p = p0 + m;
                if (p < BBSZ)
                    out[(size_t)(n_img * 32 + oc) * BBSZ + p] = v;
            } else {
                int oy = y0t + (m >> 3), ox = x0t + (m & 7);
                if (oy < 264)
                    out[((size_t)(n_img * 32 + oc) * 264 + oy) * 264 + ox] = v;
            }
        }
    } else {
        if (kq == 0) {   // oc 0 lives in lanes with lane%4 == 0, regs 0 (m_lo) and 2 (m_hi)
            if (MODE == 0) {
                int pl = p0 + m_lo, ph = p0 + m_hi;
                if (pl < BBSZ) out[(size_t)pl * NCOL + n_img] = acc[0][0];
                if (ph < BBSZ) out[(size_t)ph * NCOL + n_img] = acc[0][2];
            } else {
                int oyl = y0t + ylo, oyh = y0t + yhi;
                if (oyl < 264) out[(size_t)n_img * HP * HP + oyl * 264 + (x0t + xlo)] = acc[0][0];
                if (oyh < 264) out[(size_t)n_img * HP * HP + oyh * 264 + (x0t + xhi)] = acc[0][2];
            }
        }
    }
}

// ---------------- blockify / unblockify ---------------------------------------
__global__ void blockify_input_kernel(const float* __restrict__ in, float* __restrict__ Xb) {
    int idx = blockIdx.x * blockDim.x + threadIdx.x;
    if (idx >= BBSZ * NCOL) return;
    int r = idx / NCOL, n = idx % NCOL;
    int i = r / BQ, j = r % BQ;
    int l = n / (NH * NS), h = (n / NS) % NH, s = n % NS;
    Xb[idx] = in[(s * HP + h * BQ + i) * HP + l * BQ + j];
}
__global__ void unblockify_kernel(const float* __restrict__ X, float* __restrict__ img) {
    int idx = blockIdx.x * blockDim.x + threadIdx.x;
    if (idx >= IMGPIX) return;
    int s = idx / (HP * HP);
    int rem = idx % (HP * HP);
    int R = rem / HP, C = rem % HP;
    int h = R / BQ, i = R % BQ, l = C / BQ, j = C % BQ;
    img[idx] = X[(i * BQ + j) * NCOL + (l * (NH * NS) + h * NS + s)];
}
__global__ void blockify_sub_kernel(const float* __restrict__ img,
                                    const float* __restrict__ db,
                                    float* __restrict__ X) {
    int idx = blockIdx.x * blockDim.x + threadIdx.x;
    if (idx >= IMGPIX) return;
    int s = idx / (HP * HP);
    int rem = idx % (HP * HP);
    int R = rem / HP, C = rem % HP;
    int h = R / BQ, i = R % BQ, l = C / BQ, j = C % BQ;
    X[(i * BQ + j) * NCOL + (l * (NH * NS) + h * NS + s)] = img[idx] - db[idx];
}

// ---------------- SIMT GEMM with fused epilogues -------------------------------
#define GBM 64
#define GBN 64
#define GBK 16
__global__ void gemm_kernel(const float* __restrict__ A, const float* __restrict__ B,
                            float* __restrict__ C,
                            int M, int N, int K, int lda, int transA,
                            int epi, const float* __restrict__ E1,
                            const float* __restrict__ E2,
                            const float* __restrict__ stepsPtr, int stepIdx) {
    __shared__ float As[GBK][GBM];
    __shared__ float Bs[GBK][GBN + 1];
    int bm = blockIdx.y * GBM, bn = blockIdx.x * GBN;
    int tid = threadIdx.x;
    int tx = tid % 16, ty = tid / 16;
    float acc[4][4];
#pragma unroll
    for (int i = 0; i < 4; i++)
#pragma unroll
        for (int j = 0; j < 4; j++) acc[i][j] = 0.f;
    for (int k0 = 0; k0 < K; k0 += GBK) {
        if (transA) {
            for (int e = tid; e < GBM * GBK; e += 256) {
                int k = e / GBM, mm = e % GBM;
                int gm = bm + mm, gk = k0 + k;
                As[k][mm] = (gm < M && gk < K) ? A[(size_t)gk * lda + gm] : 0.f;
            }
        } else {
            for (int e = tid; e < GBM * GBK; e += 256) {
                int mm = e / GBK, k = e % GBK;
                int gm = bm + mm, gk = k0 + k;
                As[k][mm] = (gm < M && gk < K) ? A[(size_t)gm * lda + gk] : 0.f;
            }
        }
        for (int e = tid; e < GBK * GBN; e += 256) {
            int k = e / GBN, nn = e % GBN;
            int gk = k0 + k, gn = bn + nn;
            Bs[k][nn] = (gk < K && gn < N) ? B[(size_t)gk * N + gn] : 0.f;
        }
        __syncthreads();
#pragma unroll
        for (int k = 0; k < GBK; k++) {
            float a[4], b[4];
#pragma unroll
            for (int i = 0; i < 4; i++) a[i] = As[k][ty * 4 + i];
#pragma unroll
            for (int j = 0; j < 4; j++) b[j] = Bs[k][tx * 4 + j];
#pragma unroll
            for (int i = 0; i < 4; i++)
#pragma unroll
                for (int j = 0; j < 4; j++) acc[i][j] += a[i] * b[j];
        }
        __syncthreads();
    }
    float step = (stepsPtr != nullptr) ? stepsPtr[stepIdx] : 0.f;
#pragma unroll
    for (int i = 0; i < 4; i++) {
        int gm = bm + ty * 4 + i;
        if (gm >= M) continue;
#pragma unroll
        for (int j = 0; j < 4; j++) {
            int gn = bn + tx * 4 + j;
            if (gn >= N) continue;
            size_t idx = (size_t)gm * N + gn;
            float v = acc[i][j], o;
            if (epi == 0)      o = v;
            else if (epi == 1) o = E1[idx] - v;
            else if (epi == 2) o = step * v + E1[idx];
            else               o = E1[idx] - step * v + E2[idx];
            C[idx] = o;
        }
    }
}

// ---------------- SIMT conv (used only for conv1: Cin=1 -> 32) ----------------
template <int COPB>
__global__ void conv3x3_kernel(const float* __restrict__ in,
                               const float* __restrict__ wt,
                               const float* __restrict__ bias,
                               float* __restrict__ out,
                               int Cin, int Cout,
                               int Himg, int Wimg, int tilesX, int tilesY,
                               int relu, int inTrans, int outTrans) {
    __shared__ float s_in[35 * 35];
    __shared__ float s_w[COPB * 9];
    int tpi = tilesX * tilesY;
    int n = blockIdx.x / tpi;
    int trem = blockIdx.x % tpi;
    int ty0 = (trem / tilesX) * BQ;
    int tx0 = (trem % tilesX) * BQ;
    int ocBase = blockIdx.y * COPB;
    int tid = threadIdx.x;
    float acc[3][COPB];
#pragma unroll
    for (int pp = 0; pp < 3; pp++)
#pragma unroll
        for (int oc = 0; oc < COPB; oc++) acc[pp][oc] = 0.f;
    for (int c = 0; c < Cin; c++) {
        __syncthreads();
        for (int q = tid; q < 35 * 35; q += 363) {
            int gi = ty0 + q / 35 - 1;
            int gj = tx0 + q % 35 - 1;
            float v = 0.f;
            if (gi >= 0 && gi < Himg && gj >= 0 && gj < Wimg) {
                if (inTrans) v = in[(size_t)(gi * Wimg + gj) * NCOL + n];
                else         v = in[((size_t)(n * Cin + c) * Himg + gi) * Wimg + gj];
            }
            s_in[q] = v;
        }
        for (int q = tid; q < COPB * 9; q += 363)
            s_w[q] = wt[((size_t)(ocBase + q / 9) * Cin + c) * 9 + (q % 9)];
        __syncthreads();
        float v[3][9];
#pragma unroll
        for (int pp = 0; pp < 3; pp++) {
            int p = tid + pp * 363;
            int i = p / BQ, j = p % BQ;
#pragma unroll
            for (int di = 0; di < 3; di++)
#pragma unroll
                for (int dj = 0; dj < 3; dj++)
                    v[pp][di * 3 + dj] = s_in[(i + di) * 35 + (j + dj)];
        }
#pragma unroll
        for (int oc = 0; oc < COPB; oc++) {
            float w[9];
#pragma unroll
            for (int r = 0; r < 9; r++) w[r] = s_w[oc * 9 + r];
#pragma unroll
            for (int pp = 0; pp < 3; pp++) {
                float s = 0.f;
#pragma unroll
                for (int r = 0; r < 9; r++) s += v[pp][r] * w[r];
                acc[pp][oc] += s;
            }
        }
    }
#pragma unroll
    for (int pp = 0; pp < 3; pp++) {
        int p = tid + pp * 363;
        int i = p / BQ, j = p % BQ;
        int gi = ty0 + i, gj = tx0 + j;
#pragma unroll
        for (int oc = 0; oc < COPB; oc++) {
            float bv = (bias != nullptr) ? bias[ocBase + oc] : 0.f;
            float v = acc[pp][oc] + bv;
            if (relu) v = fmaxf(v, 0.f);
            if (outTrans) out[(size_t)(gi * Wimg + gj) * NCOL + n] = v;
            else out[((size_t)(n * Cout + ocBase + oc) * Himg + gi) * Wimg + gj] = v;
        }
    }
}

// ---------------- host driver --------------------------------------------------
extern "C" void kernel_launch(void* const* d_in, const int* in_sizes, int n_in,
                              void* d_out, int out_size) {
    const float* inputs = (const float*)d_in[0];
    const float* A      = (const float*)d_in[1];
    const float* Q      = (const float*)d_in[2];
    const float* steps  = (const float*)d_in[3];
    const float* den_w1 = (const float*)d_in[4];
    const float* den_b1 = (const float*)d_in[5];
    const float* den_w2 = (const float*)d_in[6];
    const float* den_b2 = (const float*)d_in[7];
    const float* den_w3 = (const float*)d_in[8];
    const float* den_b3 = (const float*)d_in[9];
    const float* den_w4 = (const float*)d_in[10];
    const float* deb_w1 = (const float*)d_in[11];
    const float* deb_b1 = (const float*)d_in[12];
    const float* deb_w2 = (const float*)d_in[13];
    const float* deb_b2 = (const float*)d_in[14];
    const float* deb_w3 = (const float*)d_in[15];
    const float* deb_b3 = (const float*)d_in[16];
    const float* deb_w4 = (const float*)d_in[17];
    int layers = in_sizes[3];

    float *pX, *pY, *pR, *pZ, *pN, *pAtA, *pIm, *pT1, *pT2;
    cudaGetSymbolAddress((void**)&pX, g_X);
    cudaGetSymbolAddress((void**)&pY, g_y);
    cudaGetSymbolAddress((void**)&pR, g_r);
    cudaGetSymbolAddress((void**)&pZ, g_z);
    cudaGetSymbolAddress((void**)&pN, g_noise);
    cudaGetSymbolAddress((void**)&pAtA, g_AtA);
    cudaGetSymbolAddress((void**)&pIm, g_im);
    cudaGetSymbolAddress((void**)&pT1, g_t1);
    cudaGetSymbolAddress((void**)&pT2, g_t2);

    const int EW = 256;
    const int EG = (IMGPIX + EW - 1) / EW;
    dim3 gN512M272((NCOL + GBN - 1) / GBN, (MROW + GBM - 1) / GBM);
    dim3 gN512M1089((NCOL + GBN - 1) / GBN, (BBSZ + GBM - 1) / GBM);
    dim3 gAtA((BBSZ + GBN - 1) / GBN, (BBSZ + GBM - 1) / GBM);

    const int SM0 = SM_HALO + 32 * 231 * 4;   // 38016 + 29568 = 67584
    const int SM1 = SM_HALO + 32 * 180 * 4;   // 38016 + 23040 = 61056
    cudaFuncSetAttribute(conv_hmma_kernel<0,0>, cudaFuncAttributeMaxDynamicSharedMemorySize, SM0);
    cudaFuncSetAttribute(conv_hmma_kernel<0,1>, cudaFuncAttributeMaxDynamicSharedMemorySize, SM0);
    cudaFuncSetAttribute(conv_hmma_kernel<1,0>, cudaFuncAttributeMaxDynamicSharedMemorySize, SM1);
    cudaFuncSetAttribute(conv_hmma_kernel<1,2>, cudaFuncAttributeMaxDynamicSharedMemorySize, SM1);

    blockify_input_kernel<<<EG, EW>>>(inputs, pZ);
    gemm_kernel<<<gN512M272, 256>>>(A, pZ, pY, MROW, NCOL, BBSZ, BBSZ, 0, 0,
                                    nullptr, nullptr, nullptr, 0);
    gemm_kernel<<<gN512M1089, 256>>>(Q, pY, pX, BBSZ, NCOL, MROW, MROW, 0, 0,
                                     nullptr, nullptr, nullptr, 0);
    gemm_kernel<<<gAtA, 256>>>(A, A, pAtA, BBSZ, BBSZ, MROW, BBSZ, 1, 0,
                               nullptr, nullptr, nullptr, 0);

    dim3 cgrid32(NCOL, 4);
    const int G0 = NCOL * 9;          // 4608 denoise tiles
    const int G1 = 8 * 17 * 33;       // 4488 deblock tiles

    for (int n = 0; n < layers; n++) {
        gemm_kernel<<<gN512M272, 256>>>(A, pX, pR, MROW, NCOL, BBSZ, BBSZ, 0, 1,
                                        pY, nullptr, nullptr, 0);
        gemm_kernel<<<gN512M1089, 256>>>(A, pR, pZ, BBSZ, NCOL, MROW, BBSZ, 1, 2,
                                         pX, nullptr, steps, n);
        // denoise: conv1 SIMT, conv2/3/4 HMMA
        conv3x3_kernel<8><<<cgrid32, 363>>>(pX, den_w1 + (size_t)n * 32 * 9,
                                            den_b1 + n * 32, pT1, 1, 32,
                                            BQ, BQ, 1, 1, 1, 1, 0);
        conv_hmma_kernel<0,0><<<G0, 256, SM0>>>(pT1, den_w2 + (size_t)n * 32 * 32 * 9,
                                                den_b2 + n * 32, pT2);
        conv_hmma_kernel<0,0><<<G0, 256, SM0>>>(pT2, den_w3 + (size_t)n * 32 * 32 * 9,
                                                den_b3 + n * 32, pT1);
        conv_hmma_kernel<0,1><<<G0, 256, SM0>>>(pT1, den_w4 + (size_t)n * 32 * 9,
                                                nullptr, pN);
        gemm_kernel<<<gN512M1089, 256>>>(pAtA, pN, pX, BBSZ, NCOL, BBSZ, BBSZ, 0, 3,
                                         pZ, pN, steps, n);
        unblockify_kernel<<<EG, EW>>>(pX, pIm);
        // deblock: conv1 SIMT, conv2/3/4 HMMA
        conv3x3_kernel<8><<<cgrid32, 363>>>(pIm, deb_w1 + (size_t)n * 32 * 9,
                                            deb_b1 + n * 32, pT1, 1, 32,
                                            HP, HP, 8, 8, 1, 0, 0);
        conv_hmma_kernel<1,0><<<G1, 256, SM1>>>(pT1, deb_w2 + (size_t)n * 32 * 32 * 9,
                                                deb_b2 + n * 32, pT2);
        conv_hmma_kernel<1,0><<<G1, 256, SM1>>>(pT2, deb_w3 + (size_t)n * 32 * 32 * 9,
                                                deb_b3 + n * 32, pT1);
        conv_hmma_kernel<1,2><<<G1, 256, SM1>>>(pT1, deb_w4 + (size_t)n * 32 * 9,
                                                nullptr, pZ);
        blockify_sub_kernel<<<EG, EW>>>(pIm, pZ, pX);
    }

    unblockify_kernel<<<EG, EW>>>(pX, (float*)d_out);
}

// round 5
// speedup vs baseline: 1.4035x; 1.0208x over previous
#include <cuda_runtime.h>
#include <cuda_fp16.h>
#include <cstdint>

#define BQ   33
#define BBSZ 1089
#define NS   8
#define NH   8
#define NL   8
#define NCOL 512
#define MROW 272
#define HP   264
#define IMGPIX (NS*HP*HP)

// ---------------- scratch ----------------------------------------------------
__device__ float g_X[BBSZ * NCOL];
__device__ float g_y[MROW * NCOL];
__device__ float g_r[MROW * NCOL];
__device__ float g_z[BBSZ * NCOL];
__device__ float g_noise[BBSZ * NCOL];
__device__ float g_AtA[BBSZ * BBSZ];
__device__ float g_im[IMGPIX];
__device__ float g_t1[(size_t)NCOL * 32 * BBSZ];
__device__ float g_t2[(size_t)NCOL * 32 * BBSZ];

// ---------------- HMMA helpers ------------------------------------------------
#define HMMA16816(c, a0, a1, a2, a3, b0, b1) \
    asm volatile("mma.sync.aligned.m16n8k16.row.col.f32.f16.f16.f32 " \
        "{%0,%1,%2,%3}, {%4,%5,%6,%7}, {%8,%9}, {%0,%1,%2,%3};" \
        : "+f"((c)[0]), "+f"((c)[1]), "+f"((c)[2]), "+f"((c)[3]) \
        : "r"(a0), "r"(a1), "r"(a2), "r"(a3), "r"(b0), "r"(b1))

__device__ __forceinline__ uint32_t h2bits(__half2 h) {
    return *reinterpret_cast<uint32_t*>(&h);
}
// pack (x,y) into fp16 hi pair; lo pair = residuals
__device__ __forceinline__ uint32_t pack_split(float x, float y, uint32_t& lo) {
    __half2 h = __floats2half2_rn(x, y);
    __half2 l = __floats2half2_rn(x - __low2float(h), y - __high2float(h));
    lo = h2bits(l);
    return h2bits(h);
}

// ---------------- HMMA implicit-GEMM conv: 32ch in -> 32 (or 1) ch out --------
// MODE 0: 512 imgs 33x33, tile = 128 linear pixels (9 tiles/img), halo 7x35/pair
// MODE 1: 8 imgs 264x264, tile = 16x8 px (17x33 tiles/img), halo 18x10/pair
// OUTM 0: 32ch NCHW + bias + relu
// OUTM 1: 1ch col-major out[p*NCOL + n]
// OUTM 2: 1ch image  out[n*HP*HP + oy*HP+ox]
// K = 288 (tap-major, k = tap*32+ic). Halo pre-split into fp16 hi/lo half2
// channel pairs so one LDS.32 = one complete A fragment register.
#define WBYTES (144 * 33 * 8)    // interleaved (hi,lo) weight pairs

template<int MODE, int OUTM>
__global__ void conv_hmma_kernel(const float* __restrict__ in,
                                 const float* __restrict__ wt,
                                 const float* __restrict__ bias,
                                 float* __restrict__ out) {
    extern __shared__ char smem[];
    uint2* wsm = (uint2*)smem;                        // [144][33] (hi,lo)
    constexpr int PSTR = (MODE == 0) ? 245 : 180;     // words per pair-plane
    constexpr int WROW = (MODE == 0) ? 35 : 10;       // halo row width
    uint32_t* hhi = (uint32_t*)(smem + WBYTES);       // [16][PSTR]
    uint32_t* hlo = hhi + 16 * PSTR;
    constexpr int NT = (OUTM == 0) ? 4 : 1;

    const int tid = threadIdx.x;     // 256
    const int wid = tid >> 5;
    const int lane = tid & 31;
    const int rg = lane >> 2;
    const int l3 = lane & 3;
    const int kq = l3 * 2;

    int n_img, p0 = 0, y_first = 0, y0t = 0, x0t = 0;
    if (MODE == 0) {
        n_img = blockIdx.x / 9;
        p0 = (blockIdx.x % 9) * 128;
        y_first = p0 / 33;
    } else {
        int b = blockIdx.x;
        int tx = b % 33; b /= 33;
        int ty = b % 17; b /= 17;
        n_img = b; y0t = ty * 16; x0t = tx * 8;
    }

    // ---- weights: wsm[kp*33+oc] = (hi,lo) of half2(w[2kp], w[2kp+1]) ----
    constexpr int COUTR = (OUTM == 0) ? 32 : 1;
    for (int e = tid; e < 144 * 32; e += 256) {
        int kp = e >> 5, oc = e & 31;
        int k0 = 2 * kp;
        int tap = k0 >> 5, ic = k0 & 31;
        float w0 = 0.f, w1 = 0.f;
        if (oc < COUTR) {
            w0 = wt[(oc * 32 + ic) * 9 + tap];
            w1 = wt[(oc * 32 + ic + 1) * 9 + tap];
        }
        uint32_t lo;
        uint32_t hi = pack_split(w0, w1, lo);
        wsm[kp * 33 + oc] = make_uint2(hi, lo);
    }

    // ---- halo load + hi/lo split, channel-pair packed ----
    if (MODE == 0) {
        for (int e = tid; e < 16 * 245; e += 256) {
            int pair = e / 245, pos = e % 245;
            int row = pos / 35, xp = pos % 35;
            int gy = y_first - 1 + row, gx = xp - 1;
            bool ok = (gy >= 0) && (gy < 33) && (xp >= 1) && (xp < 34);
            size_t bi = (size_t)(n_img * 32 + 2 * pair) * BBSZ + gy * 33 + gx;
            float f0 = ok ? in[bi] : 0.f;
            float f1 = ok ? in[bi + BBSZ] : 0.f;
            uint32_t lo;
            hhi[e] = pack_split(f0, f1, lo);
            hlo[e] = lo;
        }
    } else {
        for (int e = tid; e < 16 * 180; e += 256) {
            int pair = e / 180, pos = e % 180;
            int row = pos / 10, xp = pos % 10;
            int gy = y0t - 1 + row, gx = x0t - 1 + xp;
            bool ok = (gy >= 0) && (gy < 264) && (gx >= 0) && (gx < 264);
            size_t bi = (size_t)(n_img * 32 + 2 * pair) * 264 * 264 + gy * 264 + gx;
            float f0 = ok ? in[bi] : 0.f;
            float f1 = ok ? in[bi + 264 * 264] : 0.f;
            uint32_t lo;
            hhi[e] = pack_split(f0, f1, lo);
            hlo[e] = lo;
        }
    }
    __syncthreads();

    // ---- per-thread pixel bases ----
    int m_lo = wid * 16 + rg;
    int m_hi = m_lo + 8;
    int base_lo, base_hi;
    if (MODE == 0) {
        int pl = p0 + m_lo, ph = p0 + m_hi;
        int yl = pl / 33, yh = ph / 33;
        base_lo = (pl < BBSZ) ? (yl - y_first) * 35 + (pl - yl * 33) : 0;
        base_hi = (ph < BBSZ) ? (yh - y_first) * 35 + (ph - yh * 33) : 0;
    } else {
        base_lo = (m_lo >> 3) * 10 + (m_lo & 7);
        base_hi = (m_hi >> 3) * 10 + (m_hi & 7);
    }
    const uint32_t* phi_lo = hhi + l3 * PSTR + base_lo;
    const uint32_t* phi_hi = hhi + l3 * PSTR + base_hi;
    const uint32_t* plo_lo = hlo + l3 * PSTR + base_lo;
    const uint32_t* plo_hi = hlo + l3 * PSTR + base_hi;

    float acc[NT][4];
#pragma unroll
    for (int nt = 0; nt < NT; nt++)
#pragma unroll
        for (int i = 0; i < 4; i++) acc[nt][i] = 0.f;

#pragma unroll
    for (int t = 0; t < 9; t++) {
        const int toff = (t / 3) * WROW + (t % 3);
#pragma unroll
        for (int e2 = 0; e2 < 2; e2++) {
            const int c = 2 * t + e2;
            const int pb = e2 * 8 * PSTR + toff;
            uint32_t a0h = phi_lo[pb];
            uint32_t a1h = phi_hi[pb];
            uint32_t a2h = phi_lo[pb + 4 * PSTR];
            uint32_t a3h = phi_hi[pb + 4 * PSTR];
            uint32_t a0l = plo_lo[pb];
            uint32_t a1l = plo_hi[pb];
            uint32_t a2l = plo_lo[pb + 4 * PSTR];
            uint32_t a3l = plo_hi[pb + 4 * PSTR];
            const int kp0 = c * 8 + l3;
#pragma unroll
            for (int nt = 0; nt < NT; nt++) {
                uint2 b0 = wsm[kp0 * 33 + nt * 8 + rg];
                uint2 b1 = wsm[(kp0 + 4) * 33 + nt * 8 + rg];
                HMMA16816(acc[nt], a0h, a1h, a2h, a3h, b0.x, b1.x);
                HMMA16816(acc[nt], a0h, a1h, a2h, a3h, b0.y, b1.y);
                HMMA16816(acc[nt], a0l, a1l, a2l, a3l, b0.x, b1.x);
            }
        }
    }

    // ---- epilogue ----
    if (OUTM == 0) {
        __syncthreads();
        float* sbuf = (float*)smem;      // [32][132], fits in weight region
#pragma unroll
        for (int nt = 0; nt < NT; nt++) {
            int oc = nt * 8 + kq;
            sbuf[oc * 132 + m_lo]       = acc[nt][0];
            sbuf[(oc + 1) * 132 + m_lo] = acc[nt][1];
            sbuf[oc * 132 + m_hi]       = acc[nt][2];
            sbuf[(oc + 1) * 132 + m_hi] = acc[nt][3];
        }
        __syncthreads();
        int oc = tid >> 3;
        float bv = bias[oc];
#pragma unroll
        for (int i = 0; i < 16; i++) {
            int m = (tid & 7) + 8 * i;
            float v = fmaxf(sbuf[oc * 132 + m] + bv, 0.f);
            if (MODE == 0) {
                int p = p0 + m;
                if (p < BBSZ)
                    out[(size_t)(n_img * 32 + oc) * BBSZ + p] = v;
            } else {
                int oy = y0t + (m >> 3), ox = x0t + (m & 7);
                if (oy < 264)
                    out[((size_t)(n_img * 32 + oc) * 264 + oy) * 264 + ox] = v;
            }
        }
    } else {
        if (l3 == 0) {
            if (MODE == 0) {
                int pl = p0 + m_lo, ph = p0 + m_hi;
                if (pl < BBSZ) out[(size_t)pl * NCOL + n_img] = acc[0][0];
                if (ph < BBSZ) out[(size_t)ph * NCOL + n_img] = acc[0][2];
            } else {
                int oyl = y0t + (m_lo >> 3), oyh = y0t + (m_hi >> 3);
                if (oyl < 264)
                    out[(size_t)n_img * HP * HP + oyl * 264 + x0t + (m_lo & 7)] = acc[0][0];
                if (oyh < 264)
                    out[(size_t)n_img * HP * HP + oyh * 264 + x0t + (m_hi & 7)] = acc[0][2];
            }
        }
    }
}

// ---------------- blockify / unblockify ---------------------------------------
__global__ void blockify_input_kernel(const float* __restrict__ in, float* __restrict__ Xb) {
    int idx = blockIdx.x * blockDim.x + threadIdx.x;
    if (idx >= BBSZ * NCOL) return;
    int r = idx / NCOL, n = idx % NCOL;
    int i = r / BQ, j = r % BQ;
    int l = n / (NH * NS), h = (n / NS) % NH, s = n % NS;
    Xb[idx] = in[(s * HP + h * BQ + i) * HP + l * BQ + j];
}
__global__ void unblockify_kernel(const float* __restrict__ X, float* __restrict__ img) {
    int idx = blockIdx.x * blockDim.x + threadIdx.x;
    if (idx >= IMGPIX) return;
    int s = idx / (HP * HP);
    int rem = idx % (HP * HP);
    int R = rem / HP, C = rem % HP;
    int h = R / BQ, i = R % BQ, l = C / BQ, j = C % BQ;
    img[idx] = X[(i * BQ + j) * NCOL + (l * (NH * NS) + h * NS + s)];
}
__global__ void blockify_sub_kernel(const float* __restrict__ img,
                                    const float* __restrict__ db,
                                    float* __restrict__ X) {
    int idx = blockIdx.x * blockDim.x + threadIdx.x;
    if (idx >= IMGPIX) return;
    int s = idx / (HP * HP);
    int rem = idx % (HP * HP);
    int R = rem / HP, C = rem % HP;
    int h = R / BQ, i = R % BQ, l = C / BQ, j = C % BQ;
    X[(i * BQ + j) * NCOL + (l * (NH * NS) + h * NS + s)] = img[idx] - db[idx];
}

// ---------------- SIMT GEMM with fused epilogues -------------------------------
#define GBM 64
#define GBN 64
#define GBK 16
__global__ void gemm_kernel(const float* __restrict__ A, const float* __restrict__ B,
                            float* __restrict__ C,
                            int M, int N, int K, int lda, int transA,
                            int epi, const float* __restrict__ E1,
                            const float* __restrict__ E2,
                            const float* __restrict__ stepsPtr, int stepIdx) {
    __shared__ float As[GBK][GBM];
    __shared__ float Bs[GBK][GBN + 1];
    int bm = blockIdx.y * GBM, bn = blockIdx.x * GBN;
    int tid = threadIdx.x;
    int tx = tid % 16, ty = tid / 16;
    float acc[4][4];
#pragma unroll
    for (int i = 0; i < 4; i++)
#pragma unroll
        for (int j = 0; j < 4; j++) acc[i][j] = 0.f;
    for (int k0 = 0; k0 < K; k0 += GBK) {
        if (transA) {
            for (int e = tid; e < GBM * GBK; e += 256) {
                int k = e / GBM, mm = e % GBM;
                int gm = bm + mm, gk = k0 + k;
                As[k][mm] = (gm < M && gk < K) ? A[(size_t)gk * lda + gm] : 0.f;
            }
        } else {
            for (int e = tid; e < GBM * GBK; e += 256) {
                int mm = e / GBK, k = e % GBK;
                int gm = bm + mm, gk = k0 + k;
                As[k][mm] = (gm < M && gk < K) ? A[(size_t)gm * lda + gk] : 0.f;
            }
        }
        for (int e = tid; e < GBK * GBN; e += 256) {
            int k = e / GBN, nn = e % GBN;
            int gk = k0 + k, gn = bn + nn;
            Bs[k][nn] = (gk < K && gn < N) ? B[(size_t)gk * N + gn] : 0.f;
        }
        __syncthreads();
#pragma unroll
        for (int k = 0; k < GBK; k++) {
            float a[4], b[4];
#pragma unroll
            for (int i = 0; i < 4; i++) a[i] = As[k][ty * 4 + i];
#pragma unroll
            for (int j = 0; j < 4; j++) b[j] = Bs[k][tx * 4 + j];
#pragma unroll
            for (int i = 0; i < 4; i++)
#pragma unroll
                for (int j = 0; j < 4; j++) acc[i][j] += a[i] * b[j];
        }
        __syncthreads();
    }
    float step = (stepsPtr != nullptr) ? stepsPtr[stepIdx] : 0.f;
#pragma unroll
    for (int i = 0; i < 4; i++) {
        int gm = bm + ty * 4 + i;
        if (gm >= M) continue;
#pragma unroll
        for (int j = 0; j < 4; j++) {
            int gn = bn + tx * 4 + j;
            if (gn >= N) continue;
            size_t idx = (size_t)gm * N + gn;
            float v = acc[i][j], o;
            if (epi == 0)      o = v;
            else if (epi == 1) o = E1[idx] - v;
            else if (epi == 2) o = step * v + E1[idx];
            else               o = E1[idx] - step * v + E2[idx];
            C[idx] = o;
        }
    }
}

// ---------------- SIMT conv (conv1: Cin=1 -> 32) -------------------------------
template <int COPB>
__global__ void conv3x3_kernel(const float* __restrict__ in,
                               const float* __restrict__ wt,
                               const float* __restrict__ bias,
                               float* __restrict__ out,
                               int Cin, int Cout,
                               int Himg, int Wimg, int tilesX, int tilesY,
                               int relu, int inTrans, int outTrans) {
    __shared__ float s_in[35 * 35];
    __shared__ float s_w[COPB * 9];
    int tpi = tilesX * tilesY;
    int n = blockIdx.x / tpi;
    int trem = blockIdx.x % tpi;
    int ty0 = (trem / tilesX) * BQ;
    int tx0 = (trem % tilesX) * BQ;
    int ocBase = blockIdx.y * COPB;
    int tid = threadIdx.x;
    float acc[3][COPB];
#pragma unroll
    for (int pp = 0; pp < 3; pp++)
#pragma unroll
        for (int oc = 0; oc < COPB; oc++) acc[pp][oc] = 0.f;
    for (int c = 0; c < Cin; c++) {
        __syncthreads();
        for (int q = tid; q < 35 * 35; q += 363) {
            int gi = ty0 + q / 35 - 1;
            int gj = tx0 + q % 35 - 1;
            float v = 0.f;
            if (gi >= 0 && gi < Himg && gj >= 0 && gj < Wimg) {
                if (inTrans) v = in[(size_t)(gi * Wimg + gj) * NCOL + n];
                else         v = in[((size_t)(n * Cin + c) * Himg + gi) * Wimg + gj];
            }
            s_in[q] = v;
        }
        for (int q = tid; q < COPB * 9; q += 363)
            s_w[q] = wt[((size_t)(ocBase + q / 9) * Cin + c) * 9 + (q % 9)];
        __syncthreads();
        float v[3][9];
#pragma unroll
        for (int pp = 0; pp < 3; pp++) {
            int p = tid + pp * 363;
            int i = p / BQ, j = p % BQ;
#pragma unroll
            for (int di = 0; di < 3; di++)
#pragma unroll
                for (int dj = 0; dj < 3; dj++)
                    v[pp][di * 3 + dj] = s_in[(i + di) * 35 + (j + dj)];
        }
#pragma unroll
        for (int oc = 0; oc < COPB; oc++) {
            float w[9];
#pragma unroll
            for (int r = 0; r < 9; r++) w[r] = s_w[oc * 9 + r];
#pragma unroll
            for (int pp = 0; pp < 3; pp++) {
                float s = 0.f;
#pragma unroll
                for (int r = 0; r < 9; r++) s += v[pp][r] * w[r];
                acc[pp][oc] += s;
            }
        }
    }
#pragma unroll
    for (int pp = 0; pp < 3; pp++) {
        int p = tid + pp * 363;
        int i = p / BQ, j = p % BQ;
        int gi = ty0 + i, gj = tx0 + j;
#pragma unroll
        for (int oc = 0; oc < COPB; oc++) {
            float bv = (bias != nullptr) ? bias[ocBase + oc] : 0.f;
            float v = acc[pp][oc] + bv;
            if (relu) v = fmaxf(v, 0.f);
            if (outTrans) out[(size_t)(gi * Wimg + gj) * NCOL + n] = v;
            else out[((size_t)(n * Cout + ocBase + oc) * Himg + gi) * Wimg + gj] = v;
        }
    }
}

// ---------------- host driver --------------------------------------------------
extern "C" void kernel_launch(void* const* d_in, const int* in_sizes, int n_in,
                              void* d_out, int out_size) {
    const float* inputs = (const float*)d_in[0];
    const float* A      = (const float*)d_in[1];
    const float* Q      = (const float*)d_in[2];
    const float* steps  = (const float*)d_in[3];
    const float* den_w1 = (const float*)d_in[4];
    const float* den_b1 = (const float*)d_in[5];
    const float* den_w2 = (const float*)d_in[6];
    const float* den_b2 = (const float*)d_in[7];
    const float* den_w3 = (const float*)d_in[8];
    const float* den_b3 = (const float*)d_in[9];
    const float* den_w4 = (const float*)d_in[10];
    const float* deb_w1 = (const float*)d_in[11];
    const float* deb_b1 = (const float*)d_in[12];
    const float* deb_w2 = (const float*)d_in[13];
    const float* deb_b2 = (const float*)d_in[14];
    const float* deb_w3 = (const float*)d_in[15];
    const float* deb_b3 = (const float*)d_in[16];
    const float* deb_w4 = (const float*)d_in[17];
    int layers = in_sizes[3];

    float *pX, *pY, *pR, *pZ, *pN, *pAtA, *pIm, *pT1, *pT2;
    cudaGetSymbolAddress((void**)&pX, g_X);
    cudaGetSymbolAddress((void**)&pY, g_y);
    cudaGetSymbolAddress((void**)&pR, g_r);
    cudaGetSymbolAddress((void**)&pZ, g_z);
    cudaGetSymbolAddress((void**)&pN, g_noise);
    cudaGetSymbolAddress((void**)&pAtA, g_AtA);
    cudaGetSymbolAddress((void**)&pIm, g_im);
    cudaGetSymbolAddress((void**)&pT1, g_t1);
    cudaGetSymbolAddress((void**)&pT2, g_t2);

    const int EW = 256;
    const int EG = (IMGPIX + EW - 1) / EW;
    dim3 gN512M272((NCOL + GBN - 1) / GBN, (MROW + GBM - 1) / GBM);
    dim3 gN512M1089((NCOL + GBN - 1) / GBN, (BBSZ + GBM - 1) / GBM);
    dim3 gAtA((BBSZ + GBN - 1) / GBN, (BBSZ + GBM - 1) / GBM);

    const int SM0 = WBYTES + 2 * 16 * 245 * 4;   // 69376
    const int SM1 = WBYTES + 2 * 16 * 180 * 4;   // 61056
    cudaFuncSetAttribute(conv_hmma_kernel<0,0>, cudaFuncAttributeMaxDynamicSharedMemorySize, SM0);
    cudaFuncSetAttribute(conv_hmma_kernel<0,1>, cudaFuncAttributeMaxDynamicSharedMemorySize, SM0);
    cudaFuncSetAttribute(conv_hmma_kernel<1,0>, cudaFuncAttributeMaxDynamicSharedMemorySize, SM1);
    cudaFuncSetAttribute(conv_hmma_kernel<1,2>, cudaFuncAttributeMaxDynamicSharedMemorySize, SM1);

    blockify_input_kernel<<<EG, EW>>>(inputs, pZ);
    gemm_kernel<<<gN512M272, 256>>>(A, pZ, pY, MROW, NCOL, BBSZ, BBSZ, 0, 0,
                                    nullptr, nullptr, nullptr, 0);
    gemm_kernel<<<gN512M1089, 256>>>(Q, pY, pX, BBSZ, NCOL, MROW, MROW, 0, 0,
                                     nullptr, nullptr, nullptr, 0);
    gemm_kernel<<<gAtA, 256>>>(A, A, pAtA, BBSZ, BBSZ, MROW, BBSZ, 1, 0,
                               nullptr, nullptr, nullptr, 0);

    dim3 cgrid32(NCOL, 4);
    const int G0 = NCOL * 9;
    const int G1 = 8 * 17 * 33;

    for (int n = 0; n < layers; n++) {
        gemm_kernel<<<gN512M272, 256>>>(A, pX, pR, MROW, NCOL, BBSZ, BBSZ, 0, 1,
                                        pY, nullptr, nullptr, 0);
        gemm_kernel<<<gN512M1089, 256>>>(A, pR, pZ, BBSZ, NCOL, MROW, BBSZ, 1, 2,
                                         pX, nullptr, steps, n);
        conv3x3_kernel<8><<<cgrid32, 363>>>(pX, den_w1 + (size_t)n * 32 * 9,
                                            den_b1 + n * 32, pT1, 1, 32,
                                            BQ, BQ, 1, 1, 1, 1, 0);
        conv_hmma_kernel<0,0><<<G0, 256, SM0>>>(pT1, den_w2 + (size_t)n * 32 * 32 * 9,
                                                den_b2 + n * 32, pT2);
        conv_hmma_kernel<0,0><<<G0, 256, SM0>>>(pT2, den_w3 + (size_t)n * 32 * 32 * 9,
                                                den_b3 + n * 32, pT1);
        conv_hmma_kernel<0,1><<<G0, 256, SM0>>>(pT1, den_w4 + (size_t)n * 32 * 9,
                                                nullptr, pN);
        gemm_kernel<<<gN512M1089, 256>>>(pAtA, pN, pX, BBSZ, NCOL, BBSZ, BBSZ, 0, 3,
                                         pZ, pN, steps, n);
        unblockify_kernel<<<EG, EW>>>(pX, pIm);
        conv3x3_kernel<8><<<cgrid32, 363>>>(pIm, deb_w1 + (size_t)n * 32 * 9,
                                            deb_b1 + n * 32, pT1, 1, 32,
                                            HP, HP, 8, 8, 1, 0, 0);
        conv_hmma_kernel<1,0><<<G1, 256, SM1>>>(pT1, deb_w2 + (size_t)n * 32 * 32 * 9,
                                                deb_b2 + n * 32, pT2);
        conv_hmma_kernel<1,0><<<G1, 256, SM1>>>(pT2, deb_w3 + (size_t)n * 32 * 32 * 9,
                                                deb_b3 + n * 32, pT1);
        conv_hmma_kernel<1,2><<<G1, 256, SM1>>>(pT1, deb_w4 + (size_t)n * 32 * 9,
                                                nullptr, pZ);
        blockify_sub_kernel<<<EG, EW>>>(pIm, pZ, pX);
    }

    unblockify_kernel<<<EG, EW>>>(pX, (float*)d_out);
}

// round 6
// speedup vs baseline: 1.7927x; 1.2774x over previous
#include <cuda_runtime.h>
#include <cuda_fp16.h>
#include <cstdint>

#define BQ   33
#define BBSZ 1089
#define NS   8
#define NH   8
#define NL   8
#define NCOL 512
#define MROW 272
#define HP   264
#define IMGPIX (NS*HP*HP)

// ---------------- scratch ----------------------------------------------------
__device__ float g_X[BBSZ * NCOL];
__device__ float g_y[MROW * NCOL];
__device__ float g_r[MROW * NCOL];
__device__ float g_z[BBSZ * NCOL];
__device__ float g_noise[BBSZ * NCOL];
__device__ float g_AtA[BBSZ * BBSZ];
__device__ float g_im[IMGPIX];
__device__ float g_t1[(size_t)NCOL * 32 * BBSZ];
__device__ float g_t2[(size_t)NCOL * 32 * BBSZ];
__device__ uint2 g_wpack[8 * 6 * 4608];   // [layer][conv-set][144*32]

// ---------------- HMMA helpers ------------------------------------------------
#define HMMA16816(c, a0, a1, a2, a3, b0, b1) \
    asm volatile("mma.sync.aligned.m16n8k16.row.col.f32.f16.f16.f32 " \
        "{%0,%1,%2,%3}, {%4,%5,%6,%7}, {%8,%9}, {%0,%1,%2,%3};" \
        : "+f"((c)[0]), "+f"((c)[1]), "+f"((c)[2]), "+f"((c)[3]) \
        : "r"(a0), "r"(a1), "r"(a2), "r"(a3), "r"(b0), "r"(b1))

__device__ __forceinline__ uint32_t h2bits(__half2 h) {
    return *reinterpret_cast<uint32_t*>(&h);
}
__device__ __forceinline__ uint32_t pack_split(float x, float y, uint32_t& lo) {
    __half2 h = __floats2half2_rn(x, y);
    __half2 l = __floats2half2_rn(x - __low2float(h), y - __high2float(h));
    lo = h2bits(l);
    return h2bits(h);
}

// ---------------- weight pre-pack (once per run) -------------------------------
// set 0..5 = den2, den3, den4, deb2, deb3, deb4 ; grid (6, layers), 256 thr
__global__ void prep_weights(const float* __restrict__ dw2, const float* __restrict__ dw3,
                             const float* __restrict__ dw4, const float* __restrict__ bw2,
                             const float* __restrict__ bw3, const float* __restrict__ bw4,
                             uint2* __restrict__ outp) {
    int set = blockIdx.x, n = blockIdx.y;
    const float* wt; int coutr;
    switch (set) {
        case 0: wt = dw2 + (size_t)n * 32 * 32 * 9; coutr = 32; break;
        case 1: wt = dw3 + (size_t)n * 32 * 32 * 9; coutr = 32; break;
        case 2: wt = dw4 + (size_t)n * 32 * 9;      coutr = 1;  break;
        case 3: wt = bw2 + (size_t)n * 32 * 32 * 9; coutr = 32; break;
        case 4: wt = bw3 + (size_t)n * 32 * 32 * 9; coutr = 32; break;
        default: wt = bw4 + (size_t)n * 32 * 9;     coutr = 1;  break;
    }
    uint2* o = outp + ((size_t)n * 6 + set) * 4608;
    for (int e = threadIdx.x; e < 144 * 32; e += 256) {
        int kp = e >> 5, oc = e & 31;
        int k0 = 2 * kp;
        int tap = k0 >> 5, ic = k0 & 31;
        float w0 = 0.f, w1 = 0.f;
        if (oc < coutr) {
            w0 = wt[(oc * 32 + ic) * 9 + tap];
            w1 = wt[(oc * 32 + ic + 1) * 9 + tap];
        }
        uint32_t lo;
        uint32_t hi = pack_split(w0, w1, lo);
        o[e] = make_uint2(hi, lo);
    }
}

// ---------------- HMMA implicit-GEMM conv: 32ch in -> 32 (or 1) ch out --------
// MODE 0: 512 imgs 33x33, tile = 128 linear pixels (9 tiles/img), halo 7x35/pair
// MODE 1: 8 imgs 264x264, tile = 16x8 px (17x33 tiles/img), halo 18x10/pair
// OUTM 0: 32ch NCHW + bias + relu ; 1: 1ch col-major ; 2: 1ch image
#define WBYTES (144 * 33 * 8)

template<int MODE, int OUTM>
__global__ void conv_hmma_kernel(const float* __restrict__ in,
                                 const uint2* __restrict__ wpack,
                                 const float* __restrict__ bias,
                                 float* __restrict__ out) {
    extern __shared__ char smem[];
    uint2* wsm = (uint2*)smem;                        // [144][33] (hi,lo)
    constexpr int PSTR = (MODE == 0) ? 245 : 180;
    constexpr int WROW = (MODE == 0) ? 35 : 10;
    uint32_t* hhi = (uint32_t*)(smem + WBYTES);       // [16][PSTR]
    uint32_t* hlo = hhi + 16 * PSTR;
    constexpr int NT = (OUTM == 0) ? 4 : 1;

    const int tid = threadIdx.x;     // 256
    const int wid = tid >> 5;
    const int lane = tid & 31;
    const int rg = lane >> 2;
    const int l3 = lane & 3;
    const int kq = l3 * 2;

    int n_img, p0 = 0, y_first = 0, y0t = 0, x0t = 0;
    if (MODE == 0) {
        n_img = blockIdx.x / 9;
        p0 = (blockIdx.x % 9) * 128;
        y_first = p0 / 33;
    } else {
        int b = blockIdx.x;
        int tx = b % 33; b /= 33;
        int ty = b % 17; b /= 17;
        n_img = b; y0t = ty * 16; x0t = tx * 8;
    }

    // ---- weights: coalesced uint2 loads from pre-packed table ----
#pragma unroll
    for (int e = tid; e < 144 * 32; e += 256) {
        int kp = e >> 5, oc = e & 31;
        wsm[kp * 33 + oc] = wpack[e];
    }

    // ---- halo load + hi/lo split, channel-pair packed ----
    if (MODE == 0) {
        for (int e = tid; e < 16 * 245; e += 256) {
            int pair = e / 245, pos = e % 245;
            int row = pos / 35, xp = pos % 35;
            int gy = y_first - 1 + row, gx = xp - 1;
            bool ok = (gy >= 0) && (gy < 33) && (xp >= 1) && (xp < 34);
            size_t bi = (size_t)(n_img * 32 + 2 * pair) * BBSZ + gy * 33 + gx;
            float f0 = ok ? in[bi] : 0.f;
            float f1 = ok ? in[bi + BBSZ] : 0.f;
            uint32_t lo;
            hhi[e] = pack_split(f0, f1, lo);
            hlo[e] = lo;
        }
    } else {
        for (int e = tid; e < 16 * 180; e += 256) {
            int pair = e / 180, pos = e % 180;
            int row = pos / 10, xp = pos % 10;
            int gy = y0t - 1 + row, gx = x0t - 1 + xp;
            bool ok = (gy >= 0) && (gy < 264) && (gx >= 0) && (gx < 264);
            size_t bi = (size_t)(n_img * 32 + 2 * pair) * 264 * 264 + gy * 264 + gx;
            float f0 = ok ? in[bi] : 0.f;
            float f1 = ok ? in[bi + 264 * 264] : 0.f;
            uint32_t lo;
            hhi[e] = pack_split(f0, f1, lo);
            hlo[e] = lo;
        }
    }
    __syncthreads();

    // ---- per-thread pixel bases ----
    int m_lo = wid * 16 + rg;
    int m_hi = m_lo + 8;
    int base_lo, base_hi;
    if (MODE == 0) {
        int pl = p0 + m_lo, ph = p0 + m_hi;
        int yl = pl / 33, yh = ph / 33;
        base_lo = (pl < BBSZ) ? (yl - y_first) * 35 + (pl - yl * 33) : 0;
        base_hi = (ph < BBSZ) ? (yh - y_first) * 35 + (ph - yh * 33) : 0;
    } else {
        base_lo = (m_lo >> 3) * 10 + (m_lo & 7);
        base_hi = (m_hi >> 3) * 10 + (m_hi & 7);
    }
    const uint32_t* phi_lo = hhi + l3 * PSTR + base_lo;
    const uint32_t* phi_hi = hhi + l3 * PSTR + base_hi;
    const uint32_t* plo_lo = hlo + l3 * PSTR + base_lo;
    const uint32_t* plo_hi = hlo + l3 * PSTR + base_hi;

    float acc[NT][4];
#pragma unroll
    for (int nt = 0; nt < NT; nt++)
#pragma unroll
        for (int i = 0; i < 4; i++) acc[nt][i] = 0.f;

#pragma unroll
    for (int t = 0; t < 9; t++) {
        const int toff = (t / 3) * WROW + (t % 3);
#pragma unroll
        for (int e2 = 0; e2 < 2; e2++) {
            const int c = 2 * t + e2;
            const int pb = e2 * 8 * PSTR + toff;
            uint32_t a0h = phi_lo[pb];
            uint32_t a1h = phi_hi[pb];
            uint32_t a2h = phi_lo[pb + 4 * PSTR];
            uint32_t a3h = phi_hi[pb + 4 * PSTR];
            uint32_t a0l = plo_lo[pb];
            uint32_t a1l = plo_hi[pb];
            uint32_t a2l = plo_lo[pb + 4 * PSTR];
            uint32_t a3l = plo_hi[pb + 4 * PSTR];
            const int kp0 = c * 8 + l3;
#pragma unroll
            for (int nt = 0; nt < NT; nt++) {
                uint2 b0 = wsm[kp0 * 33 + nt * 8 + rg];
                uint2 b1 = wsm[(kp0 + 4) * 33 + nt * 8 + rg];
                HMMA16816(acc[nt], a0h, a1h, a2h, a3h, b0.x, b1.x);
                HMMA16816(acc[nt], a0h, a1h, a2h, a3h, b0.y, b1.y);
                HMMA16816(acc[nt], a0l, a1l, a2l, a3l, b0.x, b1.x);
            }
        }
    }

    // ---- epilogue ----
    if (OUTM == 0) {
        __syncthreads();
        float* sbuf = (float*)smem;      // [32][132]
#pragma unroll
        for (int nt = 0; nt < NT; nt++) {
            int oc = nt * 8 + kq;
            sbuf[oc * 132 + m_lo]       = acc[nt][0];
            sbuf[(oc + 1) * 132 + m_lo] = acc[nt][1];
            sbuf[oc * 132 + m_hi]       = acc[nt][2];
            sbuf[(oc + 1) * 132 + m_hi] = acc[nt][3];
        }
        __syncthreads();
        int oc = tid >> 3;
        float bv = bias[oc];
#pragma unroll
        for (int i = 0; i < 16; i++) {
            int m = (tid & 7) + 8 * i;
            float v = fmaxf(sbuf[oc * 132 + m] + bv, 0.f);
            if (MODE == 0) {
                int p = p0 + m;
                if (p < BBSZ)
                    out[(size_t)(n_img * 32 + oc) * BBSZ + p] = v;
            } else {
                int oy = y0t + (m >> 3), ox = x0t + (m & 7);
                if (oy < 264)
                    out[((size_t)(n_img * 32 + oc) * 264 + oy) * 264 + ox] = v;
            }
        }
    } else {
        if (l3 == 0) {
            if (MODE == 0) {
                int pl = p0 + m_lo, ph = p0 + m_hi;
                if (pl < BBSZ) out[(size_t)pl * NCOL + n_img] = acc[0][0];
                if (ph < BBSZ) out[(size_t)ph * NCOL + n_img] = acc[0][2];
            } else {
                int oyl = y0t + (m_lo >> 3), oyh = y0t + (m_hi >> 3);
                if (oyl < 264)
                    out[(size_t)n_img * HP * HP + oyl * 264 + x0t + (m_lo & 7)] = acc[0][0];
                if (oyh < 264)
                    out[(size_t)n_img * HP * HP + oyh * 264 + x0t + (m_hi & 7)] = acc[0][2];
            }
        }
    }
}

// ---------------- blockify / unblockify ---------------------------------------
__global__ void blockify_input_kernel(const float* __restrict__ in, float* __restrict__ Xb) {
    int idx = blockIdx.x * blockDim.x + threadIdx.x;
    if (idx >= BBSZ * NCOL) return;
    int r = idx / NCOL, n = idx % NCOL;
    int i = r / BQ, j = r % BQ;
    int l = n / (NH * NS), h = (n / NS) % NH, s = n % NS;
    Xb[idx] = in[(s * HP + h * BQ + i) * HP + l * BQ + j];
}
__global__ void unblockify_kernel(const float* __restrict__ X, float* __restrict__ img) {
    int idx = blockIdx.x * blockDim.x + threadIdx.x;
    if (idx >= IMGPIX) return;
    int s = idx / (HP * HP);
    int rem = idx % (HP * HP);
    int R = rem / HP, C = rem % HP;
    int h = R / BQ, i = R % BQ, l = C / BQ, j = C % BQ;
    img[idx] = X[(i * BQ + j) * NCOL + (l * (NH * NS) + h * NS + s)];
}
__global__ void blockify_sub_kernel(const float* __restrict__ img,
                                    const float* __restrict__ db,
                                    float* __restrict__ X) {
    int idx = blockIdx.x * blockDim.x + threadIdx.x;
    if (idx >= IMGPIX) return;
    int s = idx / (HP * HP);
    int rem = idx % (HP * HP);
    int R = rem / HP, C = rem % HP;
    int h = R / BQ, i = R % BQ, l = C / BQ, j = C % BQ;
    X[(i * BQ + j) * NCOL + (l * (NH * NS) + h * NS + s)] = img[idx] - db[idx];
}

// ---------------- SIMT GEMM with fused epilogues -------------------------------
#define GBM 64
#define GBN 64
#define GBK 16
__global__ void gemm_kernel(const float* __restrict__ A, const float* __restrict__ B,
                            float* __restrict__ C,
                            int M, int N, int K, int lda, int transA,
                            int epi, const float* __restrict__ E1,
                            const float* __restrict__ E2,
                            const float* __restrict__ stepsPtr, int stepIdx) {
    __shared__ float As[GBK][GBM];
    __shared__ float Bs[GBK][GBN + 1];
    int bm = blockIdx.y * GBM, bn = blockIdx.x * GBN;
    int tid = threadIdx.x;
    int tx = tid % 16, ty = tid / 16;
    float acc[4][4];
#pragma unroll
    for (int i = 0; i < 4; i++)
#pragma unroll
        for (int j = 0; j < 4; j++) acc[i][j] = 0.f;
    for (int k0 = 0; k0 < K; k0 += GBK) {
        if (transA) {
            for (int e = tid; e < GBM * GBK; e += 256) {
                int k = e / GBM, mm = e % GBM;
                int gm = bm + mm, gk = k0 + k;
                As[k][mm] = (gm < M && gk < K) ? A[(size_t)gk * lda + gm] : 0.f;
            }
        } else {
            for (int e = tid; e < GBM * GBK; e += 256) {
                int mm = e / GBK, k = e % GBK;
                int gm = bm + mm, gk = k0 + k;
                As[k][mm] = (gm < M && gk < K) ? A[(size_t)gm * lda + gk] : 0.f;
            }
        }
        for (int e = tid; e < GBK * GBN; e += 256) {
            int k = e / GBN, nn = e % GBN;
            int gk = k0 + k, gn = bn + nn;
            Bs[k][nn] = (gk < K && gn < N) ? B[(size_t)gk * N + gn] : 0.f;
        }
        __syncthreads();
#pragma unroll
        for (int k = 0; k < GBK; k++) {
            float a[4], b[4];
#pragma unroll
            for (int i = 0; i < 4; i++) a[i] = As[k][ty * 4 + i];
#pragma unroll
            for (int j = 0; j < 4; j++) b[j] = Bs[k][tx * 4 + j];
#pragma unroll
            for (int i = 0; i < 4; i++)
#pragma unroll
                for (int j = 0; j < 4; j++) acc[i][j] += a[i] * b[j];
        }
        __syncthreads();
    }
    float step = (stepsPtr != nullptr) ? stepsPtr[stepIdx] : 0.f;
#pragma unroll
    for (int i = 0; i < 4; i++) {
        int gm = bm + ty * 4 + i;
        if (gm >= M) continue;
#pragma unroll
        for (int j = 0; j < 4; j++) {
            int gn = bn + tx * 4 + j;
            if (gn >= N) continue;
            size_t idx = (size_t)gm * N + gn;
            float v = acc[i][j], o;
            if (epi == 0)      o = v;
            else if (epi == 1) o = E1[idx] - v;
            else if (epi == 2) o = step * v + E1[idx];
            else               o = E1[idx] - step * v + E2[idx];
            C[idx] = o;
        }
    }
}

// ---------------- SIMT conv (conv1: Cin=1 -> 32) -------------------------------
template <int COPB>
__global__ void conv3x3_kernel(const float* __restrict__ in,
                               const float* __restrict__ wt,
                               const float* __restrict__ bias,
                               float* __restrict__ out,
                               int Cin, int Cout,
                               int Himg, int Wimg, int tilesX, int tilesY,
                               int relu, int inTrans, int outTrans) {
    __shared__ float s_in[35 * 35];
    __shared__ float s_w[COPB * 9];
    int tpi = tilesX * tilesY;
    int n = blockIdx.x / tpi;
    int trem = blockIdx.x % tpi;
    int ty0 = (trem / tilesX) * BQ;
    int tx0 = (trem % tilesX) * BQ;
    int ocBase = blockIdx.y * COPB;
    int tid = threadIdx.x;
    float acc[3][COPB];
#pragma unroll
    for (int pp = 0; pp < 3; pp++)
#pragma unroll
        for (int oc = 0; oc < COPB; oc++) acc[pp][oc] = 0.f;
    for (int c = 0; c < Cin; c++) {
        __syncthreads();
        for (int q = tid; q < 35 * 35; q += 363) {
            int gi = ty0 + q / 35 - 1;
            int gj = tx0 + q % 35 - 1;
            float v = 0.f;
            if (gi >= 0 && gi < Himg && gj >= 0 && gj < Wimg) {
                if (inTrans) v = in[(size_t)(gi * Wimg + gj) * NCOL + n];
                else         v = in[((size_t)(n * Cin + c) * Himg + gi) * Wimg + gj];
            }
            s_in[q] = v;
        }
        for (int q = tid; q < COPB * 9; q += 363)
            s_w[q] = wt[((size_t)(ocBase + q / 9) * Cin + c) * 9 + (q % 9)];
        __syncthreads();
        float v[3][9];
#pragma unroll
        for (int pp = 0; pp < 3; pp++) {
            int p = tid + pp * 363;
            int i = p / BQ, j = p % BQ;
#pragma unroll
            for (int di = 0; di < 3; di++)
#pragma unroll
                for (int dj = 0; dj < 3; dj++)
                    v[pp][di * 3 + dj] = s_in[(i + di) * 35 + (j + dj)];
        }
#pragma unroll
        for (int oc = 0; oc < COPB; oc++) {
            float w[9];
#pragma unroll
            for (int r = 0; r < 9; r++) w[r] = s_w[oc * 9 + r];
#pragma unroll
            for (int pp = 0; pp < 3; pp++) {
                float s = 0.f;
#pragma unroll
                for (int r = 0; r < 9; r++) s += v[pp][r] * w[r];
                acc[pp][oc] += s;
            }
        }
    }
#pragma unroll
    for (int pp = 0; pp < 3; pp++) {
        int p = tid + pp * 363;
        int i = p / BQ, j = p % BQ;
        int gi = ty0 + i, gj = tx0 + j;
#pragma unroll
        for (int oc = 0; oc < COPB; oc++) {
            float bv = (bias != nullptr) ? bias[ocBase + oc] : 0.f;
            float v = acc[pp][oc] + bv;
            if (relu) v = fmaxf(v, 0.f);
            if (outTrans) out[(size_t)(gi * Wimg + gj) * NCOL + n] = v;
            else out[((size_t)(n * Cout + ocBase + oc) * Himg + gi) * Wimg + gj] = v;
        }
    }
}

// ---------------- host driver --------------------------------------------------
extern "C" void kernel_launch(void* const* d_in, const int* in_sizes, int n_in,
                              void* d_out, int out_size) {
    const float* inputs = (const float*)d_in[0];
    const float* A      = (const float*)d_in[1];
    const float* Q      = (const float*)d_in[2];
    const float* steps  = (const float*)d_in[3];
    const float* den_w1 = (const float*)d_in[4];
    const float* den_b1 = (const float*)d_in[5];
    const float* den_w2 = (const float*)d_in[6];
    const float* den_b2 = (const float*)d_in[7];
    const float* den_w3 = (const float*)d_in[8];
    const float* den_b3 = (const float*)d_in[9];
    const float* den_w4 = (const float*)d_in[10];
    const float* deb_w1 = (const float*)d_in[11];
    const float* deb_b1 = (const float*)d_in[12];
    const float* deb_w2 = (const float*)d_in[13];
    const float* deb_b2 = (const float*)d_in[14];
    const float* deb_w3 = (const float*)d_in[15];
    const float* deb_b3 = (const float*)d_in[16];
    const float* deb_w4 = (const float*)d_in[17];
    int layers = in_sizes[3];

    float *pX, *pY, *pR, *pZ, *pN, *pAtA, *pIm, *pT1, *pT2;
    uint2* pWp;
    cudaGetSymbolAddress((void**)&pX, g_X);
    cudaGetSymbolAddress((void**)&pY, g_y);
    cudaGetSymbolAddress((void**)&pR, g_r);
    cudaGetSymbolAddress((void**)&pZ, g_z);
    cudaGetSymbolAddress((void**)&pN, g_noise);
    cudaGetSymbolAddress((void**)&pAtA, g_AtA);
    cudaGetSymbolAddress((void**)&pIm, g_im);
    cudaGetSymbolAddress((void**)&pT1, g_t1);
    cudaGetSymbolAddress((void**)&pT2, g_t2);
    cudaGetSymbolAddress((void**)&pWp, g_wpack);

    const int EW = 256;
    const int EG = (IMGPIX + EW - 1) / EW;
    dim3 gN512M272((NCOL + GBN - 1) / GBN, (MROW + GBM - 1) / GBM);
    dim3 gN512M1089((NCOL + GBN - 1) / GBN, (BBSZ + GBM - 1) / GBM);
    dim3 gAtA((BBSZ + GBN - 1) / GBN, (BBSZ + GBM - 1) / GBM);

    const int SM0 = WBYTES + 2 * 16 * 245 * 4;   // 69376
    const int SM1 = WBYTES + 2 * 16 * 180 * 4;   // 61056
    cudaFuncSetAttribute(conv_hmma_kernel<0,0>, cudaFuncAttributeMaxDynamicSharedMemorySize, SM0);
    cudaFuncSetAttribute(conv_hmma_kernel<0,1>, cudaFuncAttributeMaxDynamicSharedMemorySize, SM0);
    cudaFuncSetAttribute(conv_hmma_kernel<1,0>, cudaFuncAttributeMaxDynamicSharedMemorySize, SM1);
    cudaFuncSetAttribute(conv_hmma_kernel<1,2>, cudaFuncAttributeMaxDynamicSharedMemorySize, SM1);

    // pre-pack all conv weights (coalesced table for conv blocks)
    prep_weights<<<dim3(6, layers), 256>>>(den_w2, den_w3, den_w4,
                                           deb_w2, deb_w3, deb_w4, pWp);

    blockify_input_kernel<<<EG, EW>>>(inputs, pZ);
    gemm_kernel<<<gN512M272, 256>>>(A, pZ, pY, MROW, NCOL, BBSZ, BBSZ, 0, 0,
                                    nullptr, nullptr, nullptr, 0);
    gemm_kernel<<<gN512M1089, 256>>>(Q, pY, pX, BBSZ, NCOL, MROW, MROW, 0, 0,
                                     nullptr, nullptr, nullptr, 0);
    gemm_kernel<<<gAtA, 256>>>(A, A, pAtA, BBSZ, BBSZ, MROW, BBSZ, 1, 0,
                               nullptr, nullptr, nullptr, 0);

    dim3 cgrid32(NCOL, 4);
    const int G0 = NCOL * 9;
    const int G1 = 8 * 17 * 33;

    for (int n = 0; n < layers; n++) {
        const uint2* wp = pWp + (size_t)(n * 6) * 4608;
        gemm_kernel<<<gN512M272, 256>>>(A, pX, pR, MROW, NCOL, BBSZ, BBSZ, 0, 1,
                                        pY, nullptr, nullptr, 0);
        gemm_kernel<<<gN512M1089, 256>>>(A, pR, pZ, BBSZ, NCOL, MROW, BBSZ, 1, 2,
                                         pX, nullptr, steps, n);
        conv3x3_kernel<8><<<cgrid32, 363>>>(pX, den_w1 + (size_t)n * 32 * 9,
                                            den_b1 + n * 32, pT1, 1, 32,
                                            BQ, BQ, 1, 1, 1, 1, 0);
        conv_hmma_kernel<0,0><<<G0, 256, SM0>>>(pT1, wp + 0 * 4608, den_b2 + n * 32, pT2);
        conv_hmma_kernel<0,0><<<G0, 256, SM0>>>(pT2, wp + 1 * 4608, den_b3 + n * 32, pT1);
        conv_hmma_kernel<0,1><<<G0, 256, SM0>>>(pT1, wp + 2 * 4608, nullptr, pN);
        gemm_kernel<<<gN512M1089, 256>>>(pAtA, pN, pX, BBSZ, NCOL, BBSZ, BBSZ, 0, 3,
                                         pZ, pN, steps, n);
        unblockify_kernel<<<EG, EW>>>(pX, pIm);
        conv3x3_kernel<8><<<cgrid32, 363>>>(pIm, deb_w1 + (size_t)n * 32 * 9,
                                            deb_b1 + n * 32, pT1, 1, 32,
                                            HP, HP, 8, 8, 1, 0, 0);
        conv_hmma_kernel<1,0><<<G1, 256, SM1>>>(pT1, wp + 3 * 4608, deb_b2 + n * 32, pT2);
        conv_hmma_kernel<1,0><<<G1, 256, SM1>>>(pT2, wp + 4 * 4608, deb_b3 + n * 32, pT1);
        conv_hmma_kernel<1,2><<<G1, 256, SM1>>>(pT1, wp + 5 * 4608, nullptr, pZ);
        blockify_sub_kernel<<<EG, EW>>>(pIm, pZ, pX);
    }

    unblockify_kernel<<<EG, EW>>>(pX, (float*)d_out);
}

// round 7
// speedup vs baseline: 1.7939x; 1.0006x over previous
#include <cuda_runtime.h>
#include <cuda_fp16.h>
#include <cstdint>

#define BQ   33
#define BBSZ 1089
#define NS   8
#define NH   8
#define NL   8
#define NCOL 512
#define MROW 272
#define HP   264
#define IMGPIX (NS*HP*HP)

// ---------------- scratch ----------------------------------------------------
__device__ float g_X[BBSZ * NCOL];
__device__ float g_y[MROW * NCOL];
__device__ float g_r[MROW * NCOL];
__device__ float g_z[BBSZ * NCOL];
__device__ float g_noise[BBSZ * NCOL];
__device__ float g_AtA[BBSZ * BBSZ];
__device__ float g_t1[(size_t)NCOL * 32 * BBSZ];
__device__ float g_t2[(size_t)NCOL * 32 * BBSZ];
__device__ uint2 g_wpack[8 * 6 * 4608];   // [layer][conv-set][144*32]

// ---------------- HMMA helpers ------------------------------------------------
#define HMMA16816(c, a0, a1, a2, a3, b0, b1) \
    asm volatile("mma.sync.aligned.m16n8k16.row.col.f32.f16.f16.f32 " \
        "{%0,%1,%2,%3}, {%4,%5,%6,%7}, {%8,%9}, {%0,%1,%2,%3};" \
        : "+f"((c)[0]), "+f"((c)[1]), "+f"((c)[2]), "+f"((c)[3]) \
        : "r"(a0), "r"(a1), "r"(a2), "r"(a3), "r"(b0), "r"(b1))

__device__ __forceinline__ uint32_t h2bits(__half2 h) {
    return *reinterpret_cast<uint32_t*>(&h);
}
__device__ __forceinline__ uint32_t pack_split(float x, float y, uint32_t& lo) {
    __half2 h = __floats2half2_rn(x, y);
    __half2 l = __floats2half2_rn(x - __low2float(h), y - __high2float(h));
    lo = h2bits(l);
    return h2bits(h);
}

// ---------------- weight pre-pack (once per run) -------------------------------
__global__ void prep_weights(const float* __restrict__ dw2, const float* __restrict__ dw3,
                             const float* __restrict__ dw4, const float* __restrict__ bw2,
                             const float* __restrict__ bw3, const float* __restrict__ bw4,
                             uint2* __restrict__ outp) {
    int set = blockIdx.x, n = blockIdx.y;
    const float* wt; int coutr;
    switch (set) {
        case 0: wt = dw2 + (size_t)n * 32 * 32 * 9; coutr = 32; break;
        case 1: wt = dw3 + (size_t)n * 32 * 32 * 9; coutr = 32; break;
        case 2: wt = dw4 + (size_t)n * 32 * 9;      coutr = 1;  break;
        case 3: wt = bw2 + (size_t)n * 32 * 32 * 9; coutr = 32; break;
        case 4: wt = bw3 + (size_t)n * 32 * 32 * 9; coutr = 32; break;
        default: wt = bw4 + (size_t)n * 32 * 9;     coutr = 1;  break;
    }
    uint2* o = outp + ((size_t)n * 6 + set) * 4608;
    for (int e = threadIdx.x; e < 144 * 32; e += 256) {
        int kp = e >> 5, oc = e & 31;
        int k0 = 2 * kp;
        int tap = k0 >> 5, ic = k0 & 31;
        float w0 = 0.f, w1 = 0.f;
        if (oc < coutr) {
            w0 = wt[(oc * 32 + ic) * 9 + tap];
            w1 = wt[(oc * 32 + ic + 1) * 9 + tap];
        }
        uint32_t lo;
        uint32_t hi = pack_split(w0, w1, lo);
        o[e] = make_uint2(hi, lo);
    }
}

// X col-major index of image pixel (s, gy, gx)
__device__ __forceinline__ int ximg_idx(int s, int gy, int gx) {
    int h = gy / 33, i = gy % 33, l = gx / 33, j = gx % 33;
    return (i * 33 + j) * NCOL + l * (NH * NS) + h * NS + s;
}

#define WBYTES (144 * 33 * 8)

// ============ fused conv1(1->32,relu)+conv2(32->32,relu) via HMMA ==============
// MODE 0: denoise — input X col-major [1089,512]; 512 imgs x 9 tiles of 128 px
// MODE 1: deblock — input X col-major read via unblockify map; 8 imgs,
//         tiles 16x8 px (17x33 per img)
// Output: 32ch NCHW + bias2 + relu
template<int MODE>
__global__ void __launch_bounds__(256)
conv12_hmma(const float* __restrict__ xin,
            const float* __restrict__ w1g,      // [32][9]
            const float* __restrict__ b1g,      // [32]
            const uint2* __restrict__ wpack,
            const float* __restrict__ bias2,
            float* __restrict__ out) {
    extern __shared__ char smem[];
    constexpr int PSTR = (MODE == 0) ? 245 : 180;
    constexpr int WROW = (MODE == 0) ? 35 : 10;
    constexpr int NPOS = (MODE == 0) ? 245 : 180;
    constexpr int RW   = (MODE == 0) ? 37 : 12;
    constexpr int RAWN = (MODE == 0) ? 9 * 37 : 20 * 12;
    uint2* wsm = (uint2*)smem;
    uint32_t* hhi = (uint32_t*)(smem + WBYTES);
    uint32_t* hlo = hhi + 16 * PSTR;
    float* raw = (float*)(smem + WBYTES + 2 * 16 * PSTR * 4);
    float* w1s = raw + ((RAWN + 3) & ~3);       // 288 w + 32 bias

    const int tid = threadIdx.x;
    const int wid = tid >> 5;
    const int lane = tid & 31;
    const int rg = lane >> 2;
    const int l3 = lane & 3;
    const int kq = l3 * 2;

    int n_img, p0 = 0, y_first = 0, y0t = 0, x0t = 0;
    if (MODE == 0) {
        n_img = blockIdx.x / 9;
        p0 = (blockIdx.x % 9) * 128;
        y_first = p0 / 33;
    } else {
        int b = blockIdx.x;
        int tx = b % 33; b /= 33;
        int ty = b % 17; b /= 17;
        n_img = b; y0t = ty * 16; x0t = tx * 8;
    }

    // conv2 packed weights
    for (int e = tid; e < 144 * 32; e += 256) {
        int kp = e >> 5, oc = e & 31;
        wsm[kp * 33 + oc] = wpack[e];
    }
    // conv1 weights + bias
    for (int e = tid; e < 320; e += 256)
        w1s[e] = (e < 288) ? w1g[e] : b1g[e - 288];
    // raw single-channel tile (+2 halo), zero outside image
    if (MODE == 0) {
        for (int e = tid; e < RAWN; e += 256) {
            int ry = e / RW, rx = e % RW;
            int gy = y_first - 2 + ry, gx = rx - 2;
            bool ok = (gy >= 0) && (gy < 33) && (gx >= 0) && (gx < 33);
            raw[e] = ok ? xin[(gy * 33 + gx) * NCOL + n_img] : 0.f;
        }
    } else {
        for (int e = tid; e < RAWN; e += 256) {
            int ry = e / RW, rx = e % RW;
            int gy = y0t - 2 + ry, gx = x0t - 2 + rx;
            bool ok = (gy >= 0) && (gy < HP) && (gx >= 0) && (gx < HP);
            raw[e] = ok ? xin[ximg_idx(n_img, gy, gx)] : 0.f;
        }
    }
    __syncthreads();

    // conv1 for halo region -> packed hi/lo planes
    if (tid < NPOS) {
        int hy = tid / WROW, hx = tid % WROW;
        int gy, gx, GHW;
        if (MODE == 0) { gy = y_first - 1 + hy; gx = hx - 1; GHW = 33; }
        else           { gy = y0t - 1 + hy;     gx = x0t - 1 + hx; GHW = HP; }
        bool valid = (gy >= 0) && (gy < GHW) && (gx >= 0) && (gx < ((MODE == 0) ? 33 : HP));
        float c1[32];
        if (valid) {
            float t0 = raw[hy * RW + hx],     t1 = raw[hy * RW + hx + 1],     t2 = raw[hy * RW + hx + 2];
            float t3 = raw[(hy+1) * RW + hx], t4 = raw[(hy+1) * RW + hx + 1], t5 = raw[(hy+1) * RW + hx + 2];
            float t6 = raw[(hy+2) * RW + hx], t7 = raw[(hy+2) * RW + hx + 1], t8 = raw[(hy+2) * RW + hx + 2];
#pragma unroll
            for (int oc = 0; oc < 32; oc++) {
                const float* w = w1s + oc * 9;
                float s = w1s[288 + oc];
                s += t0*w[0] + t1*w[1] + t2*w[2]
                   + t3*w[3] + t4*w[4] + t5*w[5]
                   + t6*w[6] + t7*w[7] + t8*w[8];
                c1[oc] = fmaxf(s, 0.f);
            }
        } else {
#pragma unroll
            for (int oc = 0; oc < 32; oc++) c1[oc] = 0.f;
        }
#pragma unroll
        for (int p = 0; p < 16; p++) {
            uint32_t lo;
            uint32_t hi = pack_split(c1[2*p], c1[2*p+1], lo);
            hhi[p * PSTR + tid] = hi;
            hlo[p * PSTR + tid] = lo;
        }
    }
    __syncthreads();

    // ---- MMA mainloop (identical to conv_hmma OUTM0) ----
    int m_lo = wid * 16 + rg;
    int m_hi = m_lo + 8;
    int base_lo, base_hi;
    if (MODE == 0) {
        int pl = p0 + m_lo, ph = p0 + m_hi;
        int yl = pl / 33, yh = ph / 33;
        base_lo = (pl < BBSZ) ? (yl - y_first) * 35 + (pl - yl * 33) : 0;
        base_hi = (ph < BBSZ) ? (yh - y_first) * 35 + (ph - yh * 33) : 0;
    } else {
        base_lo = (m_lo >> 3) * 10 + (m_lo & 7);
        base_hi = (m_hi >> 3) * 10 + (m_hi & 7);
    }
    const uint32_t* phi_lo = hhi + l3 * PSTR + base_lo;
    const uint32_t* phi_hi = hhi + l3 * PSTR + base_hi;
    const uint32_t* plo_lo = hlo + l3 * PSTR + base_lo;
    const uint32_t* plo_hi = hlo + l3 * PSTR + base_hi;

    float acc[4][4];
#pragma unroll
    for (int nt = 0; nt < 4; nt++)
#pragma unroll
        for (int i = 0; i < 4; i++) acc[nt][i] = 0.f;

#pragma unroll
    for (int t = 0; t < 9; t++) {
        const int toff = (t / 3) * WROW + (t % 3);
#pragma unroll
        for (int e2 = 0; e2 < 2; e2++) {
            const int c = 2 * t + e2;
            const int pb = e2 * 8 * PSTR + toff;
            uint32_t a0h = phi_lo[pb];
            uint32_t a1h = phi_hi[pb];
            uint32_t a2h = phi_lo[pb + 4 * PSTR];
            uint32_t a3h = phi_hi[pb + 4 * PSTR];
            uint32_t a0l = plo_lo[pb];
            uint32_t a1l = plo_hi[pb];
            uint32_t a2l = plo_lo[pb + 4 * PSTR];
            uint32_t a3l = plo_hi[pb + 4 * PSTR];
            const int kp0 = c * 8 + l3;
#pragma unroll
            for (int nt = 0; nt < 4; nt++) {
                uint2 b0 = wsm[kp0 * 33 + nt * 8 + rg];
                uint2 b1 = wsm[(kp0 + 4) * 33 + nt * 8 + rg];
                HMMA16816(acc[nt], a0h, a1h, a2h, a3h, b0.x, b1.x);
                HMMA16816(acc[nt], a0h, a1h, a2h, a3h, b0.y, b1.y);
                HMMA16816(acc[nt], a0l, a1l, a2l, a3l, b0.x, b1.x);
            }
        }
    }

    // ---- epilogue: NCHW + bias2 + relu ----
    __syncthreads();
    float* sbuf = (float*)smem;
#pragma unroll
    for (int nt = 0; nt < 4; nt++) {
        int oc = nt * 8 + kq;
        sbuf[oc * 132 + m_lo]       = acc[nt][0];
        sbuf[(oc + 1) * 132 + m_lo] = acc[nt][1];
        sbuf[oc * 132 + m_hi]       = acc[nt][2];
        sbuf[(oc + 1) * 132 + m_hi] = acc[nt][3];
    }
    __syncthreads();
    int oc = tid >> 3;
    float bv = bias2[oc];
#pragma unroll
    for (int i = 0; i < 16; i++) {
        int m = (tid & 7) + 8 * i;
        float v = fmaxf(sbuf[oc * 132 + m] + bv, 0.f);
        if (MODE == 0) {
            int p = p0 + m;
            if (p < BBSZ)
                out[(size_t)(n_img * 32 + oc) * BBSZ + p] = v;
        } else {
            int oy = y0t + (m >> 3), ox = x0t + (m & 7);
            if (oy < HP)
                out[((size_t)(n_img * 32 + oc) * HP + oy) * HP + ox] = v;
        }
    }
}

// ---------------- HMMA conv: 32ch NCHW in -> 32/1 ch out ----------------------
// OUTM 0: 32ch NCHW + bias + relu ; 1: 1ch col-major (noise)
// OUTM 3: (MODE 1) X[r,n] -= result (in-place deblock update via blockify map)
template<int MODE, int OUTM>
__global__ void __launch_bounds__(256)
conv_hmma_kernel(const float* __restrict__ in,
                 const uint2* __restrict__ wpack,
                 const float* __restrict__ bias,
                 float* __restrict__ out) {
    extern __shared__ char smem[];
    uint2* wsm = (uint2*)smem;
    constexpr int PSTR = (MODE == 0) ? 245 : 180;
    constexpr int WROW = (MODE == 0) ? 35 : 10;
    uint32_t* hhi = (uint32_t*)(smem + WBYTES);
    uint32_t* hlo = hhi + 16 * PSTR;
    constexpr int NT = (OUTM == 0) ? 4 : 1;

    const int tid = threadIdx.x;
    const int wid = tid >> 5;
    const int lane = tid & 31;
    const int rg = lane >> 2;
    const int l3 = lane & 3;
    const int kq = l3 * 2;

    int n_img, p0 = 0, y_first = 0, y0t = 0, x0t = 0;
    if (MODE == 0) {
        n_img = blockIdx.x / 9;
        p0 = (blockIdx.x % 9) * 128;
        y_first = p0 / 33;
    } else {
        int b = blockIdx.x;
        int tx = b % 33; b /= 33;
        int ty = b % 17; b /= 17;
        n_img = b; y0t = ty * 16; x0t = tx * 8;
    }

    for (int e = tid; e < 144 * 32; e += 256) {
        int kp = e >> 5, oc = e & 31;
        wsm[kp * 33 + oc] = wpack[e];
    }

    if (MODE == 0) {
        for (int e = tid; e < 16 * 245; e += 256) {
            int pair = e / 245, pos = e % 245;
            int row = pos / 35, xp = pos % 35;
            int gy = y_first - 1 + row, gx = xp - 1;
            bool ok = (gy >= 0) && (gy < 33) && (xp >= 1) && (xp < 34);
            size_t bi = (size_t)(n_img * 32 + 2 * pair) * BBSZ + gy * 33 + gx;
            float f0 = ok ? in[bi] : 0.f;
            float f1 = ok ? in[bi + BBSZ] : 0.f;
            uint32_t lo;
            hhi[e] = pack_split(f0, f1, lo);
            hlo[e] = lo;
        }
    } else {
        for (int e = tid; e < 16 * 180; e += 256) {
            int pair = e / 180, pos = e % 180;
            int row = pos / 10, xp = pos % 10;
            int gy = y0t - 1 + row, gx = x0t - 1 + xp;
            bool ok = (gy >= 0) && (gy < HP) && (gx >= 0) && (gx < HP);
            size_t bi = (size_t)(n_img * 32 + 2 * pair) * HP * HP + gy * HP + gx;
            float f0 = ok ? in[bi] : 0.f;
            float f1 = ok ? in[bi + HP * HP] : 0.f;
            uint32_t lo;
            hhi[e] = pack_split(f0, f1, lo);
            hlo[e] = lo;
        }
    }
    __syncthreads();

    int m_lo = wid * 16 + rg;
    int m_hi = m_lo + 8;
    int base_lo, base_hi;
    if (MODE == 0) {
        int pl = p0 + m_lo, ph = p0 + m_hi;
        int yl = pl / 33, yh = ph / 33;
        base_lo = (pl < BBSZ) ? (yl - y_first) * 35 + (pl - yl * 33) : 0;
        base_hi = (ph < BBSZ) ? (yh - y_first) * 35 + (ph - yh * 33) : 0;
    } else {
        base_lo = (m_lo >> 3) * 10 + (m_lo & 7);
        base_hi = (m_hi >> 3) * 10 + (m_hi & 7);
    }
    const uint32_t* phi_lo = hhi + l3 * PSTR + base_lo;
    const uint32_t* phi_hi = hhi + l3 * PSTR + base_hi;
    const uint32_t* plo_lo = hlo + l3 * PSTR + base_lo;
    const uint32_t* plo_hi = hlo + l3 * PSTR + base_hi;

    float acc[NT][4];
#pragma unroll
    for (int nt = 0; nt < NT; nt++)
#pragma unroll
        for (int i = 0; i < 4; i++) acc[nt][i] = 0.f;

#pragma unroll
    for (int t = 0; t < 9; t++) {
        const int toff = (t / 3) * WROW + (t % 3);
#pragma unroll
        for (int e2 = 0; e2 < 2; e2++) {
            const int c = 2 * t + e2;
            const int pb = e2 * 8 * PSTR + toff;
            uint32_t a0h = phi_lo[pb];
            uint32_t a1h = phi_hi[pb];
            uint32_t a2h = phi_lo[pb + 4 * PSTR];
            uint32_t a3h = phi_hi[pb + 4 * PSTR];
            uint32_t a0l = plo_lo[pb];
            uint32_t a1l = plo_hi[pb];
            uint32_t a2l = plo_lo[pb + 4 * PSTR];
            uint32_t a3l = plo_hi[pb + 4 * PSTR];
            const int kp0 = c * 8 + l3;
#pragma unroll
            for (int nt = 0; nt < NT; nt++) {
                uint2 b0 = wsm[kp0 * 33 + nt * 8 + rg];
                uint2 b1 = wsm[(kp0 + 4) * 33 + nt * 8 + rg];
                HMMA16816(acc[nt], a0h, a1h, a2h, a3h, b0.x, b1.x);
                HMMA16816(acc[nt], a0h, a1h, a2h, a3h, b0.y, b1.y);
                HMMA16816(acc[nt], a0l, a1l, a2l, a3l, b0.x, b1.x);
            }
        }
    }

    if (OUTM == 0) {
        __syncthreads();
        float* sbuf = (float*)smem;
#pragma unroll
        for (int nt = 0; nt < NT; nt++) {
            int oc = nt * 8 + kq;
            sbuf[oc * 132 + m_lo]       = acc[nt][0];
            sbuf[(oc + 1) * 132 + m_lo] = acc[nt][1];
            sbuf[oc * 132 + m_hi]       = acc[nt][2];
            sbuf[(oc + 1) * 132 + m_hi] = acc[nt][3];
        }
        __syncthreads();
        int oc = tid >> 3;
        float bv = bias[oc];
#pragma unroll
        for (int i = 0; i < 16; i++) {
            int m = (tid & 7) + 8 * i;
            float v = fmaxf(sbuf[oc * 132 + m] + bv, 0.f);
            if (MODE == 0) {
                int p = p0 + m;
                if (p < BBSZ)
                    out[(size_t)(n_img * 32 + oc) * BBSZ + p] = v;
            } else {
                int oy = y0t + (m >> 3), ox = x0t + (m & 7);
                if (oy < HP)
                    out[((size_t)(n_img * 32 + oc) * HP + oy) * HP + ox] = v;
            }
        }
    } else if (OUTM == 1) {
        if (l3 == 0) {
            int pl = p0 + m_lo, ph = p0 + m_hi;
            if (pl < BBSZ) out[(size_t)pl * NCOL + n_img] = acc[0][0];
            if (ph < BBSZ) out[(size_t)ph * NCOL + n_img] = acc[0][2];
        }
    } else {  // OUTM 3: X -= D via blockify map (MODE 1)
        if (l3 == 0) {
            int gyl = y0t + (m_lo >> 3), gxl = x0t + (m_lo & 7);
            int gyh = y0t + (m_hi >> 3), gxh = x0t + (m_hi & 7);
            if (gyl < HP) { int ix = ximg_idx(n_img, gyl, gxl); out[ix] -= acc[0][0]; }
            if (gyh < HP) { int ix = ximg_idx(n_img, gyh, gxh); out[ix] -= acc[0][2]; }
        }
    }
}

// ---------------- blockify / unblockify ---------------------------------------
__global__ void blockify_input_kernel(const float* __restrict__ in, float* __restrict__ Xb) {
    int idx = blockIdx.x * blockDim.x + threadIdx.x;
    if (idx >= BBSZ * NCOL) return;
    int r = idx / NCOL, n = idx % NCOL;
    int i = r / BQ, j = r % BQ;
    int l = n / (NH * NS), h = (n / NS) % NH, s = n % NS;
    Xb[idx] = in[(s * HP + h * BQ + i) * HP + l * BQ + j];
}
__global__ void unblockify_kernel(const float* __restrict__ X, float* __restrict__ img) {
    int idx = blockIdx.x * blockDim.x + threadIdx.x;
    if (idx >= IMGPIX) return;
    int s = idx / (HP * HP);
    int rem = idx % (HP * HP);
    int R = rem / HP, C = rem % HP;
    int h = R / BQ, i = R % BQ, l = C / BQ, j = C % BQ;
    img[idx] = X[(i * BQ + j) * NCOL + (l * (NH * NS) + h * NS + s)];
}

// ---------------- SIMT GEMM with fused epilogues -------------------------------
#define GBM 64
#define GBN 64
#define GBK 16
__global__ void gemm_kernel(const float* __restrict__ A, const float* __restrict__ B,
                            float* __restrict__ C,
                            int M, int N, int K, int lda, int transA,
                            int epi, const float* __restrict__ E1,
                            const float* __restrict__ E2,
                            const float* __restrict__ stepsPtr, int stepIdx) {
    __shared__ float As[GBK][GBM];
    __shared__ float Bs[GBK][GBN + 1];
    int bm = blockIdx.y * GBM, bn = blockIdx.x * GBN;
    int tid = threadIdx.x;
    int tx = tid % 16, ty = tid / 16;
    float acc[4][4];
#pragma unroll
    for (int i = 0; i < 4; i++)
#pragma unroll
        for (int j = 0; j < 4; j++) acc[i][j] = 0.f;
    for (int k0 = 0; k0 < K; k0 += GBK) {
        if (transA) {
            for (int e = tid; e < GBM * GBK; e += 256) {
                int k = e / GBM, mm = e % GBM;
                int gm = bm + mm, gk = k0 + k;
                As[k][mm] = (gm < M && gk < K) ? A[(size_t)gk * lda + gm] : 0.f;
            }
        } else {
            for (int e = tid; e < GBM * GBK; e += 256) {
                int mm = e / GBK, k = e % GBK;
                int gm = bm + mm, gk = k0 + k;
                As[k][mm] = (gm < M && gk < K) ? A[(size_t)gm * lda + gk] : 0.f;
            }
        }
        for (int e = tid; e < GBK * GBN; e += 256) {
            int k = e / GBN, nn = e % GBN;
            int gk = k0 + k, gn = bn + nn;
            Bs[k][nn] = (gk < K && gn < N) ? B[(size_t)gk * N + gn] : 0.f;
        }
        __syncthreads();
#pragma unroll
        for (int k = 0; k < GBK; k++) {
            float a[4], b[4];
#pragma unroll
            for (int i = 0; i < 4; i++) a[i] = As[k][ty * 4 + i];
#pragma unroll
            for (int j = 0; j < 4; j++) b[j] = Bs[k][tx * 4 + j];
#pragma unroll
            for (int i = 0; i < 4; i++)
#pragma unroll
                for (int j = 0; j < 4; j++) acc[i][j] += a[i] * b[j];
        }
        __syncthreads();
    }
    float step = (stepsPtr != nullptr) ? stepsPtr[stepIdx] : 0.f;
#pragma unroll
    for (int i = 0; i < 4; i++) {
        int gm = bm + ty * 4 + i;
        if (gm >= M) continue;
#pragma unroll
        for (int j = 0; j < 4; j++) {
            int gn = bn + tx * 4 + j;
            if (gn >= N) continue;
            size_t idx = (size_t)gm * N + gn;
            float v = acc[i][j], o;
            if (epi == 0)      o = v;
            else if (epi == 1) o = E1[idx] - v;
            else if (epi == 2) o = step * v + E1[idx];
            else               o = E1[idx] - step * v + E2[idx];
            C[idx] = o;
        }
    }
}

// ---------------- host driver --------------------------------------------------
extern "C" void kernel_launch(void* const* d_in, const int* in_sizes, int n_in,
                              void* d_out, int out_size) {
    const float* inputs = (const float*)d_in[0];
    const float* A      = (const float*)d_in[1];
    const float* Q      = (const float*)d_in[2];
    const float* steps  = (const float*)d_in[3];
    const float* den_w1 = (const float*)d_in[4];
    const float* den_b1 = (const float*)d_in[5];
    const float* den_w2 = (const float*)d_in[6];
    const float* den_b2 = (const float*)d_in[7];
    const float* den_w3 = (const float*)d_in[8];
    const float* den_b3 = (const float*)d_in[9];
    const float* den_w4 = (const float*)d_in[10];
    const float* deb_w1 = (const float*)d_in[11];
    const float* deb_b1 = (const float*)d_in[12];
    const float* deb_w2 = (const float*)d_in[13];
    const float* deb_b2 = (const float*)d_in[14];
    const float* deb_w3 = (const float*)d_in[15];
    const float* deb_b3 = (const float*)d_in[16];
    const float* deb_w4 = (const float*)d_in[17];
    int layers = in_sizes[3];

    float *pX, *pY, *pR, *pZ, *pN, *pAtA, *pT1, *pT2;
    uint2* pWp;
    cudaGetSymbolAddress((void**)&pX, g_X);
    cudaGetSymbolAddress((void**)&pY, g_y);
    cudaGetSymbolAddress((void**)&pR, g_r);
    cudaGetSymbolAddress((void**)&pZ, g_z);
    cudaGetSymbolAddress((void**)&pN, g_noise);
    cudaGetSymbolAddress((void**)&pAtA, g_AtA);
    cudaGetSymbolAddress((void**)&pT1, g_t1);
    cudaGetSymbolAddress((void**)&pT2, g_t2);
    cudaGetSymbolAddress((void**)&pWp, g_wpack);

    const int EW = 256;
    const int EG = (IMGPIX + EW - 1) / EW;
    dim3 gN512M272((NCOL + GBN - 1) / GBN, (MROW + GBM - 1) / GBM);
    dim3 gN512M1089((NCOL + GBN - 1) / GBN, (BBSZ + GBM - 1) / GBM);
    dim3 gAtA((BBSZ + GBN - 1) / GBN, (BBSZ + GBM - 1) / GBM);

    const int SM0 = WBYTES + 2 * 16 * 245 * 4;                       // 69376
    const int SM1 = WBYTES + 2 * 16 * 180 * 4;                       // 61056
    const int SM12_0 = SM0 + ((9 * 37 + 3) & ~3) * 4 + 320 * 4;      // + raw + w1
    const int SM12_1 = SM1 + ((20 * 12 + 3) & ~3) * 4 + 320 * 4;
    cudaFuncSetAttribute(conv12_hmma<0>, cudaFuncAttributeMaxDynamicSharedMemorySize, SM12_0);
    cudaFuncSetAttribute(conv12_hmma<1>, cudaFuncAttributeMaxDynamicSharedMemorySize, SM12_1);
    cudaFuncSetAttribute(conv_hmma_kernel<0,0>, cudaFuncAttributeMaxDynamicSharedMemorySize, SM0);
    cudaFuncSetAttribute(conv_hmma_kernel<0,1>, cudaFuncAttributeMaxDynamicSharedMemorySize, SM0);
    cudaFuncSetAttribute(conv_hmma_kernel<1,0>, cudaFuncAttributeMaxDynamicSharedMemorySize, SM1);
    cudaFuncSetAttribute(conv_hmma_kernel<1,3>, cudaFuncAttributeMaxDynamicSharedMemorySize, SM1);

    prep_weights<<<dim3(6, layers), 256>>>(den_w2, den_w3, den_w4,
                                           deb_w2, deb_w3, deb_w4, pWp);

    blockify_input_kernel<<<EG, EW>>>(inputs, pZ);
    gemm_kernel<<<gN512M272, 256>>>(A, pZ, pY, MROW, NCOL, BBSZ, BBSZ, 0, 0,
                                    nullptr, nullptr, nullptr, 0);
    gemm_kernel<<<gN512M1089, 256>>>(Q, pY, pX, BBSZ, NCOL, MROW, MROW, 0, 0,
                                     nullptr, nullptr, nullptr, 0);
    gemm_kernel<<<gAtA, 256>>>(A, A, pAtA, BBSZ, BBSZ, MROW, BBSZ, 1, 0,
                               nullptr, nullptr, nullptr, 0);

    const int G0 = NCOL * 9;          // 4608
    const int G1 = 8 * 17 * 33;       // 4488

    for (int n = 0; n < layers; n++) {
        const uint2* wp = pWp + (size_t)(n * 6) * 4608;
        gemm_kernel<<<gN512M272, 256>>>(A, pX, pR, MROW, NCOL, BBSZ, BBSZ, 0, 1,
                                        pY, nullptr, nullptr, 0);
        gemm_kernel<<<gN512M1089, 256>>>(A, pR, pZ, BBSZ, NCOL, MROW, BBSZ, 1, 2,
                                         pX, nullptr, steps, n);
        // denoise: fused conv1+2, conv3, conv4(noise col-major)
        conv12_hmma<0><<<G0, 256, SM12_0>>>(pX, den_w1 + (size_t)n * 32 * 9,
                                            den_b1 + n * 32, wp + 0 * 4608,
                                            den_b2 + n * 32, pT1);
        conv_hmma_kernel<0,0><<<G0, 256, SM0>>>(pT1, wp + 1 * 4608, den_b3 + n * 32, pT2);
        conv_hmma_kernel<0,1><<<G0, 256, SM0>>>(pT2, wp + 2 * 4608, nullptr, pN);
        gemm_kernel<<<gN512M1089, 256>>>(pAtA, pN, pX, BBSZ, NCOL, BBSZ, BBSZ, 0, 3,
                                         pZ, pN, steps, n);
        // deblock: fused conv1+2 (reads X via unblockify map), conv3,
        // conv4 (X -= D in place via blockify map)
        conv12_hmma<1><<<G1, 256, SM12_1>>>(pX, deb_w1 + (size_t)n * 32 * 9,
                                            deb_b1 + n * 32, wp + 3 * 4608,
                                            deb_b2 + n * 32, pT1);
        conv_hmma_kernel<1,0><<<G1, 256, SM1>>>(pT1, wp + 4 * 4608, deb_b3 + n * 32, pT2);
        conv_hmma_kernel<1,3><<<G1, 256, SM1>>>(pT2, wp + 5 * 4608, nullptr, pX);
    }

    unblockify_kernel<<<EG, EW>>>(pX, (float*)d_out);
}

// round 8
// speedup vs baseline: 2.1572x; 1.2025x over previous
#include <cuda_runtime.h>
#include <cuda_fp16.h>
#include <cstdint>

#define BQ   33
#define BBSZ 1089
#define NS   8
#define NH   8
#define NL   8
#define NCOL 512
#define MROW 272
#define HP   264
#define IMGPIX (NS*HP*HP)

// ---------------- scratch ----------------------------------------------------
__device__ float g_X[BBSZ * NCOL];
__device__ float g_y[MROW * NCOL];
__device__ float g_r[MROW * NCOL];
__device__ float g_z[BBSZ * NCOL];
__device__ float g_noise[BBSZ * NCOL];
__device__ float g_AtA[BBSZ * BBSZ];
__device__ float g_t1[(size_t)NCOL * 32 * BBSZ];
__device__ float g_t2[(size_t)NCOL * 32 * BBSZ];
__device__ uint32_t g_wpack[8 * 6 * 2 * 4608];  // [layer][set][hi|lo][144*32]

// ---------------- HMMA helpers ------------------------------------------------
#define HMMA16816(c, a0, a1, a2, a3, b0, b1) \
    asm volatile("mma.sync.aligned.m16n8k16.row.col.f32.f16.f16.f32 " \
        "{%0,%1,%2,%3}, {%4,%5,%6,%7}, {%8,%9}, {%0,%1,%2,%3};" \
        : "+f"((c)[0]), "+f"((c)[1]), "+f"((c)[2]), "+f"((c)[3]) \
        : "r"(a0), "r"(a1), "r"(a2), "r"(a3), "r"(b0), "r"(b1))

__device__ __forceinline__ uint32_t h2bits(__half2 h) {
    return *reinterpret_cast<uint32_t*>(&h);
}
__device__ __forceinline__ uint32_t pack_split(float x, float y, uint32_t& lo) {
    __half2 h = __floats2half2_rn(x, y);
    __half2 l = __floats2half2_rn(x - __low2float(h), y - __high2float(h));
    lo = h2bits(l);
    return h2bits(h);
}

// ---------------- weight pre-pack (once per run) -------------------------------
__global__ void prep_weights(const float* __restrict__ dw2, const float* __restrict__ dw3,
                             const float* __restrict__ dw4, const float* __restrict__ bw2,
                             const float* __restrict__ bw3, const float* __restrict__ bw4,
                             uint32_t* __restrict__ outp) {
    int set = blockIdx.x, n = blockIdx.y;
    const float* wt; int coutr;
    switch (set) {
        case 0: wt = dw2 + (size_t)n * 32 * 32 * 9; coutr = 32; break;
        case 1: wt = dw3 + (size_t)n * 32 * 32 * 9; coutr = 32; break;
        case 2: wt = dw4 + (size_t)n * 32 * 9;      coutr = 1;  break;
        case 3: wt = bw2 + (size_t)n * 32 * 32 * 9; coutr = 32; break;
        case 4: wt = bw3 + (size_t)n * 32 * 32 * 9; coutr = 32; break;
        default: wt = bw4 + (size_t)n * 32 * 9;     coutr = 1;  break;
    }
    uint32_t* o = outp + ((size_t)n * 6 + set) * 9216;
    for (int e = threadIdx.x; e < 144 * 32; e += 256) {
        int kp = e >> 5, oc = e & 31;
        int k0 = 2 * kp;
        int tap = k0 >> 5, ic = k0 & 31;
        float w0 = 0.f, w1 = 0.f;
        if (oc < coutr) {
            w0 = wt[(oc * 32 + ic) * 9 + tap];
            w1 = wt[(oc * 32 + ic + 1) * 9 + tap];
        }
        uint32_t lo;
        uint32_t hi = pack_split(w0, w1, lo);
        o[e] = hi;
        o[4608 + e] = lo;
    }
}

// X col-major index of image pixel (s, gy, gx)
__device__ __forceinline__ int ximg_idx(int s, int gy, int gx) {
    int h = gy / 33, i = gy % 33, l = gx / 33, j = gx % 33;
    return (i * 33 + j) * NCOL + l * (NH * NS) + h * NS + s;
}

#define WSTR   40                      // weight smem stride (40 % 32 == 8 -> conflict-free)
#define WBYTES (2 * 144 * WSTR * 4)    // 46080

// ============ fused conv1(1->32,relu)+conv2(32->32,relu) via HMMA ==============
template<int MODE>
__global__ void __launch_bounds__(256)
conv12_hmma(const float* __restrict__ xin,
            const float* __restrict__ w1g,
            const float* __restrict__ b1g,
            const uint32_t* __restrict__ wpack,
            const float* __restrict__ bias2,
            float* __restrict__ out) {
    extern __shared__ char smem[];
    constexpr int PSTR = (MODE == 0) ? 248 : 184;   // % 32 == 24 -> conflict-free
    constexpr int WROW = (MODE == 0) ? 35 : 10;
    constexpr int NPOS = (MODE == 0) ? 245 : 180;
    constexpr int RW   = (MODE == 0) ? 37 : 12;
    constexpr int RAWN = (MODE == 0) ? 9 * 37 : 20 * 12;
    uint32_t* wh = (uint32_t*)smem;                 // [144][WSTR]
    uint32_t* wl = wh + 144 * WSTR;
    uint32_t* hhi = (uint32_t*)(smem + WBYTES);     // [16][PSTR]
    uint32_t* hlo = hhi + 16 * PSTR;
    float* raw = (float*)(smem + WBYTES + 2 * 16 * PSTR * 4);
    float* w1s = raw + ((RAWN + 3) & ~3);

    const int tid = threadIdx.x;
    const int wid = tid >> 5;
    const int lane = tid & 31;
    const int rg = lane >> 2;
    const int l3 = lane & 3;
    const int kq = l3 * 2;

    int n_img, p0 = 0, y_first = 0, y0t = 0, x0t = 0;
    if (MODE == 0) {
        n_img = blockIdx.x / 9;
        p0 = (blockIdx.x % 9) * 128;
        y_first = p0 / 33;
    } else {
        int b = blockIdx.x;
        int tx = b % 33; b /= 33;
        int ty = b % 17; b /= 17;
        n_img = b; y0t = ty * 16; x0t = tx * 8;
    }

    for (int e = tid; e < 144 * 32; e += 256) {
        int kp = e >> 5, oc = e & 31;
        wh[kp * WSTR + oc] = wpack[e];
        wl[kp * WSTR + oc] = wpack[4608 + e];
    }
    for (int e = tid; e < 320; e += 256)
        w1s[e] = (e < 288) ? w1g[e] : b1g[e - 288];
    if (MODE == 0) {
        for (int e = tid; e < RAWN; e += 256) {
            int ry = e / RW, rx = e % RW;
            int gy = y_first - 2 + ry, gx = rx - 2;
            bool ok = (gy >= 0) && (gy < 33) && (gx >= 0) && (gx < 33);
            raw[e] = ok ? xin[(gy * 33 + gx) * NCOL + n_img] : 0.f;
        }
    } else {
        for (int e = tid; e < RAWN; e += 256) {
            int ry = e / RW, rx = e % RW;
            int gy = y0t - 2 + ry, gx = x0t - 2 + rx;
            bool ok = (gy >= 0) && (gy < HP) && (gx >= 0) && (gx < HP);
            raw[e] = ok ? xin[ximg_idx(n_img, gy, gx)] : 0.f;
        }
    }
    __syncthreads();

    if (tid < NPOS) {
        int hy = tid / WROW, hx = tid % WROW;
        int gy, gx, GHW;
        if (MODE == 0) { gy = y_first - 1 + hy; gx = hx - 1; GHW = 33; }
        else           { gy = y0t - 1 + hy;     gx = x0t - 1 + hx; GHW = HP; }
        bool valid = (gy >= 0) && (gy < GHW) && (gx >= 0) && (gx < ((MODE == 0) ? 33 : HP));
        float c1[32];
        if (valid) {
            float t0 = raw[hy * RW + hx],     t1 = raw[hy * RW + hx + 1],     t2 = raw[hy * RW + hx + 2];
            float t3 = raw[(hy+1) * RW + hx], t4 = raw[(hy+1) * RW + hx + 1], t5 = raw[(hy+1) * RW + hx + 2];
            float t6 = raw[(hy+2) * RW + hx], t7 = raw[(hy+2) * RW + hx + 1], t8 = raw[(hy+2) * RW + hx + 2];
#pragma unroll
            for (int oc = 0; oc < 32; oc++) {
                const float* w = w1s + oc * 9;
                float s = w1s[288 + oc];
                s += t0*w[0] + t1*w[1] + t2*w[2]
                   + t3*w[3] + t4*w[4] + t5*w[5]
                   + t6*w[6] + t7*w[7] + t8*w[8];
                c1[oc] = fmaxf(s, 0.f);
            }
        } else {
#pragma unroll
            for (int oc = 0; oc < 32; oc++) c1[oc] = 0.f;
        }
#pragma unroll
        for (int p = 0; p < 16; p++) {
            uint32_t lo;
            uint32_t hi = pack_split(c1[2*p], c1[2*p+1], lo);
            hhi[p * PSTR + tid] = hi;
            hlo[p * PSTR + tid] = lo;
        }
    }
    __syncthreads();

    int m_lo = wid * 16 + rg;
    int m_hi = m_lo + 8;
    int base_lo, base_hi;
    if (MODE == 0) {
        int pl = p0 + m_lo, ph = p0 + m_hi;
        int yl = pl / 33, yh = ph / 33;
        base_lo = (pl < BBSZ) ? (yl - y_first) * 35 + (pl - yl * 33) : 0;
        base_hi = (ph < BBSZ) ? (yh - y_first) * 35 + (ph - yh * 33) : 0;
    } else {
        base_lo = (m_lo >> 3) * 10 + (m_lo & 7);
        base_hi = (m_hi >> 3) * 10 + (m_hi & 7);
    }
    const uint32_t* phi_lo = hhi + l3 * PSTR + base_lo;
    const uint32_t* phi_hi = hhi + l3 * PSTR + base_hi;
    const uint32_t* plo_lo = hlo + l3 * PSTR + base_lo;
    const uint32_t* plo_hi = hlo + l3 * PSTR + base_hi;

    float acc[4][4];
#pragma unroll
    for (int nt = 0; nt < 4; nt++)
#pragma unroll
        for (int i = 0; i < 4; i++) acc[nt][i] = 0.f;

#pragma unroll
    for (int t = 0; t < 9; t++) {
        const int toff = (t / 3) * WROW + (t % 3);
#pragma unroll
        for (int e2 = 0; e2 < 2; e2++) {
            const int c = 2 * t + e2;
            const int pb = e2 * 8 * PSTR + toff;
            uint32_t a0h = phi_lo[pb];
            uint32_t a1h = phi_hi[pb];
            uint32_t a2h = phi_lo[pb + 4 * PSTR];
            uint32_t a3h = phi_hi[pb + 4 * PSTR];
            uint32_t a0l = plo_lo[pb];
            uint32_t a1l = plo_hi[pb];
            uint32_t a2l = plo_lo[pb + 4 * PSTR];
            uint32_t a3l = plo_hi[pb + 4 * PSTR];
            const int kb = (c * 8 + l3) * WSTR + rg;
#pragma unroll
            for (int nt = 0; nt < 4; nt++) {
                uint32_t bh0 = wh[kb + nt * 8];
                uint32_t bh1 = wh[kb + 4 * WSTR + nt * 8];
                uint32_t bl0 = wl[kb + nt * 8];
                uint32_t bl1 = wl[kb + 4 * WSTR + nt * 8];
                HMMA16816(acc[nt], a0h, a1h, a2h, a3h, bh0, bh1);
                HMMA16816(acc[nt], a0h, a1h, a2h, a3h, bl0, bl1);
                HMMA16816(acc[nt], a0l, a1l, a2l, a3l, bh0, bh1);
            }
        }
    }

    __syncthreads();
    float* sbuf = (float*)smem;
#pragma unroll
    for (int nt = 0; nt < 4; nt++) {
        int oc = nt * 8 + kq;
        sbuf[oc * 132 + m_lo]       = acc[nt][0];
        sbuf[(oc + 1) * 132 + m_lo] = acc[nt][1];
        sbuf[oc * 132 + m_hi]       = acc[nt][2];
        sbuf[(oc + 1) * 132 + m_hi] = acc[nt][3];
    }
    __syncthreads();
    int oc = tid >> 3;
    float bv = bias2[oc];
#pragma unroll
    for (int i = 0; i < 16; i++) {
        int m = (tid & 7) + 8 * i;
        float v = fmaxf(sbuf[oc * 132 + m] + bv, 0.f);
        if (MODE == 0) {
            int p = p0 + m;
            if (p < BBSZ)
                out[(size_t)(n_img * 32 + oc) * BBSZ + p] = v;
        } else {
            int oy = y0t + (m >> 3), ox = x0t + (m & 7);
            if (oy < HP)
                out[((size_t)(n_img * 32 + oc) * HP + oy) * HP + ox] = v;
        }
    }
}

// ---------------- HMMA conv: 32ch NCHW in -> 32/1 ch out ----------------------
template<int MODE, int OUTM>
__global__ void __launch_bounds__(256)
conv_hmma_kernel(const float* __restrict__ in,
                 const uint32_t* __restrict__ wpack,
                 const float* __restrict__ bias,
                 float* __restrict__ out) {
    extern __shared__ char smem[];
    uint32_t* wh = (uint32_t*)smem;
    uint32_t* wl = wh + 144 * WSTR;
    constexpr int PSTR = (MODE == 0) ? 248 : 184;
    constexpr int WROW = (MODE == 0) ? 35 : 10;
    uint32_t* hhi = (uint32_t*)(smem + WBYTES);
    uint32_t* hlo = hhi + 16 * PSTR;
    constexpr int NT = (OUTM == 0) ? 4 : 1;

    const int tid = threadIdx.x;
    const int wid = tid >> 5;
    const int lane = tid & 31;
    const int rg = lane >> 2;
    const int l3 = lane & 3;
    const int kq = l3 * 2;

    int n_img, p0 = 0, y_first = 0, y0t = 0, x0t = 0;
    if (MODE == 0) {
        n_img = blockIdx.x / 9;
        p0 = (blockIdx.x % 9) * 128;
        y_first = p0 / 33;
    } else {
        int b = blockIdx.x;
        int tx = b % 33; b /= 33;
        int ty = b % 17; b /= 17;
        n_img = b; y0t = ty * 16; x0t = tx * 8;
    }

    for (int e = tid; e < 144 * 32; e += 256) {
        int kp = e >> 5, oc = e & 31;
        wh[kp * WSTR + oc] = wpack[e];
        wl[kp * WSTR + oc] = wpack[4608 + e];
    }

    if (MODE == 0) {
        for (int e = tid; e < 16 * 245; e += 256) {
            int pair = e / 245, pos = e % 245;
            int row = pos / 35, xp = pos % 35;
            int gy = y_first - 1 + row, gx = xp - 1;
            bool ok = (gy >= 0) && (gy < 33) && (xp >= 1) && (xp < 34);
            size_t bi = (size_t)(n_img * 32 + 2 * pair) * BBSZ + gy * 33 + gx;
            float f0 = ok ? in[bi] : 0.f;
            float f1 = ok ? in[bi + BBSZ] : 0.f;
            uint32_t lo;
            uint32_t hi = pack_split(f0, f1, lo);
            hhi[pair * PSTR + pos] = hi;
            hlo[pair * PSTR + pos] = lo;
        }
    } else {
        for (int e = tid; e < 16 * 180; e += 256) {
            int pair = e / 180, pos = e % 180;
            int row = pos / 10, xp = pos % 10;
            int gy = y0t - 1 + row, gx = x0t - 1 + xp;
            bool ok = (gy >= 0) && (gy < HP) && (gx >= 0) && (gx < HP);
            size_t bi = (size_t)(n_img * 32 + 2 * pair) * HP * HP + gy * HP + gx;
            float f0 = ok ? in[bi] : 0.f;
            float f1 = ok ? in[bi + HP * HP] : 0.f;
            uint32_t lo;
            uint32_t hi = pack_split(f0, f1, lo);
            hhi[pair * PSTR + pos] = hi;
            hlo[pair * PSTR + pos] = lo;
        }
    }
    __syncthreads();

    int m_lo = wid * 16 + rg;
    int m_hi = m_lo + 8;
    int base_lo, base_hi;
    if (MODE == 0) {
        int pl = p0 + m_lo, ph = p0 + m_hi;
        int yl = pl / 33, yh = ph / 33;
        base_lo = (pl < BBSZ) ? (yl - y_first) * 35 + (pl - yl * 33) : 0;
        base_hi = (ph < BBSZ) ? (yh - y_first) * 35 + (ph - yh * 33) : 0;
    } else {
        base_lo = (m_lo >> 3) * 10 + (m_lo & 7);
        base_hi = (m_hi >> 3) * 10 + (m_hi & 7);
    }
    const uint32_t* phi_lo = hhi + l3 * PSTR + base_lo;
    const uint32_t* phi_hi = hhi + l3 * PSTR + base_hi;
    const uint32_t* plo_lo = hlo + l3 * PSTR + base_lo;
    const uint32_t* plo_hi = hlo + l3 * PSTR + base_hi;

    float acc[NT][4];
#pragma unroll
    for (int nt = 0; nt < NT; nt++)
#pragma unroll
        for (int i = 0; i < 4; i++) acc[nt][i] = 0.f;

#pragma unroll
    for (int t = 0; t < 9; t++) {
        const int toff = (t / 3) * WROW + (t % 3);
#pragma unroll
        for (int e2 = 0; e2 < 2; e2++) {
            const int c = 2 * t + e2;
            const int pb = e2 * 8 * PSTR + toff;
            uint32_t a0h = phi_lo[pb];
            uint32_t a1h = phi_hi[pb];
            uint32_t a2h = phi_lo[pb + 4 * PSTR];
            uint32_t a3h = phi_hi[pb + 4 * PSTR];
            uint32_t a0l = plo_lo[pb];
            uint32_t a1l = plo_hi[pb];
            uint32_t a2l = plo_lo[pb + 4 * PSTR];
            uint32_t a3l = plo_hi[pb + 4 * PSTR];
            const int kb = (c * 8 + l3) * WSTR + rg;
#pragma unroll
            for (int nt = 0; nt < NT; nt++) {
                uint32_t bh0 = wh[kb + nt * 8];
                uint32_t bh1 = wh[kb + 4 * WSTR + nt * 8];
                uint32_t bl0 = wl[kb + nt * 8];
                uint32_t bl1 = wl[kb + 4 * WSTR + nt * 8];
                HMMA16816(acc[nt], a0h, a1h, a2h, a3h, bh0, bh1);
                HMMA16816(acc[nt], a0h, a1h, a2h, a3h, bl0, bl1);
                HMMA16816(acc[nt], a0l, a1l, a2l, a3l, bh0, bh1);
            }
        }
    }

    if (OUTM == 0) {
        __syncthreads();
        float* sbuf = (float*)smem;
#pragma unroll
        for (int nt = 0; nt < NT; nt++) {
            int oc = nt * 8 + kq;
            sbuf[oc * 132 + m_lo]       = acc[nt][0];
            sbuf[(oc + 1) * 132 + m_lo] = acc[nt][1];
            sbuf[oc * 132 + m_hi]       = acc[nt][2];
            sbuf[(oc + 1) * 132 + m_hi] = acc[nt][3];
        }
        __syncthreads();
        int oc = tid >> 3;
        float bv = bias[oc];
#pragma unroll
        for (int i = 0; i < 16; i++) {
            int m = (tid & 7) + 8 * i;
            float v = fmaxf(sbuf[oc * 132 + m] + bv, 0.f);
            if (MODE == 0) {
                int p = p0 + m;
                if (p < BBSZ)
                    out[(size_t)(n_img * 32 + oc) * BBSZ + p] = v;
            } else {
                int oy = y0t + (m >> 3), ox = x0t + (m & 7);
                if (oy < HP)
                    out[((size_t)(n_img * 32 + oc) * HP + oy) * HP + ox] = v;
            }
        }
    } else if (OUTM == 1) {
        if (l3 == 0) {
            int pl = p0 + m_lo, ph = p0 + m_hi;
            if (pl < BBSZ) out[(size_t)pl * NCOL + n_img] = acc[0][0];
            if (ph < BBSZ) out[(size_t)ph * NCOL + n_img] = acc[0][2];
        }
    } else {
        if (l3 == 0) {
            int gyl = y0t + (m_lo >> 3), gxl = x0t + (m_lo & 7);
            int gyh = y0t + (m_hi >> 3), gxh = x0t + (m_hi & 7);
            if (gyl < HP) { int ix = ximg_idx(n_img, gyl, gxl); out[ix] -= acc[0][0]; }
            if (gyh < HP) { int ix = ximg_idx(n_img, gyh, gxh); out[ix] -= acc[0][2]; }
        }
    }
}

// ---------------- blockify / unblockify ---------------------------------------
__global__ void blockify_input_kernel(const float* __restrict__ in, float* __restrict__ Xb) {
    int idx = blockIdx.x * blockDim.x + threadIdx.x;
    if (idx >= BBSZ * NCOL) return;
    int r = idx / NCOL, n = idx % NCOL;
    int i = r / BQ, j = r % BQ;
    int l = n / (NH * NS), h = (n / NS) % NH, s = n % NS;
    Xb[idx] = in[(s * HP + h * BQ + i) * HP + l * BQ + j];
}
__global__ void unblockify_kernel(const float* __restrict__ X, float* __restrict__ img) {
    int idx = blockIdx.x * blockDim.x + threadIdx.x;
    if (idx >= IMGPIX) return;
    int s = idx / (HP * HP);
    int rem = idx % (HP * HP);
    int R = rem / HP, C = rem % HP;
    int h = R / BQ, i = R % BQ, l = C / BQ, j = C % BQ;
    img[idx] = X[(i * BQ + j) * NCOL + (l * (NH * NS) + h * NS + s)];
}

// ---------------- SIMT GEMM with fused epilogues -------------------------------
#define GBM 64
#define GBN 64
#define GBK 16
__global__ void gemm_kernel(const float* __restrict__ A, const float* __restrict__ B,
                            float* __restrict__ C,
                            int M, int N, int K, int lda, int transA,
                            int epi, const float* __restrict__ E1,
                            const float* __restrict__ E2,
                            const float* __restrict__ stepsPtr, int stepIdx) {
    __shared__ float As[GBK][GBM];
    __shared__ float Bs[GBK][GBN + 1];
    int bm = blockIdx.y * GBM, bn = blockIdx.x * GBN;
    int tid = threadIdx.x;
    int tx = tid % 16, ty = tid / 16;
    float acc[4][4];
#pragma unroll
    for (int i = 0; i < 4; i++)
#pragma unroll
        for (int j = 0; j < 4; j++) acc[i][j] = 0.f;
    for (int k0 = 0; k0 < K; k0 += GBK) {
        if (transA) {
            for (int e = tid; e < GBM * GBK; e += 256) {
                int k = e / GBM, mm = e % GBM;
                int gm = bm + mm, gk = k0 + k;
                As[k][mm] = (gm < M && gk < K) ? A[(size_t)gk * lda + gm] : 0.f;
            }
        } else {
            for (int e = tid; e < GBM * GBK; e += 256) {
                int mm = e / GBK, k = e % GBK;
                int gm = bm + mm, gk = k0 + k;
                As[k][mm] = (gm < M && gk < K) ? A[(size_t)gm * lda + gk] : 0.f;
            }
        }
        for (int e = tid; e < GBK * GBN; e += 256) {
            int k = e / GBN, nn = e % GBN;
            int gk = k0 + k, gn = bn + nn;
            Bs[k][nn] = (gk < K && gn < N) ? B[(size_t)gk * N + gn] : 0.f;
        }
        __syncthreads();
#pragma unroll
        for (int k = 0; k < GBK; k++) {
            float a[4], b[4];
#pragma unroll
            for (int i = 0; i < 4; i++) a[i] = As[k][ty * 4 + i];
#pragma unroll
            for (int j = 0; j < 4; j++) b[j] = Bs[k][tx * 4 + j];
#pragma unroll
            for (int i = 0; i < 4; i++)
#pragma unroll
                for (int j = 0; j < 4; j++) acc[i][j] += a[i] * b[j];
        }
        __syncthreads();
    }
    float step = (stepsPtr != nullptr) ? stepsPtr[stepIdx] : 0.f;
#pragma unroll
    for (int i = 0; i < 4; i++) {
        int gm = bm + ty * 4 + i;
        if (gm >= M) continue;
#pragma unroll
        for (int j = 0; j < 4; j++) {
            int gn = bn + tx * 4 + j;
            if (gn >= N) continue;
            size_t idx = (size_t)gm * N + gn;
            float v = acc[i][j], o;
            if (epi == 0)      o = v;
            else if (epi == 1) o = E1[idx] - v;
            else if (epi == 2) o = step * v + E1[idx];
            else               o = E1[idx] - step * v + E2[idx];
            C[idx] = o;
        }
    }
}

// ---------------- host driver --------------------------------------------------
extern "C" void kernel_launch(void* const* d_in, const int* in_sizes, int n_in,
                              void* d_out, int out_size) {
    const float* inputs = (const float*)d_in[0];
    const float* A      = (const float*)d_in[1];
    const float* Q      = (const float*)d_in[2];
    const float* steps  = (const float*)d_in[3];
    const float* den_w1 = (const float*)d_in[4];
    const float* den_b1 = (const float*)d_in[5];
    const float* den_w2 = (const float*)d_in[6];
    const float* den_b2 = (const float*)d_in[7];
    const float* den_w3 = (const float*)d_in[8];
    const float* den_b3 = (const float*)d_in[9];
    const float* den_w4 = (const float*)d_in[10];
    const float* deb_w1 = (const float*)d_in[11];
    const float* deb_b1 = (const float*)d_in[12];
    const float* deb_w2 = (const float*)d_in[13];
    const float* deb_b2 = (const float*)d_in[14];
    const float* deb_w3 = (const float*)d_in[15];
    const float* deb_b3 = (const float*)d_in[16];
    const float* deb_w4 = (const float*)d_in[17];
    int layers = in_sizes[3];

    float *pX, *pY, *pR, *pZ, *pN, *pAtA, *pT1, *pT2;
    uint32_t* pWp;
    cudaGetSymbolAddress((void**)&pX, g_X);
    cudaGetSymbolAddress((void**)&pY, g_y);
    cudaGetSymbolAddress((void**)&pR, g_r);
    cudaGetSymbolAddress((void**)&pZ, g_z);
    cudaGetSymbolAddress((void**)&pN, g_noise);
    cudaGetSymbolAddress((void**)&pAtA, g_AtA);
    cudaGetSymbolAddress((void**)&pT1, g_t1);
    cudaGetSymbolAddress((void**)&pT2, g_t2);
    cudaGetSymbolAddress((void**)&pWp, g_wpack);

    const int EW = 256;
    const int EG = (IMGPIX + EW - 1) / EW;
    dim3 gN512M272((NCOL + GBN - 1) / GBN, (MROW + GBM - 1) / GBM);
    dim3 gN512M1089((NCOL + GBN - 1) / GBN, (BBSZ + GBM - 1) / GBM);
    dim3 gAtA((BBSZ + GBN - 1) / GBN, (BBSZ + GBM - 1) / GBM);

    const int SM0 = WBYTES + 2 * 16 * 248 * 4;                    // 77824
    const int SM1 = WBYTES + 2 * 16 * 184 * 4;                    // 69632
    const int SM12_0 = SM0 + ((9 * 37 + 3) & ~3) * 4 + 320 * 4;   // 80448
    const int SM12_1 = SM1 + ((20 * 12 + 3) & ~3) * 4 + 320 * 4;  // 71872
    cudaFuncSetAttribute(conv12_hmma<0>, cudaFuncAttributeMaxDynamicSharedMemorySize, SM12_0);
    cudaFuncSetAttribute(conv12_hmma<1>, cudaFuncAttributeMaxDynamicSharedMemorySize, SM12_1);
    cudaFuncSetAttribute(conv_hmma_kernel<0,0>, cudaFuncAttributeMaxDynamicSharedMemorySize, SM0);
    cudaFuncSetAttribute(conv_hmma_kernel<0,1>, cudaFuncAttributeMaxDynamicSharedMemorySize, SM0);
    cudaFuncSetAttribute(conv_hmma_kernel<1,0>, cudaFuncAttributeMaxDynamicSharedMemorySize, SM1);
    cudaFuncSetAttribute(conv_hmma_kernel<1,3>, cudaFuncAttributeMaxDynamicSharedMemorySize, SM1);

    const int G0 = NCOL * 9;
    const int G1 = 8 * 17 * 33;

    // launch 1-3
    prep_weights<<<dim3(6, layers), 256>>>(den_w2, den_w3, den_w4,
                                           deb_w2, deb_w3, deb_w4, pWp);
    blockify_input_kernel<<<EG, EW>>>(inputs, pZ);
    gemm_kernel<<<gN512M272, 256>>>(A, pZ, pY, MROW, NCOL, BBSZ, BBSZ, 0, 0,
                                    nullptr, nullptr, nullptr, 0);
    // launch 4: throwaway conv for ncu visibility (profiled slot); output
    // overwritten before use, input deterministic garbage (unused result)
    conv_hmma_kernel<0,0><<<G0, 256, SM0>>>(pT1, pWp, den_b3, pT2);
    // rest of init
    gemm_kernel<<<gN512M1089, 256>>>(Q, pY, pX, BBSZ, NCOL, MROW, MROW, 0, 0,
                                     nullptr, nullptr, nullptr, 0);
    gemm_kernel<<<gAtA, 256>>>(A, A, pAtA, BBSZ, BBSZ, MROW, BBSZ, 1, 0,
                               nullptr, nullptr, nullptr, 0);

    for (int n = 0; n < layers; n++) {
        const uint32_t* wp = pWp + (size_t)(n * 6) * 9216;
        gemm_kernel<<<gN512M272, 256>>>(A, pX, pR, MROW, NCOL, BBSZ, BBSZ, 0, 1,
                                        pY, nullptr, nullptr, 0);
        gemm_kernel<<<gN512M1089, 256>>>(A, pR, pZ, BBSZ, NCOL, MROW, BBSZ, 1, 2,
                                         pX, nullptr, steps, n);
        conv12_hmma<0><<<G0, 256, SM12_0>>>(pX, den_w1 + (size_t)n * 32 * 9,
                                            den_b1 + n * 32, wp + 0 * 9216,
                                            den_b2 + n * 32, pT1);
        conv_hmma_kernel<0,0><<<G0, 256, SM0>>>(pT1, wp + 1 * 9216, den_b3 + n * 32, pT2);
        conv_hmma_kernel<0,1><<<G0, 256, SM0>>>(pT2, wp + 2 * 9216, nullptr, pN);
        gemm_kernel<<<gN512M1089, 256>>>(pAtA, pN, pX, BBSZ, NCOL, BBSZ, BBSZ, 0, 3,
                                         pZ, pN, steps, n);
        conv12_hmma<1><<<G1, 256, SM12_1>>>(pX, deb_w1 + (size_t)n * 32 * 9,
                                            deb_b1 + n * 32, wp + 3 * 9216,
                                            deb_b2 + n * 32, pT1);
        conv_hmma_kernel<1,0><<<G1, 256, SM1>>>(pT1, wp + 4 * 9216, deb_b3 + n * 32, pT2);
        conv_hmma_kernel<1,3><<<G1, 256, SM1>>>(pT2, wp + 5 * 9216, nullptr, pX);
    }

    unblockify_kernel<<<EG, EW>>>(pX, (float*)d_out);
}

// round 9
// speedup vs baseline: 2.7363x; 1.2685x over previous
#include <cuda_runtime.h>
#include <cuda_fp16.h>
#include <cstdint>

#define BQ   33
#define BBSZ 1089
#define NS   8
#define NH   8
#define NL   8
#define NCOL 512
#define MROW 272
#define HP   264
#define IMGPIX (NS*HP*HP)
#define PLN  8921088   // 512*16*1089 == 8*16*264*264 (packed half2 planes)

// ---------------- scratch ----------------------------------------------------
__device__ float g_X[BBSZ * NCOL];
__device__ float g_y[MROW * NCOL];
__device__ float g_r[MROW * NCOL];
__device__ float g_z[BBSZ * NCOL];
__device__ float g_noise[BBSZ * NCOL];
__device__ float g_AtA[BBSZ * BBSZ];
__device__ uint32_t g_t1[PLN];
__device__ uint32_t g_t2[PLN];
__device__ uint32_t g_wpack[8 * 6 * 2 * 4608];  // [layer][set][hi|lo][144*32]

// ---------------- HMMA helpers ------------------------------------------------
#define HMMA16816(c, a0, a1, a2, a3, b0, b1) \
    asm volatile("mma.sync.aligned.m16n8k16.row.col.f32.f16.f16.f32 " \
        "{%0,%1,%2,%3}, {%4,%5,%6,%7}, {%8,%9}, {%0,%1,%2,%3};" \
        : "+f"((c)[0]), "+f"((c)[1]), "+f"((c)[2]), "+f"((c)[3]) \
        : "r"(a0), "r"(a1), "r"(a2), "r"(a3), "r"(b0), "r"(b1))

__device__ __forceinline__ uint32_t h2bits(__half2 h) {
    return *reinterpret_cast<uint32_t*>(&h);
}
__device__ __forceinline__ uint32_t pack2(float x, float y) {
    __half2 h = __floats2half2_rn(x, y);
    return h2bits(h);
}
__device__ __forceinline__ uint32_t pack_split(float x, float y, uint32_t& lo) {
    __half2 h = __floats2half2_rn(x, y);
    __half2 l = __floats2half2_rn(x - __low2float(h), y - __high2float(h));
    lo = h2bits(l);
    return h2bits(h);
}

// ---------------- weight pre-pack (once per run) -------------------------------
__global__ void prep_weights(const float* __restrict__ dw2, const float* __restrict__ dw3,
                             const float* __restrict__ dw4, const float* __restrict__ bw2,
                             const float* __restrict__ bw3, const float* __restrict__ bw4,
                             uint32_t* __restrict__ outp) {
    int set = blockIdx.x, n = blockIdx.y;
    const float* wt; int coutr;
    switch (set) {
        case 0: wt = dw2 + (size_t)n * 32 * 32 * 9; coutr = 32; break;
        case 1: wt = dw3 + (size_t)n * 32 * 32 * 9; coutr = 32; break;
        case 2: wt = dw4 + (size_t)n * 32 * 9;      coutr = 1;  break;
        case 3: wt = bw2 + (size_t)n * 32 * 32 * 9; coutr = 32; break;
        case 4: wt = bw3 + (size_t)n * 32 * 32 * 9; coutr = 32; break;
        default: wt = bw4 + (size_t)n * 32 * 9;     coutr = 1;  break;
    }
    uint32_t* o = outp + ((size_t)n * 6 + set) * 9216;
    for (int e = threadIdx.x; e < 144 * 32; e += 256) {
        int kp = e >> 5, oc = e & 31;
        int k0 = 2 * kp;
        int tap = k0 >> 5, ic = k0 & 31;
        float w0 = 0.f, w1 = 0.f;
        if (oc < coutr) {
            w0 = wt[(oc * 32 + ic) * 9 + tap];
            w1 = wt[(oc * 32 + ic + 1) * 9 + tap];
        }
        uint32_t lo;
        uint32_t hi = pack_split(w0, w1, lo);
        o[e] = hi;
        o[4608 + e] = lo;
    }
}

// X col-major index of image pixel (s, gy, gx)
__device__ __forceinline__ int ximg_idx(int s, int gy, int gx) {
    int h = gy / 33, i = gy % 33, l = gx / 33, j = gx % 33;
    return (i * 33 + j) * NCOL + l * (NH * NS) + h * NS + s;
}

#define WSTR   40
#define WBYTES (2 * 144 * WSTR * 4)    // 46080

// ============ fused conv1(1->32,relu)+conv2(32->32,relu) via HMMA ==============
// Output: packed half2 channel-pair planes [n_img*16+pair][pixel]
template<int MODE>
__global__ void __launch_bounds__(256)
conv12_hmma(const float* __restrict__ xin,
            const float* __restrict__ w1g,
            const float* __restrict__ b1g,
            const uint32_t* __restrict__ wpack,
            const float* __restrict__ bias2,
            uint32_t* __restrict__ out) {
    extern __shared__ char smem[];
    constexpr int PSTR = (MODE == 0) ? 248 : 184;
    constexpr int WROW = (MODE == 0) ? 35 : 10;
    constexpr int NPOS = (MODE == 0) ? 245 : 180;
    constexpr int RW   = (MODE == 0) ? 37 : 12;
    constexpr int RAWN = (MODE == 0) ? 9 * 37 : 20 * 12;
    uint32_t* wh = (uint32_t*)smem;
    uint32_t* wl = wh + 144 * WSTR;
    uint32_t* hhi = (uint32_t*)(smem + WBYTES);     // [16][PSTR]
    float* raw = (float*)(smem + WBYTES + 16 * PSTR * 4);
    float* w1s = raw + ((RAWN + 3) & ~3);

    const int tid = threadIdx.x;
    const int wid = tid >> 5;
    const int lane = tid & 31;
    const int rg = lane >> 2;
    const int l3 = lane & 3;
    const int kq = l3 * 2;

    int n_img, p0 = 0, y_first = 0, y0t = 0, x0t = 0;
    if (MODE == 0) {
        n_img = blockIdx.x / 9;
        p0 = (blockIdx.x % 9) * 128;
        y_first = p0 / 33;
    } else {
        int b = blockIdx.x;
        int tx = b % 33; b /= 33;
        int ty = b % 17; b /= 17;
        n_img = b; y0t = ty * 16; x0t = tx * 8;
    }

    for (int e = tid; e < 144 * 32; e += 256) {
        int kp = e >> 5, oc = e & 31;
        wh[kp * WSTR + oc] = wpack[e];
        wl[kp * WSTR + oc] = wpack[4608 + e];
    }
    for (int e = tid; e < 320; e += 256)
        w1s[e] = (e < 288) ? w1g[e] : b1g[e - 288];
    if (MODE == 0) {
        for (int e = tid; e < RAWN; e += 256) {
            int ry = e / RW, rx = e % RW;
            int gy = y_first - 2 + ry, gx = rx - 2;
            bool ok = (gy >= 0) && (gy < 33) && (gx >= 0) && (gx < 33);
            raw[e] = ok ? xin[(gy * 33 + gx) * NCOL + n_img] : 0.f;
        }
    } else {
        for (int e = tid; e < RAWN; e += 256) {
            int ry = e / RW, rx = e % RW;
            int gy = y0t - 2 + ry, gx = x0t - 2 + rx;
            bool ok = (gy >= 0) && (gy < HP) && (gx >= 0) && (gx < HP);
            raw[e] = ok ? xin[ximg_idx(n_img, gy, gx)] : 0.f;
        }
    }
    __syncthreads();

    if (tid < NPOS) {
        int hy = tid / WROW, hx = tid % WROW;
        int gy, gx, GHW;
        if (MODE == 0) { gy = y_first - 1 + hy; gx = hx - 1; GHW = 33; }
        else           { gy = y0t - 1 + hy;     gx = x0t - 1 + hx; GHW = HP; }
        bool valid = (gy >= 0) && (gy < GHW) && (gx >= 0) && (gx < ((MODE == 0) ? 33 : HP));
        float c1[32];
        if (valid) {
            float t0 = raw[hy * RW + hx],     t1 = raw[hy * RW + hx + 1],     t2 = raw[hy * RW + hx + 2];
            float t3 = raw[(hy+1) * RW + hx], t4 = raw[(hy+1) * RW + hx + 1], t5 = raw[(hy+1) * RW + hx + 2];
            float t6 = raw[(hy+2) * RW + hx], t7 = raw[(hy+2) * RW + hx + 1], t8 = raw[(hy+2) * RW + hx + 2];
#pragma unroll
            for (int oc = 0; oc < 32; oc++) {
                const float* w = w1s + oc * 9;
                float s = w1s[288 + oc];
                s += t0*w[0] + t1*w[1] + t2*w[2]
                   + t3*w[3] + t4*w[4] + t5*w[5]
                   + t6*w[6] + t7*w[7] + t8*w[8];
                c1[oc] = fmaxf(s, 0.f);
            }
        } else {
#pragma unroll
            for (int oc = 0; oc < 32; oc++) c1[oc] = 0.f;
        }
#pragma unroll
        for (int p = 0; p < 16; p++)
            hhi[p * PSTR + tid] = pack2(c1[2*p], c1[2*p+1]);
    }
    __syncthreads();

    int m_lo = wid * 16 + rg;
    int m_hi = m_lo + 8;
    int base_lo, base_hi;
    if (MODE == 0) {
        int pl = p0 + m_lo, ph = p0 + m_hi;
        int yl = pl / 33, yh = ph / 33;
        base_lo = (pl < BBSZ) ? (yl - y_first) * 35 + (pl - yl * 33) : 0;
        base_hi = (ph < BBSZ) ? (yh - y_first) * 35 + (ph - yh * 33) : 0;
    } else {
        base_lo = (m_lo >> 3) * 10 + (m_lo & 7);
        base_hi = (m_hi >> 3) * 10 + (m_hi & 7);
    }
    const uint32_t* phi_lo = hhi + l3 * PSTR + base_lo;
    const uint32_t* phi_hi = hhi + l3 * PSTR + base_hi;

    float acc[4][4];
#pragma unroll
    for (int nt = 0; nt < 4; nt++)
#pragma unroll
        for (int i = 0; i < 4; i++) acc[nt][i] = 0.f;

#pragma unroll
    for (int t = 0; t < 9; t++) {
        const int toff = (t / 3) * WROW + (t % 3);
#pragma unroll
        for (int e2 = 0; e2 < 2; e2++) {
            const int c = 2 * t + e2;
            const int pb = e2 * 8 * PSTR + toff;
            uint32_t a0h = phi_lo[pb];
            uint32_t a1h = phi_hi[pb];
            uint32_t a2h = phi_lo[pb + 4 * PSTR];
            uint32_t a3h = phi_hi[pb + 4 * PSTR];
            const int kb = (c * 8 + l3) * WSTR + rg;
#pragma unroll
            for (int nt = 0; nt < 4; nt++) {
                uint32_t bh0 = wh[kb + nt * 8];
                uint32_t bh1 = wh[kb + 4 * WSTR + nt * 8];
                uint32_t bl0 = wl[kb + nt * 8];
                uint32_t bl1 = wl[kb + 4 * WSTR + nt * 8];
                HMMA16816(acc[nt], a0h, a1h, a2h, a3h, bh0, bh1);
                HMMA16816(acc[nt], a0h, a1h, a2h, a3h, bl0, bl1);
            }
        }
    }

    // epilogue: packed half2 planes, straight from registers
#pragma unroll
    for (int nt = 0; nt < 4; nt++) {
        int oc = nt * 8 + kq;
        int p2 = nt * 4 + l3;
        float b0 = bias2[oc], b1 = bias2[oc + 1];
        uint32_t h0 = pack2(fmaxf(acc[nt][0] + b0, 0.f), fmaxf(acc[nt][1] + b1, 0.f));
        uint32_t h1 = pack2(fmaxf(acc[nt][2] + b0, 0.f), fmaxf(acc[nt][3] + b1, 0.f));
        if (MODE == 0) {
            int pl = p0 + m_lo, ph = p0 + m_hi;
            if (pl < BBSZ) out[(size_t)(n_img * 16 + p2) * BBSZ + pl] = h0;
            if (ph < BBSZ) out[(size_t)(n_img * 16 + p2) * BBSZ + ph] = h1;
        } else {
            int oyl = y0t + (m_lo >> 3), oxl = x0t + (m_lo & 7);
            int oyh = y0t + (m_hi >> 3), oxh = x0t + (m_hi & 7);
            if (oyl < HP) out[((size_t)(n_img * 16 + p2) * HP + oyl) * HP + oxl] = h0;
            if (oyh < HP) out[((size_t)(n_img * 16 + p2) * HP + oyh) * HP + oxh] = h1;
        }
    }
}

// ---------------- HMMA conv on packed planes ----------------------------------
// OUTM 0: packed half2 planes + bias + relu
// OUTM 1: 1ch col-major float (noise)
// OUTM 3: (MODE 1) X[r,n] -= result
template<int MODE, int OUTM>
__global__ void __launch_bounds__(256)
conv_hmma_kernel(const uint32_t* __restrict__ in,
                 const uint32_t* __restrict__ wpack,
                 const float* __restrict__ bias,
                 void* __restrict__ outv) {
    extern __shared__ char smem[];
    uint32_t* wh = (uint32_t*)smem;
    uint32_t* wl = wh + 144 * WSTR;
    constexpr int PSTR = (MODE == 0) ? 248 : 184;
    constexpr int WROW = (MODE == 0) ? 35 : 10;
    constexpr int NPOS = (MODE == 0) ? 245 : 180;
    uint32_t* hhi = (uint32_t*)(smem + WBYTES);
    constexpr int NT = (OUTM == 0) ? 4 : 1;

    const int tid = threadIdx.x;
    const int wid = tid >> 5;
    const int lane = tid & 31;
    const int rg = lane >> 2;
    const int l3 = lane & 3;
    const int kq = l3 * 2;

    int n_img, p0 = 0, y_first = 0, y0t = 0, x0t = 0;
    if (MODE == 0) {
        n_img = blockIdx.x / 9;
        p0 = (blockIdx.x % 9) * 128;
        y_first = p0 / 33;
    } else {
        int b = blockIdx.x;
        int tx = b % 33; b /= 33;
        int ty = b % 17; b /= 17;
        n_img = b; y0t = ty * 16; x0t = tx * 8;
    }

    for (int e = tid; e < 144 * 32; e += 256) {
        int kp = e >> 5, oc = e & 31;
        wh[kp * WSTR + oc] = wpack[e];
        wl[kp * WSTR + oc] = wpack[4608 + e];
    }

    // halo: raw uint32 copies of packed planes
    if (MODE == 0) {
        for (int e = tid; e < 16 * NPOS; e += 256) {
            int pair = e / NPOS, pos = e % NPOS;
            int row = pos / 35, xp = pos % 35;
            int gy = y_first - 1 + row, gx = xp - 1;
            bool ok = (gy >= 0) && (gy < 33) && (xp >= 1) && (xp < 34);
            uint32_t v = ok ? in[(size_t)(n_img * 16 + pair) * BBSZ + gy * 33 + gx] : 0u;
            hhi[pair * PSTR + pos] = v;
        }
    } else {
        for (int e = tid; e < 16 * NPOS; e += 256) {
            int pair = e / NPOS, pos = e % NPOS;
            int row = pos / 10, xp = pos % 10;
            int gy = y0t - 1 + row, gx = x0t - 1 + xp;
            bool ok = (gy >= 0) && (gy < HP) && (gx >= 0) && (gx < HP);
            uint32_t v = ok ? in[((size_t)(n_img * 16 + pair) * HP + gy) * HP + gx] : 0u;
            hhi[pair * PSTR + pos] = v;
        }
    }
    __syncthreads();

    int m_lo = wid * 16 + rg;
    int m_hi = m_lo + 8;
    int base_lo, base_hi;
    if (MODE == 0) {
        int pl = p0 + m_lo, ph = p0 + m_hi;
        int yl = pl / 33, yh = ph / 33;
        base_lo = (pl < BBSZ) ? (yl - y_first) * 35 + (pl - yl * 33) : 0;
        base_hi = (ph < BBSZ) ? (yh - y_first) * 35 + (ph - yh * 33) : 0;
    } else {
        base_lo = (m_lo >> 3) * 10 + (m_lo & 7);
        base_hi = (m_hi >> 3) * 10 + (m_hi & 7);
    }
    const uint32_t* phi_lo = hhi + l3 * PSTR + base_lo;
    const uint32_t* phi_hi = hhi + l3 * PSTR + base_hi;

    float acc[NT][4];
#pragma unroll
    for (int nt = 0; nt < NT; nt++)
#pragma unroll
        for (int i = 0; i < 4; i++) acc[nt][i] = 0.f;

#pragma unroll
    for (int t = 0; t < 9; t++) {
        const int toff = (t / 3) * WROW + (t % 3);
#pragma unroll
        for (int e2 = 0; e2 < 2; e2++) {
            const int c = 2 * t + e2;
            const int pb = e2 * 8 * PSTR + toff;
            uint32_t a0h = phi_lo[pb];
            uint32_t a1h = phi_hi[pb];
            uint32_t a2h = phi_lo[pb + 4 * PSTR];
            uint32_t a3h = phi_hi[pb + 4 * PSTR];
            const int kb = (c * 8 + l3) * WSTR + rg;
#pragma unroll
            for (int nt = 0; nt < NT; nt++) {
                uint32_t bh0 = wh[kb + nt * 8];
                uint32_t bh1 = wh[kb + 4 * WSTR + nt * 8];
                uint32_t bl0 = wl[kb + nt * 8];
                uint32_t bl1 = wl[kb + 4 * WSTR + nt * 8];
                HMMA16816(acc[nt], a0h, a1h, a2h, a3h, bh0, bh1);
                HMMA16816(acc[nt], a0h, a1h, a2h, a3h, bl0, bl1);
            }
        }
    }

    if (OUTM == 0) {
        uint32_t* out = (uint32_t*)outv;
#pragma unroll
        for (int nt = 0; nt < 4; nt++) {
            int oc = nt * 8 + kq;
            int p2 = nt * 4 + l3;
            float b0 = bias[oc], b1 = bias[oc + 1];
            uint32_t h0 = pack2(fmaxf(acc[nt][0] + b0, 0.f), fmaxf(acc[nt][1] + b1, 0.f));
            uint32_t h1 = pack2(fmaxf(acc[nt][2] + b0, 0.f), fmaxf(acc[nt][3] + b1, 0.f));
            if (MODE == 0) {
                int pl = p0 + m_lo, ph = p0 + m_hi;
                if (pl < BBSZ) out[(size_t)(n_img * 16 + p2) * BBSZ + pl] = h0;
                if (ph < BBSZ) out[(size_t)(n_img * 16 + p2) * BBSZ + ph] = h1;
            } else {
                int oyl = y0t + (m_lo >> 3), oxl = x0t + (m_lo & 7);
                int oyh = y0t + (m_hi >> 3), oxh = x0t + (m_hi & 7);
                if (oyl < HP) out[((size_t)(n_img * 16 + p2) * HP + oyl) * HP + oxl] = h0;
                if (oyh < HP) out[((size_t)(n_img * 16 + p2) * HP + oyh) * HP + oxh] = h1;
            }
        }
    } else if (OUTM == 1) {
        float* out = (float*)outv;
        if (l3 == 0) {
            int pl = p0 + m_lo, ph = p0 + m_hi;
            if (pl < BBSZ) out[(size_t)pl * NCOL + n_img] = acc[0][0];
            if (ph < BBSZ) out[(size_t)ph * NCOL + n_img] = acc[0][2];
        }
    } else {
        float* out = (float*)outv;
        if (l3 == 0) {
            int gyl = y0t + (m_lo >> 3), gxl = x0t + (m_lo & 7);
            int gyh = y0t + (m_hi >> 3), gxh = x0t + (m_hi & 7);
            if (gyl < HP) { int ix = ximg_idx(n_img, gyl, gxl); out[ix] -= acc[0][0]; }
            if (gyh < HP) { int ix = ximg_idx(n_img, gyh, gxh); out[ix] -= acc[0][2]; }
        }
    }
}

// ---------------- blockify / unblockify ---------------------------------------
__global__ void blockify_input_kernel(const float* __restrict__ in, float* __restrict__ Xb) {
    int idx = blockIdx.x * blockDim.x + threadIdx.x;
    if (idx >= BBSZ * NCOL) return;
    int r = idx / NCOL, n = idx % NCOL;
    int i = r / BQ, j = r % BQ;
    int l = n / (NH * NS), h = (n / NS) % NH, s = n % NS;
    Xb[idx] = in[(s * HP + h * BQ + i) * HP + l * BQ + j];
}
__global__ void unblockify_kernel(const float* __restrict__ X, float* __restrict__ img) {
    int idx = blockIdx.x * blockDim.x + threadIdx.x;
    if (idx >= IMGPIX) return;
    int s = idx / (HP * HP);
    int rem = idx % (HP * HP);
    int R = rem / HP, C = rem % HP;
    int h = R / BQ, i = R % BQ, l = C / BQ, j = C % BQ;
    img[idx] = X[(i * BQ + j) * NCOL + (l * (NH * NS) + h * NS + s)];
}

// ---------------- SIMT GEMM with fused epilogues -------------------------------
#define GBM 64
#define GBN 64
#define GBK 16
__global__ void gemm_kernel(const float* __restrict__ A, const float* __restrict__ B,
                            float* __restrict__ C,
                            int M, int N, int K, int lda, int transA,
                            int epi, const float* __restrict__ E1,
                            const float* __restrict__ E2,
                            const float* __restrict__ stepsPtr, int stepIdx) {
    __shared__ float As[GBK][GBM];
    __shared__ float Bs[GBK][GBN + 1];
    int bm = blockIdx.y * GBM, bn = blockIdx.x * GBN;
    int tid = threadIdx.x;
    int tx = tid % 16, ty = tid / 16;
    float acc[4][4];
#pragma unroll
    for (int i = 0; i < 4; i++)
#pragma unroll
        for (int j = 0; j < 4; j++) acc[i][j] = 0.f;
    for (int k0 = 0; k0 < K; k0 += GBK) {
        if (transA) {
            for (int e = tid; e < GBM * GBK; e += 256) {
                int k = e / GBM, mm = e % GBM;
                int gm = bm + mm, gk = k0 + k;
                As[k][mm] = (gm < M && gk < K) ? A[(size_t)gk * lda + gm] : 0.f;
            }
        } else {
            for (int e = tid; e < GBM * GBK; e += 256) {
                int mm = e / GBK, k = e % GBK;
                int gm = bm + mm, gk = k0 + k;
                As[k][mm] = (gm < M && gk < K) ? A[(size_t)gm * lda + gk] : 0.f;
            }
        }
        for (int e = tid; e < GBK * GBN; e += 256) {
            int k = e / GBN, nn = e % GBN;
            int gk = k0 + k, gn = bn + nn;
            Bs[k][nn] = (gk < K && gn < N) ? B[(size_t)gk * N + gn] : 0.f;
        }
        __syncthreads();
#pragma unroll
        for (int k = 0; k < GBK; k++) {
            float a[4], b[4];
#pragma unroll
            for (int i = 0; i < 4; i++) a[i] = As[k][ty * 4 + i];
#pragma unroll
            for (int j = 0; j < 4; j++) b[j] = Bs[k][tx * 4 + j];
#pragma unroll
            for (int i = 0; i < 4; i++)
#pragma unroll
                for (int j = 0; j < 4; j++) acc[i][j] += a[i] * b[j];
        }
        __syncthreads();
    }
    float step = (stepsPtr != nullptr) ? stepsPtr[stepIdx] : 0.f;
#pragma unroll
    for (int i = 0; i < 4; i++) {
        int gm = bm + ty * 4 + i;
        if (gm >= M) continue;
#pragma unroll
        for (int j = 0; j < 4; j++) {
            int gn = bn + tx * 4 + j;
            if (gn >= N) continue;
            size_t idx = (size_t)gm * N + gn;
            float v = acc[i][j], o;
            if (epi == 0)      o = v;
            else if (epi == 1) o = E1[idx] - v;
            else if (epi == 2) o = step * v + E1[idx];
            else               o = E1[idx] - step * v + E2[idx];
            C[idx] = o;
        }
    }
}

// ---------------- host driver --------------------------------------------------
extern "C" void kernel_launch(void* const* d_in, const int* in_sizes, int n_in,
                              void* d_out, int out_size) {
    const float* inputs = (const float*)d_in[0];
    const float* A      = (const float*)d_in[1];
    const float* Q      = (const float*)d_in[2];
    const float* steps  = (const float*)d_in[3];
    const float* den_w1 = (const float*)d_in[4];
    const float* den_b1 = (const float*)d_in[5];
    const float* den_w2 = (const float*)d_in[6];
    const float* den_b2 = (const float*)d_in[7];
    const float* den_w3 = (const float*)d_in[8];
    const float* den_b3 = (const float*)d_in[9];
    const float* den_w4 = (const float*)d_in[10];
    const float* deb_w1 = (const float*)d_in[11];
    const float* deb_b1 = (const float*)d_in[12];
    const float* deb_w2 = (const float*)d_in[13];
    const float* deb_b2 = (const float*)d_in[14];
    const float* deb_w3 = (const float*)d_in[15];
    const float* deb_b3 = (const float*)d_in[16];
    const float* deb_w4 = (const float*)d_in[17];
    int layers = in_sizes[3];

    float *pX, *pY, *pR, *pZ, *pN, *pAtA;
    uint32_t *pT1, *pT2, *pWp;
    cudaGetSymbolAddress((void**)&pX, g_X);
    cudaGetSymbolAddress((void**)&pY, g_y);
    cudaGetSymbolAddress((void**)&pR, g_r);
    cudaGetSymbolAddress((void**)&pZ, g_z);
    cudaGetSymbolAddress((void**)&pN, g_noise);
    cudaGetSymbolAddress((void**)&pAtA, g_AtA);
    cudaGetSymbolAddress((void**)&pT1, g_t1);
    cudaGetSymbolAddress((void**)&pT2, g_t2);
    cudaGetSymbolAddress((void**)&pWp, g_wpack);

    const int EW = 256;
    const int EG = (IMGPIX + EW - 1) / EW;
    dim3 gN512M272((NCOL + GBN - 1) / GBN, (MROW + GBM - 1) / GBM);
    dim3 gN512M1089((NCOL + GBN - 1) / GBN, (BBSZ + GBM - 1) / GBM);
    dim3 gAtA((BBSZ + GBN - 1) / GBN, (BBSZ + GBM - 1) / GBM);

    const int SM0 = WBYTES + 16 * 248 * 4;                        // 61952
    const int SM1 = WBYTES + 16 * 184 * 4;                        // 57856
    const int SM12_0 = SM0 + ((9 * 37 + 3) & ~3) * 4 + 320 * 4;   // 64576
    const int SM12_1 = SM1 + ((20 * 12 + 3) & ~3) * 4 + 320 * 4;  // 60096
    cudaFuncSetAttribute(conv12_hmma<0>, cudaFuncAttributeMaxDynamicSharedMemorySize, SM12_0);
    cudaFuncSetAttribute(conv12_hmma<1>, cudaFuncAttributeMaxDynamicSharedMemorySize, SM12_1);
    cudaFuncSetAttribute(conv_hmma_kernel<0,0>, cudaFuncAttributeMaxDynamicSharedMemorySize, SM0);
    cudaFuncSetAttribute(conv_hmma_kernel<0,1>, cudaFuncAttributeMaxDynamicSharedMemorySize, SM0);
    cudaFuncSetAttribute(conv_hmma_kernel<1,0>, cudaFuncAttributeMaxDynamicSharedMemorySize, SM1);
    cudaFuncSetAttribute(conv_hmma_kernel<1,3>, cudaFuncAttributeMaxDynamicSharedMemorySize, SM1);

    const int G0 = NCOL * 9;
    const int G1 = 8 * 17 * 33;

    prep_weights<<<dim3(6, layers), 256>>>(den_w2, den_w3, den_w4,
                                           deb_w2, deb_w3, deb_w4, pWp);
    blockify_input_kernel<<<EG, EW>>>(inputs, pZ);
    gemm_kernel<<<gN512M272, 256>>>(A, pZ, pY, MROW, NCOL, BBSZ, BBSZ, 0, 0,
                                    nullptr, nullptr, nullptr, 0);
    gemm_kernel<<<gN512M1089, 256>>>(Q, pY, pX, BBSZ, NCOL, MROW, MROW, 0, 0,
                                     nullptr, nullptr, nullptr, 0);
    gemm_kernel<<<gAtA, 256>>>(A, A, pAtA, BBSZ, BBSZ, MROW, BBSZ, 1, 0,
                               nullptr, nullptr, nullptr, 0);

    for (int n = 0; n < layers; n++) {
        const uint32_t* wp = pWp + (size_t)(n * 6) * 9216;
        gemm_kernel<<<gN512M272, 256>>>(A, pX, pR, MROW, NCOL, BBSZ, BBSZ, 0, 1,
                                        pY, nullptr, nullptr, 0);
        gemm_kernel<<<gN512M1089, 256>>>(A, pR, pZ, BBSZ, NCOL, MROW, BBSZ, 1, 2,
                                         pX, nullptr, steps, n);
        conv12_hmma<0><<<G0, 256, SM12_0>>>(pX, den_w1 + (size_t)n * 32 * 9,
                                            den_b1 + n * 32, wp + 0 * 9216,
                                            den_b2 + n * 32, pT1);
        conv_hmma_kernel<0,0><<<G0, 256, SM0>>>(pT1, wp + 1 * 9216, den_b3 + n * 32, pT2);
        conv_hmma_kernel<0,1><<<G0, 256, SM0>>>(pT2, wp + 2 * 9216, nullptr, pN);
        gemm_kernel<<<gN512M1089, 256>>>(pAtA, pN, pX, BBSZ, NCOL, BBSZ, BBSZ, 0, 3,
                                         pZ, pN, steps, n);
        conv12_hmma<1><<<G1, 256, SM12_1>>>(pX, deb_w1 + (size_t)n * 32 * 9,
                                            deb_b1 + n * 32, wp + 3 * 9216,
                                            deb_b2 + n * 32, pT1);
        conv_hmma_kernel<1,0><<<G1, 256, SM1>>>(pT1, wp + 4 * 9216, deb_b3 + n * 32, pT2);
        conv_hmma_kernel<1,3><<<G1, 256, SM1>>>(pT2, wp + 5 * 9216, nullptr, pX);
    }

    unblockify_kernel<<<EG, EW>>>(pX, (float*)d_out);
}

// round 10
// speedup vs baseline: 3.9321x; 1.4370x over previous
#include <cuda_runtime.h>
#include <cuda_fp16.h>
#include <cstdint>

#define BQ   33
#define BBSZ 1089
#define NS   8
#define NH   8
#define NL   8
#define NCOL 512
#define MROW 272
#define HP   264
#define IMGPIX (NS*HP*HP)
#define PLN  8921088   // packed half2 planes

// ---------------- scratch ----------------------------------------------------
__device__ float g_X[BBSZ * NCOL];
__device__ float g_y[MROW * NCOL];
__device__ float g_r[MROW * NCOL];
__device__ float g_z[BBSZ * NCOL];
__device__ float g_noise[BBSZ * NCOL];
__device__ float g_AtA[BBSZ * BBSZ];
__device__ uint32_t g_t1[PLN];
__device__ uint32_t g_t2[PLN];
__device__ uint32_t g_wpack[8 * 6 * 2 * 4608];
// packed GEMM matrices (hi plane, then lo plane)
__device__ uint32_t g_mA[2 * 545 * 272];     // A   [272 x1089] -> Kp=545, Mp=272
__device__ uint32_t g_mAT[2 * 136 * 1092];   // A^T [1089x272]  -> Kp=136, Mp=1092
__device__ uint32_t g_mQ[2 * 136 * 1092];    // Q   [1089x272]
__device__ uint32_t g_mAtA[2 * 545 * 1092];  // AtA [1089x1089] -> Kp=545, Mp=1092

// ---------------- HMMA helpers ------------------------------------------------
#define HMMA16816(c, a0, a1, a2, a3, b0, b1) \
    asm volatile("mma.sync.aligned.m16n8k16.row.col.f32.f16.f16.f32 " \
        "{%0,%1,%2,%3}, {%4,%5,%6,%7}, {%8,%9}, {%0,%1,%2,%3};" \
        : "+f"((c)[0]), "+f"((c)[1]), "+f"((c)[2]), "+f"((c)[3]) \
        : "r"(a0), "r"(a1), "r"(a2), "r"(a3), "r"(b0), "r"(b1))

__device__ __forceinline__ uint32_t h2bits(__half2 h) {
    return *reinterpret_cast<uint32_t*>(&h);
}
__device__ __forceinline__ uint32_t pack2(float x, float y) {
    __half2 h = __floats2half2_rn(x, y);
    return h2bits(h);
}
__device__ __forceinline__ uint32_t pack_split(float x, float y, uint32_t& lo) {
    __half2 h = __floats2half2_rn(x, y);
    __half2 l = __floats2half2_rn(x - __low2float(h), y - __high2float(h));
    lo = h2bits(l);
    return h2bits(h);
}

// ---------------- matrix pre-pack: W[m][k] -> hi/lo planes [kp][m] ------------
__global__ void prep_mat(const float* __restrict__ src, int lds, int trans,
                         int M, int K, int Mp, uint32_t* __restrict__ dst) {
    int PS = ((K + 1) >> 1) * Mp;
    for (int e = blockIdx.x * blockDim.x + threadIdx.x; e < PS;
         e += gridDim.x * blockDim.x) {
        int m = e % Mp, kp = e / Mp;
        int k0 = 2 * kp;
        float w0 = 0.f, w1 = 0.f;
        if (m < M) {
            if (k0 < K)     w0 = trans ? src[(size_t)k0 * lds + m] : src[(size_t)m * lds + k0];
            if (k0 + 1 < K) w1 = trans ? src[(size_t)(k0 + 1) * lds + m] : src[(size_t)m * lds + k0 + 1];
        }
        uint32_t lo;
        uint32_t hi = pack_split(w0, w1, lo);
        dst[e] = hi;
        dst[PS + e] = lo;
    }
}

// ---------------- HMMA GEMM: C[M,N] = epi(W @ X) -------------------------------
// W pre-packed hi/lo kp-major planes (stride Mp, plane size PS).
// BM=128 (8 warps x m16), BN=32 (4 n8 tiles). 3-product hi/lo accuracy.
// epi 0: C=acc  1: C=E1-acc  2: C=step*acc+E1  3: C=E1-step*acc+E2
template<int EPI>
__global__ void __launch_bounds__(256) hgemm(
    const uint32_t* __restrict__ Wp, int PS, int Mp,
    const float* __restrict__ X, float* __restrict__ C,
    int M, int N, int K,
    const float* __restrict__ E1, const float* __restrict__ E2,
    const float* __restrict__ stepsPtr, int stepIdx) {
    __shared__ uint2 Wsm[32 * 132];   // (hi,lo) interleaved, stride 132 (conflict-free)
    __shared__ uint2 Xsm[32 * 36];    // stride 36

    const int tid = threadIdx.x;
    const int wid = tid >> 5;
    const int lane = tid & 31;
    const int rg = lane >> 2;
    const int l3 = lane & 3;
    const int bn = blockIdx.x * 32;
    const int bm = blockIdx.y * 128;
    const int mloc = wid * 16 + rg;
    const int KpTot = (K + 1) >> 1;
    const int nCh = (KpTot + 31) >> 5;

    float acc[4][4];
#pragma unroll
    for (int nt = 0; nt < 4; nt++)
#pragma unroll
        for (int i = 0; i < 4; i++) acc[nt][i] = 0.f;

    for (int ch = 0; ch < nCh; ch++) {
        int kp0 = ch * 32;
#pragma unroll
        for (int i = 0; i < 16; i++) {
            int e = i * 256 + tid;
            int m = e & 127, kp = e >> 7;
            int kpg = kp0 + kp, gm = bm + m;
            uint32_t hi = 0, lo = 0;
            if (kpg < KpTot && gm < Mp) {
                size_t off = (size_t)kpg * Mp + gm;
                hi = Wp[off];
                lo = Wp[PS + off];
            }
            Wsm[kp * 132 + m] = make_uint2(hi, lo);
        }
#pragma unroll
        for (int i = 0; i < 4; i++) {
            int e = i * 256 + tid;
            int n = e & 31, kp = e >> 5;
            int kpg = kp0 + kp, gn = bn + n;
            float f0 = 0.f, f1 = 0.f;
            int k0 = 2 * kpg;
            if (gn < N && k0 < K) {
                f0 = X[(size_t)k0 * N + gn];
                if (k0 + 1 < K) f1 = X[(size_t)(k0 + 1) * N + gn];
            }
            uint32_t lo;
            uint32_t hi = pack_split(f0, f1, lo);
            Xsm[kp * 36 + n] = make_uint2(hi, lo);
        }
        __syncthreads();
#pragma unroll
        for (int c = 0; c < 4; c++) {
            int kl = c * 8 + l3;
            uint2 A0 = Wsm[kl * 132 + mloc];
            uint2 A1 = Wsm[kl * 132 + mloc + 8];
            uint2 A2 = Wsm[(kl + 4) * 132 + mloc];
            uint2 A3 = Wsm[(kl + 4) * 132 + mloc + 8];
#pragma unroll
            for (int nt = 0; nt < 4; nt++) {
                uint2 B0 = Xsm[kl * 36 + nt * 8 + rg];
                uint2 B1 = Xsm[(kl + 4) * 36 + nt * 8 + rg];
                HMMA16816(acc[nt], A0.x, A1.x, A2.x, A3.x, B0.x, B1.x);
                HMMA16816(acc[nt], A0.x, A1.x, A2.x, A3.x, B0.y, B1.y);
                HMMA16816(acc[nt], A0.y, A1.y, A2.y, A3.y, B0.x, B1.x);
            }
        }
        __syncthreads();
    }

    float step = (stepsPtr != nullptr) ? stepsPtr[stepIdx] : 0.f;
    int gml = bm + mloc;
#pragma unroll
    for (int nt = 0; nt < 4; nt++) {
        int gn0 = bn + nt * 8 + (l3 << 1);
#pragma unroll
        for (int half = 0; half < 2; half++) {
            int gm = gml + half * 8;
            if (gm >= M) continue;
#pragma unroll
            for (int q = 0; q < 2; q++) {
                int col = gn0 + q;
                if (col >= N) continue;
                size_t idx = (size_t)gm * N + col;
                float v = acc[nt][half * 2 + q];
                float o;
                if (EPI == 0)      o = v;
                else if (EPI == 1) o = E1[idx] - v;
                else if (EPI == 2) o = step * v + E1[idx];
                else               o = E1[idx] - step * v + E2[idx];
                C[idx] = o;
            }
        }
    }
}

// ---------------- conv weight pre-pack -----------------------------------------
__global__ void prep_weights(const float* __restrict__ dw2, const float* __restrict__ dw3,
                             const float* __restrict__ dw4, const float* __restrict__ bw2,
                             const float* __restrict__ bw3, const float* __restrict__ bw4,
                             uint32_t* __restrict__ outp) {
    int set = blockIdx.x, n = blockIdx.y;
    const float* wt; int coutr;
    switch (set) {
        case 0: wt = dw2 + (size_t)n * 32 * 32 * 9; coutr = 32; break;
        case 1: wt = dw3 + (size_t)n * 32 * 32 * 9; coutr = 32; break;
        case 2: wt = dw4 + (size_t)n * 32 * 9;      coutr = 1;  break;
        case 3: wt = bw2 + (size_t)n * 32 * 32 * 9; coutr = 32; break;
        case 4: wt = bw3 + (size_t)n * 32 * 32 * 9; coutr = 32; break;
        default: wt = bw4 + (size_t)n * 32 * 9;     coutr = 1;  break;
    }
    uint32_t* o = outp + ((size_t)n * 6 + set) * 9216;
    for (int e = threadIdx.x; e < 144 * 32; e += 256) {
        int kp = e >> 5, oc = e & 31;
        int k0 = 2 * kp;
        int tap = k0 >> 5, ic = k0 & 31;
        float w0 = 0.f, w1 = 0.f;
        if (oc < coutr) {
            w0 = wt[(oc * 32 + ic) * 9 + tap];
            w1 = wt[(oc * 32 + ic + 1) * 9 + tap];
        }
        uint32_t lo;
        uint32_t hi = pack_split(w0, w1, lo);
        o[e] = hi;
        o[4608 + e] = lo;
    }
}

__device__ __forceinline__ int ximg_idx(int s, int gy, int gx) {
    int h = gy / 33, i = gy % 33, l = gx / 33, j = gx % 33;
    return (i * 33 + j) * NCOL + l * (NH * NS) + h * NS + s;
}

#define WSTR   40
#define WBYTES (2 * 144 * WSTR * 4)

// ============ fused conv1+conv2 via HMMA (unchanged from R9) ===================
template<int MODE>
__global__ void __launch_bounds__(256)
conv12_hmma(const float* __restrict__ xin,
            const float* __restrict__ w1g,
            const float* __restrict__ b1g,
            const uint32_t* __restrict__ wpack,
            const float* __restrict__ bias2,
            uint32_t* __restrict__ out) {
    extern __shared__ char smem[];
    constexpr int PSTR = (MODE == 0) ? 248 : 184;
    constexpr int WROW = (MODE == 0) ? 35 : 10;
    constexpr int NPOS = (MODE == 0) ? 245 : 180;
    constexpr int RW   = (MODE == 0) ? 37 : 12;
    constexpr int RAWN = (MODE == 0) ? 9 * 37 : 20 * 12;
    uint32_t* wh = (uint32_t*)smem;
    uint32_t* wl = wh + 144 * WSTR;
    uint32_t* hhi = (uint32_t*)(smem + WBYTES);
    float* raw = (float*)(smem + WBYTES + 16 * PSTR * 4);
    float* w1s = raw + ((RAWN + 3) & ~3);

    const int tid = threadIdx.x;
    const int wid = tid >> 5;
    const int lane = tid & 31;
    const int rg = lane >> 2;
    const int l3 = lane & 3;
    const int kq = l3 * 2;

    int n_img, p0 = 0, y_first = 0, y0t = 0, x0t = 0;
    if (MODE == 0) {
        n_img = blockIdx.x / 9;
        p0 = (blockIdx.x % 9) * 128;
        y_first = p0 / 33;
    } else {
        int b = blockIdx.x;
        int tx = b % 33; b /= 33;
        int ty = b % 17; b /= 17;
        n_img = b; y0t = ty * 16; x0t = tx * 8;
    }

    for (int e = tid; e < 144 * 32; e += 256) {
        int kp = e >> 5, oc = e & 31;
        wh[kp * WSTR + oc] = wpack[e];
        wl[kp * WSTR + oc] = wpack[4608 + e];
    }
    for (int e = tid; e < 320; e += 256)
        w1s[e] = (e < 288) ? w1g[e] : b1g[e - 288];
    if (MODE == 0) {
        for (int e = tid; e < RAWN; e += 256) {
            int ry = e / RW, rx = e % RW;
            int gy = y_first - 2 + ry, gx = rx - 2;
            bool ok = (gy >= 0) && (gy < 33) && (gx >= 0) && (gx < 33);
            raw[e] = ok ? xin[(gy * 33 + gx) * NCOL + n_img] : 0.f;
        }
    } else {
        for (int e = tid; e < RAWN; e += 256) {
            int ry = e / RW, rx = e % RW;
            int gy = y0t - 2 + ry, gx = x0t - 2 + rx;
            bool ok = (gy >= 0) && (gy < HP) && (gx >= 0) && (gx < HP);
            raw[e] = ok ? xin[ximg_idx(n_img, gy, gx)] : 0.f;
        }
    }
    __syncthreads();

    if (tid < NPOS) {
        int hy = tid / WROW, hx = tid % WROW;
        int gy, gx, GHW;
        if (MODE == 0) { gy = y_first - 1 + hy; gx = hx - 1; GHW = 33; }
        else           { gy = y0t - 1 + hy;     gx = x0t - 1 + hx; GHW = HP; }
        bool valid = (gy >= 0) && (gy < GHW) && (gx >= 0) && (gx < ((MODE == 0) ? 33 : HP));
        float c1[32];
        if (valid) {
            float t0 = raw[hy * RW + hx],     t1 = raw[hy * RW + hx + 1],     t2 = raw[hy * RW + hx + 2];
            float t3 = raw[(hy+1) * RW + hx], t4 = raw[(hy+1) * RW + hx + 1], t5 = raw[(hy+1) * RW + hx + 2];
            float t6 = raw[(hy+2) * RW + hx], t7 = raw[(hy+2) * RW + hx + 1], t8 = raw[(hy+2) * RW + hx + 2];
#pragma unroll
            for (int oc = 0; oc < 32; oc++) {
                const float* w = w1s + oc * 9;
                float s = w1s[288 + oc];
                s += t0*w[0] + t1*w[1] + t2*w[2]
                   + t3*w[3] + t4*w[4] + t5*w[5]
                   + t6*w[6] + t7*w[7] + t8*w[8];
                c1[oc] = fmaxf(s, 0.f);
            }
        } else {
#pragma unroll
            for (int oc = 0; oc < 32; oc++) c1[oc] = 0.f;
        }
#pragma unroll
        for (int p = 0; p < 16; p++)
            hhi[p * PSTR + tid] = pack2(c1[2*p], c1[2*p+1]);
    }
    __syncthreads();

    int m_lo = wid * 16 + rg;
    int m_hi = m_lo + 8;
    int base_lo, base_hi;
    if (MODE == 0) {
        int pl = p0 + m_lo, ph = p0 + m_hi;
        int yl = pl / 33, yh = ph / 33;
        base_lo = (pl < BBSZ) ? (yl - y_first) * 35 + (pl - yl * 33) : 0;
        base_hi = (ph < BBSZ) ? (yh - y_first) * 35 + (ph - yh * 33) : 0;
    } else {
        base_lo = (m_lo >> 3) * 10 + (m_lo & 7);
        base_hi = (m_hi >> 3) * 10 + (m_hi & 7);
    }
    const uint32_t* phi_lo = hhi + l3 * PSTR + base_lo;
    const uint32_t* phi_hi = hhi + l3 * PSTR + base_hi;

    float acc[4][4];
#pragma unroll
    for (int nt = 0; nt < 4; nt++)
#pragma unroll
        for (int i = 0; i < 4; i++) acc[nt][i] = 0.f;

#pragma unroll
    for (int t = 0; t < 9; t++) {
        const int toff = (t / 3) * WROW + (t % 3);
#pragma unroll
        for (int e2 = 0; e2 < 2; e2++) {
            const int c = 2 * t + e2;
            const int pb = e2 * 8 * PSTR + toff;
            uint32_t a0h = phi_lo[pb];
            uint32_t a1h = phi_hi[pb];
            uint32_t a2h = phi_lo[pb + 4 * PSTR];
            uint32_t a3h = phi_hi[pb + 4 * PSTR];
            const int kb = (c * 8 + l3) * WSTR + rg;
#pragma unroll
            for (int nt = 0; nt < 4; nt++) {
                uint32_t bh0 = wh[kb + nt * 8];
                uint32_t bh1 = wh[kb + 4 * WSTR + nt * 8];
                uint32_t bl0 = wl[kb + nt * 8];
                uint32_t bl1 = wl[kb + 4 * WSTR + nt * 8];
                HMMA16816(acc[nt], a0h, a1h, a2h, a3h, bh0, bh1);
                HMMA16816(acc[nt], a0h, a1h, a2h, a3h, bl0, bl1);
            }
        }
    }

#pragma unroll
    for (int nt = 0; nt < 4; nt++) {
        int oc = nt * 8 + kq;
        int p2 = nt * 4 + l3;
        float b0 = bias2[oc], b1 = bias2[oc + 1];
        uint32_t h0 = pack2(fmaxf(acc[nt][0] + b0, 0.f), fmaxf(acc[nt][1] + b1, 0.f));
        uint32_t h1 = pack2(fmaxf(acc[nt][2] + b0, 0.f), fmaxf(acc[nt][3] + b1, 0.f));
        if (MODE == 0) {
            int pl = p0 + m_lo, ph = p0 + m_hi;
            if (pl < BBSZ) out[(size_t)(n_img * 16 + p2) * BBSZ + pl] = h0;
            if (ph < BBSZ) out[(size_t)(n_img * 16 + p2) * BBSZ + ph] = h1;
        } else {
            int oyl = y0t + (m_lo >> 3), oxl = x0t + (m_lo & 7);
            int oyh = y0t + (m_hi >> 3), oxh = x0t + (m_hi & 7);
            if (oyl < HP) out[((size_t)(n_img * 16 + p2) * HP + oyl) * HP + oxl] = h0;
            if (oyh < HP) out[((size_t)(n_img * 16 + p2) * HP + oyh) * HP + oxh] = h1;
        }
    }
}

// ---------------- HMMA conv on packed planes (unchanged from R9) ---------------
template<int MODE, int OUTM>
__global__ void __launch_bounds__(256)
conv_hmma_kernel(const uint32_t* __restrict__ in,
                 const uint32_t* __restrict__ wpack,
                 const float* __restrict__ bias,
                 void* __restrict__ outv) {
    extern __shared__ char smem[];
    uint32_t* wh = (uint32_t*)smem;
    uint32_t* wl = wh + 144 * WSTR;
    constexpr int PSTR = (MODE == 0) ? 248 : 184;
    constexpr int WROW = (MODE == 0) ? 35 : 10;
    constexpr int NPOS = (MODE == 0) ? 245 : 180;
    uint32_t* hhi = (uint32_t*)(smem + WBYTES);
    constexpr int NT = (OUTM == 0) ? 4 : 1;

    const int tid = threadIdx.x;
    const int wid = tid >> 5;
    const int lane = tid & 31;
    const int rg = lane >> 2;
    const int l3 = lane & 3;
    const int kq = l3 * 2;

    int n_img, p0 = 0, y_first = 0, y0t = 0, x0t = 0;
    if (MODE == 0) {
        n_img = blockIdx.x / 9;
        p0 = (blockIdx.x % 9) * 128;
        y_first = p0 / 33;
    } else {
        int b = blockIdx.x;
        int tx = b % 33; b /= 33;
        int ty = b % 17; b /= 17;
        n_img = b; y0t = ty * 16; x0t = tx * 8;
    }

    for (int e = tid; e < 144 * 32; e += 256) {
        int kp = e >> 5, oc = e & 31;
        wh[kp * WSTR + oc] = wpack[e];
        wl[kp * WSTR + oc] = wpack[4608 + e];
    }

    if (MODE == 0) {
        for (int e = tid; e < 16 * NPOS; e += 256) {
            int pair = e / NPOS, pos = e % NPOS;
            int row = pos / 35, xp = pos % 35;
            int gy = y_first - 1 + row, gx = xp - 1;
            bool ok = (gy >= 0) && (gy < 33) && (xp >= 1) && (xp < 34);
            uint32_t v = ok ? in[(size_t)(n_img * 16 + pair) * BBSZ + gy * 33 + gx] : 0u;
            hhi[pair * PSTR + pos] = v;
        }
    } else {
        for (int e = tid; e < 16 * NPOS; e += 256) {
            int pair = e / NPOS, pos = e % NPOS;
            int row = pos / 10, xp = pos % 10;
            int gy = y0t - 1 + row, gx = x0t - 1 + xp;
            bool ok = (gy >= 0) && (gy < HP) && (gx >= 0) && (gx < HP);
            uint32_t v = ok ? in[((size_t)(n_img * 16 + pair) * HP + gy) * HP + gx] : 0u;
            hhi[pair * PSTR + pos] = v;
        }
    }
    __syncthreads();

    int m_lo = wid * 16 + rg;
    int m_hi = m_lo + 8;
    int base_lo, base_hi;
    if (MODE == 0) {
        int pl = p0 + m_lo, ph = p0 + m_hi;
        int yl = pl / 33, yh = ph / 33;
        base_lo = (pl < BBSZ) ? (yl - y_first) * 35 + (pl - yl * 33) : 0;
        base_hi = (ph < BBSZ) ? (yh - y_first) * 35 + (ph - yh * 33) : 0;
    } else {
        base_lo = (m_lo >> 3) * 10 + (m_lo & 7);
        base_hi = (m_hi >> 3) * 10 + (m_hi & 7);
    }
    const uint32_t* phi_lo = hhi + l3 * PSTR + base_lo;
    const uint32_t* phi_hi = hhi + l3 * PSTR + base_hi;

    float acc[NT][4];
#pragma unroll
    for (int nt = 0; nt < NT; nt++)
#pragma unroll
        for (int i = 0; i < 4; i++) acc[nt][i] = 0.f;

#pragma unroll
    for (int t = 0; t < 9; t++) {
        const int toff = (t / 3) * WROW + (t % 3);
#pragma unroll
        for (int e2 = 0; e2 < 2; e2++) {
            const int c = 2 * t + e2;
            const int pb = e2 * 8 * PSTR + toff;
            uint32_t a0h = phi_lo[pb];
            uint32_t a1h = phi_hi[pb];
            uint32_t a2h = phi_lo[pb + 4 * PSTR];
            uint32_t a3h = phi_hi[pb + 4 * PSTR];
            const int kb = (c * 8 + l3) * WSTR + rg;
#pragma unroll
            for (int nt = 0; nt < NT; nt++) {
                uint32_t bh0 = wh[kb + nt * 8];
                uint32_t bh1 = wh[kb + 4 * WSTR + nt * 8];
                uint32_t bl0 = wl[kb + nt * 8];
                uint32_t bl1 = wl[kb + 4 * WSTR + nt * 8];
                HMMA16816(acc[nt], a0h, a1h, a2h, a3h, bh0, bh1);
                HMMA16816(acc[nt], a0h, a1h, a2h, a3h, bl0, bl1);
            }
        }
    }

    if (OUTM == 0) {
        uint32_t* out = (uint32_t*)outv;
#pragma unroll
        for (int nt = 0; nt < 4; nt++) {
            int oc = nt * 8 + kq;
            int p2 = nt * 4 + l3;
            float b0 = bias[oc], b1 = bias[oc + 1];
            uint32_t h0 = pack2(fmaxf(acc[nt][0] + b0, 0.f), fmaxf(acc[nt][1] + b1, 0.f));
            uint32_t h1 = pack2(fmaxf(acc[nt][2] + b0, 0.f), fmaxf(acc[nt][3] + b1, 0.f));
            if (MODE == 0) {
                int pl = p0 + m_lo, ph = p0 + m_hi;
                if (pl < BBSZ) out[(size_t)(n_img * 16 + p2) * BBSZ + pl] = h0;
                if (ph < BBSZ) out[(size_t)(n_img * 16 + p2) * BBSZ + ph] = h1;
            } else {
                int oyl = y0t + (m_lo >> 3), oxl = x0t + (m_lo & 7);
                int oyh = y0t + (m_hi >> 3), oxh = x0t + (m_hi & 7);
                if (oyl < HP) out[((size_t)(n_img * 16 + p2) * HP + oyl) * HP + oxl] = h0;
                if (oyh < HP) out[((size_t)(n_img * 16 + p2) * HP + oyh) * HP + oxh] = h1;
            }
        }
    } else if (OUTM == 1) {
        float* out = (float*)outv;
        if (l3 == 0) {
            int pl = p0 + m_lo, ph = p0 + m_hi;
            if (pl < BBSZ) out[(size_t)pl * NCOL + n_img] = acc[0][0];
            if (ph < BBSZ) out[(size_t)ph * NCOL + n_img] = acc[0][2];
        }
    } else {
        float* out = (float*)outv;
        if (l3 == 0) {
            int gyl = y0t + (m_lo >> 3), gxl = x0t + (m_lo & 7);
            int gyh = y0t + (m_hi >> 3), gxh = x0t + (m_hi & 7);
            if (gyl < HP) { int ix = ximg_idx(n_img, gyl, gxl); out[ix] -= acc[0][0]; }
            if (gyh < HP) { int ix = ximg_idx(n_img, gyh, gxh); out[ix] -= acc[0][2]; }
        }
    }
}

// ---------------- blockify / unblockify ---------------------------------------
__global__ void blockify_input_kernel(const float* __restrict__ in, float* __restrict__ Xb) {
    int idx = blockIdx.x * blockDim.x + threadIdx.x;
    if (idx >= BBSZ * NCOL) return;
    int r = idx / NCOL, n = idx % NCOL;
    int i = r / BQ, j = r % BQ;
    int l = n / (NH * NS), h = (n / NS) % NH, s = n % NS;
    Xb[idx] = in[(s * HP + h * BQ + i) * HP + l * BQ + j];
}
__global__ void unblockify_kernel(const float* __restrict__ X, float* __restrict__ img) {
    int idx = blockIdx.x * blockDim.x + threadIdx.x;
    if (idx >= IMGPIX) return;
    int s = idx / (HP * HP);
    int rem = idx % (HP * HP);
    int R = rem / HP, C = rem % HP;
    int h = R / BQ, i = R % BQ, l = C / BQ, j = C % BQ;
    img[idx] = X[(i * BQ + j) * NCOL + (l * (NH * NS) + h * NS + s)];
}

// ---------------- host driver --------------------------------------------------
extern "C" void kernel_launch(void* const* d_in, const int* in_sizes, int n_in,
                              void* d_out, int out_size) {
    const float* inputs = (const float*)d_in[0];
    const float* A      = (const float*)d_in[1];
    const float* Q      = (const float*)d_in[2];
    const float* steps  = (const float*)d_in[3];
    const float* den_w1 = (const float*)d_in[4];
    const float* den_b1 = (const float*)d_in[5];
    const float* den_w2 = (const float*)d_in[6];
    const float* den_b2 = (const float*)d_in[7];
    const float* den_w3 = (const float*)d_in[8];
    const float* den_b3 = (const float*)d_in[9];
    const float* den_w4 = (const float*)d_in[10];
    const float* deb_w1 = (const float*)d_in[11];
    const float* deb_b1 = (const float*)d_in[12];
    const float* deb_w2 = (const float*)d_in[13];
    const float* deb_b2 = (const float*)d_in[14];
    const float* deb_w3 = (const float*)d_in[15];
    const float* deb_b3 = (const float*)d_in[16];
    const float* deb_w4 = (const float*)d_in[17];
    int layers = in_sizes[3];

    float *pX, *pY, *pR, *pZ, *pN, *pAtA;
    uint32_t *pT1, *pT2, *pWp, *pmA, *pmAT, *pmQ, *pmAtA;
    cudaGetSymbolAddress((void**)&pX, g_X);
    cudaGetSymbolAddress((void**)&pY, g_y);
    cudaGetSymbolAddress((void**)&pR, g_r);
    cudaGetSymbolAddress((void**)&pZ, g_z);
    cudaGetSymbolAddress((void**)&pN, g_noise);
    cudaGetSymbolAddress((void**)&pAtA, g_AtA);
    cudaGetSymbolAddress((void**)&pT1, g_t1);
    cudaGetSymbolAddress((void**)&pT2, g_t2);
    cudaGetSymbolAddress((void**)&pWp, g_wpack);
    cudaGetSymbolAddress((void**)&pmA, g_mA);
    cudaGetSymbolAddress((void**)&pmAT, g_mAT);
    cudaGetSymbolAddress((void**)&pmQ, g_mQ);
    cudaGetSymbolAddress((void**)&pmAtA, g_mAtA);

    const int EW = 256;
    const int EG = (IMGPIX + EW - 1) / EW;

    const int SM0 = WBYTES + 16 * 248 * 4;
    const int SM1 = WBYTES + 16 * 184 * 4;
    const int SM12_0 = SM0 + ((9 * 37 + 3) & ~3) * 4 + 320 * 4;
    const int SM12_1 = SM1 + ((20 * 12 + 3) & ~3) * 4 + 320 * 4;
    cudaFuncSetAttribute(conv12_hmma<0>, cudaFuncAttributeMaxDynamicSharedMemorySize, SM12_0);
    cudaFuncSetAttribute(conv12_hmma<1>, cudaFuncAttributeMaxDynamicSharedMemorySize, SM12_1);
    cudaFuncSetAttribute(conv_hmma_kernel<0,0>, cudaFuncAttributeMaxDynamicSharedMemorySize, SM0);
    cudaFuncSetAttribute(conv_hmma_kernel<0,1>, cudaFuncAttributeMaxDynamicSharedMemorySize, SM0);
    cudaFuncSetAttribute(conv_hmma_kernel<1,0>, cudaFuncAttributeMaxDynamicSharedMemorySize, SM1);
    cudaFuncSetAttribute(conv_hmma_kernel<1,3>, cudaFuncAttributeMaxDynamicSharedMemorySize, SM1);

    const int G0 = NCOL * 9;
    const int G1 = 8 * 17 * 33;

    // plane sizes
    const int PS_A   = 545 * 272;
    const int PS_ATQ = 136 * 1092;
    const int PS_AtA = 545 * 1092;

    // init
    prep_weights<<<dim3(6, layers), 256>>>(den_w2, den_w3, den_w4,
                                           deb_w2, deb_w3, deb_w4, pWp);
    blockify_input_kernel<<<EG, EW>>>(inputs, pZ);
    prep_mat<<<580, 256>>>(A, 1089, 0, 272, 1089, 272, pmA);
    prep_mat<<<580, 256>>>(A, 1089, 1, 1089, 272, 1092, pmAT);
    prep_mat<<<580, 256>>>(Q, 272, 0, 1089, 272, 1092, pmQ);
    // y = A@Xb
    hgemm<0><<<dim3(16, 3), 256>>>(pmA, PS_A, 272, pZ, pY, 272, 512, 1089,
                                   nullptr, nullptr, nullptr, 0);
    // X = Q@y
    hgemm<0><<<dim3(16, 9), 256>>>(pmQ, PS_ATQ, 1092, pY, pX, 1089, 512, 272,
                                   nullptr, nullptr, nullptr, 0);
    // AtA = A^T @ A  (X operand = A as [272][1089])
    hgemm<0><<<dim3(35, 9), 256>>>(pmAT, PS_ATQ, 1092, A, pAtA, 1089, 1089, 272,
                                   nullptr, nullptr, nullptr, 0);
    prep_mat<<<2325, 256>>>(pAtA, 1089, 0, 1089, 1089, 1092, pmAtA);

    for (int n = 0; n < layers; n++) {
        const uint32_t* wp = pWp + (size_t)(n * 6) * 9216;
        // r = y - A@X
        hgemm<1><<<dim3(16, 3), 256>>>(pmA, PS_A, 272, pX, pR, 272, 512, 1089,
                                       pY, nullptr, nullptr, 0);
        // z = step*(A^T@r) + X
        hgemm<2><<<dim3(16, 9), 256>>>(pmAT, PS_ATQ, 1092, pR, pZ, 1089, 512, 272,
                                       pX, nullptr, steps, n);
        conv12_hmma<0><<<G0, 256, SM12_0>>>(pX, den_w1 + (size_t)n * 32 * 9,
                                            den_b1 + n * 32, wp + 0 * 9216,
                                            den_b2 + n * 32, pT1);
        conv_hmma_kernel<0,0><<<G0, 256, SM0>>>(pT1, wp + 1 * 9216, den_b3 + n * 32, pT2);
        conv_hmma_kernel<0,1><<<G0, 256, SM0>>>(pT2, wp + 2 * 9216, nullptr, pN);
        // X = z - step*(AtA@noise) + noise
        hgemm<3><<<dim3(16, 9), 256>>>(pmAtA, PS_AtA, 1092, pN, pX, 1089, 512, 1089,
                                       pZ, pN, steps, n);
        conv12_hmma<1><<<G1, 256, SM12_1>>>(pX, deb_w1 + (size_t)n * 32 * 9,
                                            deb_b1 + n * 32, wp + 3 * 9216,
                                            deb_b2 + n * 32, pT1);
        conv_hmma_kernel<1,0><<<G1, 256, SM1>>>(pT1, wp + 4 * 9216, deb_b3 + n * 32, pT2);
        conv_hmma_kernel<1,3><<<G1, 256, SM1>>>(pT2, wp + 5 * 9216, nullptr, pX);
    }

    unblockify_kernel<<<EG, EW>>>(pX, (float*)d_out);
}

// round 11
// speedup vs baseline: 5.4758x; 1.3926x over previous
#include <cuda_runtime.h>
#include <cuda_fp16.h>
#include <cstdint>

#define BQ   33
#define BBSZ 1089
#define NS   8
#define NH   8
#define NL   8
#define NCOL 512
#define MROW 272
#define HP   264
#define IMGPIX (NS*HP*HP)
#define PLN  8921088

// ---------------- scratch ----------------------------------------------------
__device__ float g_X[BBSZ * NCOL];
__device__ float g_y[MROW * NCOL];
__device__ float g_r[MROW * NCOL];
__device__ float g_z[BBSZ * NCOL];
__device__ float g_noise[BBSZ * NCOL];
__device__ float g_AtA[BBSZ * BBSZ];
__device__ uint32_t g_t1[PLN];
__device__ uint32_t g_t2[PLN];
__device__ uint32_t g_wpack[8 * 6 * 2 * 4608];
__device__ uint32_t g_mA[2 * 545 * 272];
__device__ uint32_t g_mAT[2 * 136 * 1092];
__device__ uint32_t g_mQ[2 * 136 * 1092];
__device__ uint32_t g_mAtA[2 * 545 * 1092];

// ---------------- HMMA helpers ------------------------------------------------
#define HMMA16816(c, a0, a1, a2, a3, b0, b1) \
    asm volatile("mma.sync.aligned.m16n8k16.row.col.f32.f16.f16.f32 " \
        "{%0,%1,%2,%3}, {%4,%5,%6,%7}, {%8,%9}, {%0,%1,%2,%3};" \
        : "+f"((c)[0]), "+f"((c)[1]), "+f"((c)[2]), "+f"((c)[3]) \
        : "r"(a0), "r"(a1), "r"(a2), "r"(a3), "r"(b0), "r"(b1))

__device__ __forceinline__ uint32_t h2bits(__half2 h) {
    return *reinterpret_cast<uint32_t*>(&h);
}
__device__ __forceinline__ uint32_t pack2(float x, float y) {
    __half2 h = __floats2half2_rn(x, y);
    return h2bits(h);
}
__device__ __forceinline__ uint32_t pack_split(float x, float y, uint32_t& lo) {
    __half2 h = __floats2half2_rn(x, y);
    __half2 l = __floats2half2_rn(x - __low2float(h), y - __high2float(h));
    lo = h2bits(l);
    return h2bits(h);
}

// ---------------- matrix pre-pack ----------------------------------------------
__global__ void prep_mat(const float* __restrict__ src, int lds, int trans,
                         int M, int K, int Mp, uint32_t* __restrict__ dst) {
    int PS = ((K + 1) >> 1) * Mp;
    for (int e = blockIdx.x * blockDim.x + threadIdx.x; e < PS;
         e += gridDim.x * blockDim.x) {
        int m = e % Mp, kp = e / Mp;
        int k0 = 2 * kp;
        float w0 = 0.f, w1 = 0.f;
        if (m < M) {
            if (k0 < K)     w0 = trans ? src[(size_t)k0 * lds + m] : src[(size_t)m * lds + k0];
            if (k0 + 1 < K) w1 = trans ? src[(size_t)(k0 + 1) * lds + m] : src[(size_t)m * lds + k0 + 1];
        }
        uint32_t lo;
        uint32_t hi = pack_split(w0, w1, lo);
        dst[e] = hi;
        dst[PS + e] = lo;
    }
}

// ---------------- HMMA GEMM (unchanged from R10) -------------------------------
template<int EPI>
__global__ void __launch_bounds__(256) hgemm(
    const uint32_t* __restrict__ Wp, int PS, int Mp,
    const float* __restrict__ X, float* __restrict__ C,
    int M, int N, int K,
    const float* __restrict__ E1, const float* __restrict__ E2,
    const float* __restrict__ stepsPtr, int stepIdx) {
    __shared__ uint2 Wsm[32 * 132];
    __shared__ uint2 Xsm[32 * 36];

    const int tid = threadIdx.x;
    const int wid = tid >> 5;
    const int lane = tid & 31;
    const int rg = lane >> 2;
    const int l3 = lane & 3;
    const int bn = blockIdx.x * 32;
    const int bm = blockIdx.y * 128;
    const int mloc = wid * 16 + rg;
    const int KpTot = (K + 1) >> 1;
    const int nCh = (KpTot + 31) >> 5;

    float acc[4][4];
#pragma unroll
    for (int nt = 0; nt < 4; nt++)
#pragma unroll
        for (int i = 0; i < 4; i++) acc[nt][i] = 0.f;

    for (int ch = 0; ch < nCh; ch++) {
        int kp0 = ch * 32;
#pragma unroll
        for (int i = 0; i < 16; i++) {
            int e = i * 256 + tid;
            int m = e & 127, kp = e >> 7;
            int kpg = kp0 + kp, gm = bm + m;
            uint32_t hi = 0, lo = 0;
            if (kpg < KpTot && gm < Mp) {
                size_t off = (size_t)kpg * Mp + gm;
                hi = Wp[off];
                lo = Wp[PS + off];
            }
            Wsm[kp * 132 + m] = make_uint2(hi, lo);
        }
#pragma unroll
        for (int i = 0; i < 4; i++) {
            int e = i * 256 + tid;
            int n = e & 31, kp = e >> 5;
            int kpg = kp0 + kp, gn = bn + n;
            float f0 = 0.f, f1 = 0.f;
            int k0 = 2 * kpg;
            if (gn < N && k0 < K) {
                f0 = X[(size_t)k0 * N + gn];
                if (k0 + 1 < K) f1 = X[(size_t)(k0 + 1) * N + gn];
            }
            uint32_t lo;
            uint32_t hi = pack_split(f0, f1, lo);
            Xsm[kp * 36 + n] = make_uint2(hi, lo);
        }
        __syncthreads();
#pragma unroll
        for (int c = 0; c < 4; c++) {
            int kl = c * 8 + l3;
            uint2 A0 = Wsm[kl * 132 + mloc];
            uint2 A1 = Wsm[kl * 132 + mloc + 8];
            uint2 A2 = Wsm[(kl + 4) * 132 + mloc];
            uint2 A3 = Wsm[(kl + 4) * 132 + mloc + 8];
#pragma unroll
            for (int nt = 0; nt < 4; nt++) {
                uint2 B0 = Xsm[kl * 36 + nt * 8 + rg];
                uint2 B1 = Xsm[(kl + 4) * 36 + nt * 8 + rg];
                HMMA16816(acc[nt], A0.x, A1.x, A2.x, A3.x, B0.x, B1.x);
                HMMA16816(acc[nt], A0.x, A1.x, A2.x, A3.x, B0.y, B1.y);
                HMMA16816(acc[nt], A0.y, A1.y, A2.y, A3.y, B0.x, B1.x);
            }
        }
        __syncthreads();
    }

    float step = (stepsPtr != nullptr) ? stepsPtr[stepIdx] : 0.f;
    int gml = bm + mloc;
#pragma unroll
    for (int nt = 0; nt < 4; nt++) {
        int gn0 = bn + nt * 8 + (l3 << 1);
#pragma unroll
        for (int half = 0; half < 2; half++) {
            int gm = gml + half * 8;
            if (gm >= M) continue;
#pragma unroll
            for (int q = 0; q < 2; q++) {
                int col = gn0 + q;
                if (col >= N) continue;
                size_t idx = (size_t)gm * N + col;
                float v = acc[nt][half * 2 + q];
                float o;
                if (EPI == 0)      o = v;
                else if (EPI == 1) o = E1[idx] - v;
                else if (EPI == 2) o = step * v + E1[idx];
                else               o = E1[idx] - step * v + E2[idx];
                C[idx] = o;
            }
        }
    }
}

// ---------------- conv weight pre-pack ------------------------------------------
__global__ void prep_weights(const float* __restrict__ dw2, const float* __restrict__ dw3,
                             const float* __restrict__ dw4, const float* __restrict__ bw2,
                             const float* __restrict__ bw3, const float* __restrict__ bw4,
                             uint32_t* __restrict__ outp) {
    int set = blockIdx.x, n = blockIdx.y;
    const float* wt; int coutr;
    switch (set) {
        case 0: wt = dw2 + (size_t)n * 32 * 32 * 9; coutr = 32; break;
        case 1: wt = dw3 + (size_t)n * 32 * 32 * 9; coutr = 32; break;
        case 2: wt = dw4 + (size_t)n * 32 * 9;      coutr = 1;  break;
        case 3: wt = bw2 + (size_t)n * 32 * 32 * 9; coutr = 32; break;
        case 4: wt = bw3 + (size_t)n * 32 * 32 * 9; coutr = 32; break;
        default: wt = bw4 + (size_t)n * 32 * 9;     coutr = 1;  break;
    }
    uint32_t* o = outp + ((size_t)n * 6 + set) * 9216;
    for (int e = threadIdx.x; e < 144 * 32; e += 256) {
        int kp = e >> 5, oc = e & 31;
        int k0 = 2 * kp;
        int tap = k0 >> 5, ic = k0 & 31;
        float w0 = 0.f, w1 = 0.f;
        if (oc < coutr) {
            w0 = wt[(oc * 32 + ic) * 9 + tap];
            w1 = wt[(oc * 32 + ic + 1) * 9 + tap];
        }
        uint32_t lo;
        uint32_t hi = pack_split(w0, w1, lo);
        o[e] = hi;
        o[4608 + e] = lo;
    }
}

__device__ __forceinline__ int ximg_idx(int s, int gy, int gx) {
    int h = gy / 33, i = gy % 33, l = gx / 33, j = gx % 33;
    return (i * 33 + j) * NCOL + l * (NH * NS) + h * NS + s;
}

// weight smem loaders ------------------------------------------------------------
// full 32-oc XOR-swizzled layout: idx = kp*32 + (oc ^ ((kp&3)<<3)), 36864 bytes
__device__ __forceinline__ void load_w_full(const uint32_t* wpack, uint32_t* wh,
                                            uint32_t* wl, int tid) {
    const uint4* wp4 = (const uint4*)wpack;
    uint4* s4h = (uint4*)wh;
    uint4* s4l = (uint4*)wl;
#pragma unroll
    for (int i = 0; i < 5; i++) {
        int u = i * 256 + tid;
        if (u < 1152) {
            int kp = u >> 3, oc4 = u & 7;
            int d = kp * 8 + (oc4 ^ ((kp & 3) << 1));
            s4h[d] = wp4[u];
            s4l[d] = wp4[1152 + u];
        }
    }
}
// compact 8-oc layout (conv4): idx = kp*8 + oc, 9216 bytes
__device__ __forceinline__ void load_w_c8(const uint32_t* wpack, uint32_t* wh,
                                          uint32_t* wl, int tid) {
    const uint4* wp4 = (const uint4*)wpack;
    uint4* s4h = (uint4*)wh;
    uint4* s4l = (uint4*)wl;
#pragma unroll
    for (int i = 0; i < 2; i++) {
        int u = i * 256 + tid;
        if (u < 288) {
            int kp = u >> 1, q = u & 1;
            s4h[kp * 2 + q] = wp4[kp * 8 + q];
            s4l[kp * 2 + q] = wp4[1152 + kp * 8 + q];
        }
    }
}

// ============ fused conv1+conv2 via HMMA =========================================
template<int MODE>
__global__ void __launch_bounds__(256)
conv12_hmma(const float* __restrict__ xin,
            const float* __restrict__ w1g,
            const float* __restrict__ b1g,
            const uint32_t* __restrict__ wpack,
            const float* __restrict__ bias2,
            uint32_t* __restrict__ out) {
    extern __shared__ char smem[];
    constexpr int PSTR = (MODE == 0) ? 248 : 184;
    constexpr int WROW = (MODE == 0) ? 35 : 10;
    constexpr int NPOS = (MODE == 0) ? 245 : 180;
    constexpr int RW   = (MODE == 0) ? 37 : 12;
    constexpr int RAWN = (MODE == 0) ? 9 * 37 : 20 * 12;
    constexpr int WB   = 2 * 144 * 32 * 4;          // 36864
    uint32_t* wh = (uint32_t*)smem;
    uint32_t* wl = wh + 144 * 32;
    uint32_t* hhi = (uint32_t*)(smem + WB);
    float* raw = (float*)(smem + WB + 16 * PSTR * 4);
    float* w1s = raw + ((RAWN + 3) & ~3);

    const int tid = threadIdx.x;
    const int wid = tid >> 5;
    const int lane = tid & 31;
    const int rg = lane >> 2;
    const int l3 = lane & 3;
    const int kq = l3 * 2;
    const int xb = rg ^ (l3 << 3);

    int n_img, p0 = 0, y_first = 0, y0t = 0, x0t = 0;
    if (MODE == 0) {
        n_img = blockIdx.x / 9;
        p0 = (blockIdx.x % 9) * 128;
        y_first = p0 / 33;
    } else {
        int b = blockIdx.x;
        int tx = b % 33; b /= 33;
        int ty = b % 17; b /= 17;
        n_img = b; y0t = ty * 16; x0t = tx * 8;
    }

    load_w_full(wpack, wh, wl, tid);
    for (int e = tid; e < 320; e += 256)
        w1s[e] = (e < 288) ? w1g[e] : b1g[e - 288];
    if (MODE == 0) {
        for (int e = tid; e < RAWN; e += 256) {
            int ry = e / RW, rx = e % RW;
            int gy = y_first - 2 + ry, gx = rx - 2;
            bool ok = (gy >= 0) && (gy < 33) && (gx >= 0) && (gx < 33);
            raw[e] = ok ? xin[(gy * 33 + gx) * NCOL + n_img] : 0.f;
        }
    } else {
        for (int e = tid; e < RAWN; e += 256) {
            int ry = e / RW, rx = e % RW;
            int gy = y0t - 2 + ry, gx = x0t - 2 + rx;
            bool ok = (gy >= 0) && (gy < HP) && (gx >= 0) && (gx < HP);
            raw[e] = ok ? xin[ximg_idx(n_img, gy, gx)] : 0.f;
        }
    }
    __syncthreads();

    if (tid < NPOS) {
        int hy = tid / WROW, hx = tid % WROW;
        int gy, gx, GHW;
        if (MODE == 0) { gy = y_first - 1 + hy; gx = hx - 1; GHW = 33; }
        else           { gy = y0t - 1 + hy;     gx = x0t - 1 + hx; GHW = HP; }
        bool valid = (gy >= 0) && (gy < GHW) && (gx >= 0) && (gx < ((MODE == 0) ? 33 : HP));
        float c1[32];
        if (valid) {
            float t0 = raw[hy * RW + hx],     t1 = raw[hy * RW + hx + 1],     t2 = raw[hy * RW + hx + 2];
            float t3 = raw[(hy+1) * RW + hx], t4 = raw[(hy+1) * RW + hx + 1], t5 = raw[(hy+1) * RW + hx + 2];
            float t6 = raw[(hy+2) * RW + hx], t7 = raw[(hy+2) * RW + hx + 1], t8 = raw[(hy+2) * RW + hx + 2];
#pragma unroll
            for (int oc = 0; oc < 32; oc++) {
                const float* w = w1s + oc * 9;
                float s = w1s[288 + oc];
                s += t0*w[0] + t1*w[1] + t2*w[2]
                   + t3*w[3] + t4*w[4] + t5*w[5]
                   + t6*w[6] + t7*w[7] + t8*w[8];
                c1[oc] = fmaxf(s, 0.f);
            }
        } else {
#pragma unroll
            for (int oc = 0; oc < 32; oc++) c1[oc] = 0.f;
        }
#pragma unroll
        for (int p = 0; p < 16; p++)
            hhi[p * PSTR + tid] = pack2(c1[2*p], c1[2*p+1]);
    }
    __syncthreads();

    int m_lo = wid * 16 + rg;
    int m_hi = m_lo + 8;
    int base_lo, base_hi;
    if (MODE == 0) {
        int pl = p0 + m_lo, ph = p0 + m_hi;
        int yl = pl / 33, yh = ph / 33;
        base_lo = (pl < BBSZ) ? (yl - y_first) * 35 + (pl - yl * 33) : 0;
        base_hi = (ph < BBSZ) ? (yh - y_first) * 35 + (ph - yh * 33) : 0;
    } else {
        base_lo = (m_lo >> 3) * 10 + (m_lo & 7);
        base_hi = (m_hi >> 3) * 10 + (m_hi & 7);
    }
    const uint32_t* phi_lo = hhi + l3 * PSTR + base_lo;
    const uint32_t* phi_hi = hhi + l3 * PSTR + base_hi;

    float acc[4][4];
#pragma unroll
    for (int nt = 0; nt < 4; nt++)
#pragma unroll
        for (int i = 0; i < 4; i++) acc[nt][i] = 0.f;

#pragma unroll
    for (int t = 0; t < 9; t++) {
        const int toff = (t / 3) * WROW + (t % 3);
#pragma unroll
        for (int e2 = 0; e2 < 2; e2++) {
            const int c = 2 * t + e2;
            const int pb = e2 * 8 * PSTR + toff;
            uint32_t a0h = phi_lo[pb];
            uint32_t a1h = phi_hi[pb];
            uint32_t a2h = phi_lo[pb + 4 * PSTR];
            uint32_t a3h = phi_hi[pb + 4 * PSTR];
            const int kidx = (c * 8 + l3) * 32;
#pragma unroll
            for (int nt = 0; nt < 4; nt++) {
                int xo = xb ^ (nt << 3);
                uint32_t bh0 = wh[kidx + xo];
                uint32_t bh1 = wh[kidx + 128 + xo];
                uint32_t bl0 = wl[kidx + xo];
                uint32_t bl1 = wl[kidx + 128 + xo];
                HMMA16816(acc[nt], a0h, a1h, a2h, a3h, bh0, bh1);
                HMMA16816(acc[nt], a0h, a1h, a2h, a3h, bl0, bl1);
            }
        }
    }

#pragma unroll
    for (int nt = 0; nt < 4; nt++) {
        int oc = nt * 8 + kq;
        int p2 = nt * 4 + l3;
        float b0 = bias2[oc], b1 = bias2[oc + 1];
        uint32_t h0 = pack2(fmaxf(acc[nt][0] + b0, 0.f), fmaxf(acc[nt][1] + b1, 0.f));
        uint32_t h1 = pack2(fmaxf(acc[nt][2] + b0, 0.f), fmaxf(acc[nt][3] + b1, 0.f));
        if (MODE == 0) {
            int pl = p0 + m_lo, ph = p0 + m_hi;
            if (pl < BBSZ) out[(size_t)(n_img * 16 + p2) * BBSZ + pl] = h0;
            if (ph < BBSZ) out[(size_t)(n_img * 16 + p2) * BBSZ + ph] = h1;
        } else {
            int oyl = y0t + (m_lo >> 3), oxl = x0t + (m_lo & 7);
            int oyh = y0t + (m_hi >> 3), oxh = x0t + (m_hi & 7);
            if (oyl < HP) out[((size_t)(n_img * 16 + p2) * HP + oyl) * HP + oxl] = h0;
            if (oyh < HP) out[((size_t)(n_img * 16 + p2) * HP + oyh) * HP + oxh] = h1;
        }
    }
}

// ---------------- HMMA conv on packed planes ------------------------------------
template<int MODE, int OUTM>
__global__ void __launch_bounds__(256)
conv_hmma_kernel(const uint32_t* __restrict__ in,
                 const uint32_t* __restrict__ wpack,
                 const float* __restrict__ bias,
                 void* __restrict__ outv) {
    extern __shared__ char smem[];
    constexpr int NT = (OUTM == 0) ? 4 : 1;
    constexpr int WWORDS = (NT == 4) ? 144 * 32 : 144 * 8;
    uint32_t* wh = (uint32_t*)smem;
    uint32_t* wl = wh + WWORDS;
    constexpr int PSTR = (MODE == 0) ? 248 : 184;
    constexpr int WROW = (MODE == 0) ? 35 : 10;
    constexpr int NPOS = (MODE == 0) ? 245 : 180;
    uint32_t* hhi = (uint32_t*)(smem + 2 * WWORDS * 4);

    const int tid = threadIdx.x;
    const int wid = tid >> 5;
    const int lane = tid & 31;
    const int rg = lane >> 2;
    const int l3 = lane & 3;
    const int kq = l3 * 2;
    const int xb = rg ^ (l3 << 3);

    int n_img, p0 = 0, y_first = 0, y0t = 0, x0t = 0;
    if (MODE == 0) {
        n_img = blockIdx.x / 9;
        p0 = (blockIdx.x % 9) * 128;
        y_first = p0 / 33;
    } else {
        int b = blockIdx.x;
        int tx = b % 33; b /= 33;
        int ty = b % 17; b /= 17;
        n_img = b; y0t = ty * 16; x0t = tx * 8;
    }

    if (NT == 4) load_w_full(wpack, wh, wl, tid);
    else         load_w_c8(wpack, wh, wl, tid);

    if (MODE == 0) {
        for (int e = tid; e < 16 * NPOS; e += 256) {
            int pair = e / NPOS, pos = e % NPOS;
            int row = pos / 35, xp = pos % 35;
            int gy = y_first - 1 + row, gx = xp - 1;
            bool ok = (gy >= 0) && (gy < 33) && (xp >= 1) && (xp < 34);
            uint32_t v = ok ? in[(size_t)(n_img * 16 + pair) * BBSZ + gy * 33 + gx] : 0u;
            hhi[pair * PSTR + pos] = v;
        }
    } else {
        for (int e = tid; e < 16 * NPOS; e += 256) {
            int pair = e / NPOS, pos = e % NPOS;
            int row = pos / 10, xp = pos % 10;
            int gy = y0t - 1 + row, gx = x0t - 1 + xp;
            bool ok = (gy >= 0) && (gy < HP) && (gx >= 0) && (gx < HP);
            uint32_t v = ok ? in[((size_t)(n_img * 16 + pair) * HP + gy) * HP + gx] : 0u;
            hhi[pair * PSTR + pos] = v;
        }
    }
    __syncthreads();

    int m_lo = wid * 16 + rg;
    int m_hi = m_lo + 8;
    int base_lo, base_hi;
    if (MODE == 0) {
        int pl = p0 + m_lo, ph = p0 + m_hi;
        int yl = pl / 33, yh = ph / 33;
        base_lo = (pl < BBSZ) ? (yl - y_first) * 35 + (pl - yl * 33) : 0;
        base_hi = (ph < BBSZ) ? (yh - y_first) * 35 + (ph - yh * 33) : 0;
    } else {
        base_lo = (m_lo >> 3) * 10 + (m_lo & 7);
        base_hi = (m_hi >> 3) * 10 + (m_hi & 7);
    }
    const uint32_t* phi_lo = hhi + l3 * PSTR + base_lo;
    const uint32_t* phi_hi = hhi + l3 * PSTR + base_hi;

    float acc[NT][4];
#pragma unroll
    for (int nt = 0; nt < NT; nt++)
#pragma unroll
        for (int i = 0; i < 4; i++) acc[nt][i] = 0.f;

#pragma unroll
    for (int t = 0; t < 9; t++) {
        const int toff = (t / 3) * WROW + (t % 3);
#pragma unroll
        for (int e2 = 0; e2 < 2; e2++) {
            const int c = 2 * t + e2;
            const int pb = e2 * 8 * PSTR + toff;
            uint32_t a0h = phi_lo[pb];
            uint32_t a1h = phi_hi[pb];
            uint32_t a2h = phi_lo[pb + 4 * PSTR];
            uint32_t a3h = phi_hi[pb + 4 * PSTR];
            if (NT == 4) {
                const int kidx = (c * 8 + l3) * 32;
#pragma unroll
                for (int nt = 0; nt < NT; nt++) {
                    int xo = xb ^ (nt << 3);
                    uint32_t bh0 = wh[kidx + xo];
                    uint32_t bh1 = wh[kidx + 128 + xo];
                    uint32_t bl0 = wl[kidx + xo];
                    uint32_t bl1 = wl[kidx + 128 + xo];
                    HMMA16816(acc[nt], a0h, a1h, a2h, a3h, bh0, bh1);
                    HMMA16816(acc[nt], a0h, a1h, a2h, a3h, bl0, bl1);
                }
            } else {
                const int kidx = (c * 8 + l3) * 8 + rg;
                uint32_t bh0 = wh[kidx];
                uint32_t bh1 = wh[kidx + 32];
                uint32_t bl0 = wl[kidx];
                uint32_t bl1 = wl[kidx + 32];
                HMMA16816(acc[0], a0h, a1h, a2h, a3h, bh0, bh1);
                HMMA16816(acc[0], a0h, a1h, a2h, a3h, bl0, bl1);
            }
        }
    }

    if (OUTM == 0) {
        uint32_t* out = (uint32_t*)outv;
#pragma unroll
        for (int nt = 0; nt < 4; nt++) {
            int oc = nt * 8 + kq;
            int p2 = nt * 4 + l3;
            float b0 = bias[oc], b1 = bias[oc + 1];
            uint32_t h0 = pack2(fmaxf(acc[nt][0] + b0, 0.f), fmaxf(acc[nt][1] + b1, 0.f));
            uint32_t h1 = pack2(fmaxf(acc[nt][2] + b0, 0.f), fmaxf(acc[nt][3] + b1, 0.f));
            if (MODE == 0) {
                int pl = p0 + m_lo, ph = p0 + m_hi;
                if (pl < BBSZ) out[(size_t)(n_img * 16 + p2) * BBSZ + pl] = h0;
                if (ph < BBSZ) out[(size_t)(n_img * 16 + p2) * BBSZ + ph] = h1;
            } else {
                int oyl = y0t + (m_lo >> 3), oxl = x0t + (m_lo & 7);
                int oyh = y0t + (m_hi >> 3), oxh = x0t + (m_hi & 7);
                if (oyl < HP) out[((size_t)(n_img * 16 + p2) * HP + oyl) * HP + oxl] = h0;
                if (oyh < HP) out[((size_t)(n_img * 16 + p2) * HP + oyh) * HP + oxh] = h1;
            }
        }
    } else if (OUTM == 1) {
        float* out = (float*)outv;
        if (l3 == 0) {
            int pl = p0 + m_lo, ph = p0 + m_hi;
            if (pl < BBSZ) out[(size_t)pl * NCOL + n_img] = acc[0][0];
            if (ph < BBSZ) out[(size_t)ph * NCOL + n_img] = acc[0][2];
        }
    } else {
        float* out = (float*)outv;
        if (l3 == 0) {
            int gyl = y0t + (m_lo >> 3), gxl = x0t + (m_lo & 7);
            int gyh = y0t + (m_hi >> 3), gxh = x0t + (m_hi & 7);
            if (gyl < HP) { int ix = ximg_idx(n_img, gyl, gxl); out[ix] -= acc[0][0]; }
            if (gyh < HP) { int ix = ximg_idx(n_img, gyh, gxh); out[ix] -= acc[0][2]; }
        }
    }
}

// ---------------- blockify / unblockify ------------------------------------------
__global__ void blockify_input_kernel(const float* __restrict__ in, float* __restrict__ Xb) {
    int idx = blockIdx.x * blockDim.x + threadIdx.x;
    if (idx >= BBSZ * NCOL) return;
    int r = idx / NCOL, n = idx % NCOL;
    int i = r / BQ, j = r % BQ;
    int l = n / (NH * NS), h = (n / NS) % NH, s = n % NS;
    Xb[idx] = in[(s * HP + h * BQ + i) * HP + l * BQ + j];
}
__global__ void unblockify_kernel(const float* __restrict__ X, float* __restrict__ img) {
    int idx = blockIdx.x * blockDim.x + threadIdx.x;
    if (idx >= IMGPIX) return;
    int s = idx / (HP * HP);
    int rem = idx % (HP * HP);
    int R = rem / HP, C = rem % HP;
    int h = R / BQ, i = R % BQ, l = C / BQ, j = C % BQ;
    img[idx] = X[(i * BQ + j) * NCOL + (l * (NH * NS) + h * NS + s)];
}

// ---------------- host driver ------------------------------------------------------
extern "C" void kernel_launch(void* const* d_in, const int* in_sizes, int n_in,
                              void* d_out, int out_size) {
    const float* inputs = (const float*)d_in[0];
    const float* A      = (const float*)d_in[1];
    const float* Q      = (const float*)d_in[2];
    const float* steps  = (const float*)d_in[3];
    const float* den_w1 = (const float*)d_in[4];
    const float* den_b1 = (const float*)d_in[5];
    const float* den_w2 = (const float*)d_in[6];
    const float* den_b2 = (const float*)d_in[7];
    const float* den_w3 = (const float*)d_in[8];
    const float* den_b3 = (const float*)d_in[9];
    const float* den_w4 = (const float*)d_in[10];
    const float* deb_w1 = (const float*)d_in[11];
    const float* deb_b1 = (const float*)d_in[12];
    const float* deb_w2 = (const float*)d_in[13];
    const float* deb_b2 = (const float*)d_in[14];
    const float* deb_w3 = (const float*)d_in[15];
    const float* deb_b3 = (const float*)d_in[16];
    const float* deb_w4 = (const float*)d_in[17];
    int layers = in_sizes[3];

    float *pX, *pY, *pR, *pZ, *pN, *pAtA;
    uint32_t *pT1, *pT2, *pWp, *pmA, *pmAT, *pmQ, *pmAtA;
    cudaGetSymbolAddress((void**)&pX, g_X);
    cudaGetSymbolAddress((void**)&pY, g_y);
    cudaGetSymbolAddress((void**)&pR, g_r);
    cudaGetSymbolAddress((void**)&pZ, g_z);
    cudaGetSymbolAddress((void**)&pN, g_noise);
    cudaGetSymbolAddress((void**)&pAtA, g_AtA);
    cudaGetSymbolAddress((void**)&pT1, g_t1);
    cudaGetSymbolAddress((void**)&pT2, g_t2);
    cudaGetSymbolAddress((void**)&pWp, g_wpack);
    cudaGetSymbolAddress((void**)&pmA, g_mA);
    cudaGetSymbolAddress((void**)&pmAT, g_mAT);
    cudaGetSymbolAddress((void**)&pmQ, g_mQ);
    cudaGetSymbolAddress((void**)&pmAtA, g_mAtA);

    const int EW = 256;
    const int EG = (IMGPIX + EW - 1) / EW;

    const int WB = 2 * 144 * 32 * 4;                 // 36864
    const int SM0 = WB + 16 * 248 * 4;               // 52736
    const int SM1 = WB + 16 * 184 * 4;               // 48640
    const int SM0C = 2 * 144 * 8 * 4 + 16 * 248 * 4; // 25088
    const int SM1C = 2 * 144 * 8 * 4 + 16 * 184 * 4; // 20992
    const int SM12_0 = SM0 + ((9 * 37 + 3) & ~3) * 4 + 320 * 4;   // 55360
    const int SM12_1 = SM1 + ((20 * 12 + 3) & ~3) * 4 + 320 * 4;  // 50880
    cudaFuncSetAttribute(conv12_hmma<0>, cudaFuncAttributeMaxDynamicSharedMemorySize, SM12_0);
    cudaFuncSetAttribute(conv12_hmma<1>, cudaFuncAttributeMaxDynamicSharedMemorySize, SM12_1);
    cudaFuncSetAttribute(conv_hmma_kernel<0,0>, cudaFuncAttributeMaxDynamicSharedMemorySize, SM0);
    cudaFuncSetAttribute(conv_hmma_kernel<0,1>, cudaFuncAttributeMaxDynamicSharedMemorySize, SM0C);
    cudaFuncSetAttribute(conv_hmma_kernel<1,0>, cudaFuncAttributeMaxDynamicSharedMemorySize, SM1);
    cudaFuncSetAttribute(conv_hmma_kernel<1,3>, cudaFuncAttributeMaxDynamicSharedMemorySize, SM1C);

    const int G0 = NCOL * 9;
    const int G1 = 8 * 17 * 33;

    const int PS_A   = 545 * 272;
    const int PS_ATQ = 136 * 1092;
    const int PS_AtA = 545 * 1092;

    prep_weights<<<dim3(6, layers), 256>>>(den_w2, den_w3, den_w4,
                                           deb_w2, deb_w3, deb_w4, pWp);
    blockify_input_kernel<<<EG, EW>>>(inputs, pZ);
    prep_mat<<<580, 256>>>(A, 1089, 0, 272, 1089, 272, pmA);
    prep_mat<<<580, 256>>>(A, 1089, 1, 1089, 272, 1092, pmAT);
    prep_mat<<<580, 256>>>(Q, 272, 0, 1089, 272, 1092, pmQ);
    hgemm<0><<<dim3(16, 3), 256>>>(pmA, PS_A, 272, pZ, pY, 272, 512, 1089,
                                   nullptr, nullptr, nullptr, 0);
    hgemm<0><<<dim3(16, 9), 256>>>(pmQ, PS_ATQ, 1092, pY, pX, 1089, 512, 272,
                                   nullptr, nullptr, nullptr, 0);
    hgemm<0><<<dim3(35, 9), 256>>>(pmAT, PS_ATQ, 1092, A, pAtA, 1089, 1089, 272,
                                   nullptr, nullptr, nullptr, 0);
    prep_mat<<<2325, 256>>>(pAtA, 1089, 0, 1089, 1089, 1092, pmAtA);

    for (int n = 0; n < layers; n++) {
        const uint32_t* wp = pWp + (size_t)(n * 6) * 9216;
        hgemm<1><<<dim3(16, 3), 256>>>(pmA, PS_A, 272, pX, pR, 272, 512, 1089,
                                       pY, nullptr, nullptr, 0);
        hgemm<2><<<dim3(16, 9), 256>>>(pmAT, PS_ATQ, 1092, pR, pZ, 1089, 512, 272,
                                       pX, nullptr, steps, n);
        conv12_hmma<0><<<G0, 256, SM12_0>>>(pX, den_w1 + (size_t)n * 32 * 9,
                                            den_b1 + n * 32, wp + 0 * 9216,
                                            den_b2 + n * 32, pT1);
        conv_hmma_kernel<0,0><<<G0, 256, SM0>>>(pT1, wp + 1 * 9216, den_b3 + n * 32, pT2);
        conv_hmma_kernel<0,1><<<G0, 256, SM0C>>>(pT2, wp + 2 * 9216, nullptr, pN);
        hgemm<3><<<dim3(16, 9), 256>>>(pmAtA, PS_AtA, 1092, pN, pX, 1089, 512, 1089,
                                       pZ, pN, steps, n);
        conv12_hmma<1><<<G1, 256, SM12_1>>>(pX, deb_w1 + (size_t)n * 32 * 9,
                                            deb_b1 + n * 32, wp + 3 * 9216,
                                            deb_b2 + n * 32, pT1);
        conv_hmma_kernel<1,0><<<G1, 256, SM1>>>(pT1, wp + 4 * 9216, deb_b3 + n * 32, pT2);
        conv_hmma_kernel<1,3><<<G1, 256, SM1C>>>(pT2, wp + 5 * 9216, nullptr, pX);
    }

    unblockify_kernel<<<EG, EW>>>(pX, (float*)d_out);
}

// round 12
// speedup vs baseline: 5.5575x; 1.0149x over previous
#include <cuda_runtime.h>
#include <cuda_fp16.h>
#include <cstdint>

#define BQ   33
#define BBSZ 1089
#define NS   8
#define NH   8
#define NL   8
#define NCOL 512
#define MROW 272
#define HP   264
#define IMGPIX (NS*HP*HP)
#define PLN  8921088

// ---------------- scratch ----------------------------------------------------
__device__ float g_X[BBSZ * NCOL];
__device__ float g_y[MROW * NCOL];
__device__ float g_r[MROW * NCOL];
__device__ float g_z[BBSZ * NCOL];
__device__ float g_noise[BBSZ * NCOL];
__device__ float g_AtA[BBSZ * BBSZ];
__device__ uint32_t g_t1[PLN];
__device__ uint32_t g_t2[PLN];
__device__ uint4 g_wpack4[8 * 6 * 2304];    // full: [layer][set][(c*4+l3)*32+oc]
__device__ uint4 g_wpack4c[8 * 2 * 576];    // compact conv4: [(c*4+l3)*8+oc]
__device__ uint32_t g_mA[2 * 545 * 272];
__device__ uint32_t g_mAT[2 * 136 * 1092];
__device__ uint32_t g_mQ[2 * 136 * 1092];
__device__ uint32_t g_mAtA[2 * 545 * 1092];

// ---------------- HMMA helpers ------------------------------------------------
#define HMMA16816(c, a0, a1, a2, a3, b0, b1) \
    asm volatile("mma.sync.aligned.m16n8k16.row.col.f32.f16.f16.f32 " \
        "{%0,%1,%2,%3}, {%4,%5,%6,%7}, {%8,%9}, {%0,%1,%2,%3};" \
        : "+f"((c)[0]), "+f"((c)[1]), "+f"((c)[2]), "+f"((c)[3]) \
        : "r"(a0), "r"(a1), "r"(a2), "r"(a3), "r"(b0), "r"(b1))

__device__ __forceinline__ uint32_t h2bits(__half2 h) {
    return *reinterpret_cast<uint32_t*>(&h);
}
__device__ __forceinline__ uint32_t pack2(float x, float y) {
    __half2 h = __floats2half2_rn(x, y);
    return h2bits(h);
}
__device__ __forceinline__ uint32_t pack_split(float x, float y, uint32_t& lo) {
    __half2 h = __floats2half2_rn(x, y);
    __half2 l = __floats2half2_rn(x - __low2float(h), y - __high2float(h));
    lo = h2bits(l);
    return h2bits(h);
}

// ---------------- matrix pre-pack ----------------------------------------------
__global__ void prep_mat(const float* __restrict__ src, int lds, int trans,
                         int M, int K, int Mp, uint32_t* __restrict__ dst) {
    int PS = ((K + 1) >> 1) * Mp;
    for (int e = blockIdx.x * blockDim.x + threadIdx.x; e < PS;
         e += gridDim.x * blockDim.x) {
        int m = e % Mp, kp = e / Mp;
        int k0 = 2 * kp;
        float w0 = 0.f, w1 = 0.f;
        if (m < M) {
            if (k0 < K)     w0 = trans ? src[(size_t)k0 * lds + m] : src[(size_t)m * lds + k0];
            if (k0 + 1 < K) w1 = trans ? src[(size_t)(k0 + 1) * lds + m] : src[(size_t)m * lds + k0 + 1];
        }
        uint32_t lo;
        uint32_t hi = pack_split(w0, w1, lo);
        dst[e] = hi;
        dst[PS + e] = lo;
    }
}

// ---------------- HMMA GEMM (unchanged) ------------------------------------------
template<int EPI>
__global__ void __launch_bounds__(256) hgemm(
    const uint32_t* __restrict__ Wp, int PS, int Mp,
    const float* __restrict__ X, float* __restrict__ C,
    int M, int N, int K,
    const float* __restrict__ E1, const float* __restrict__ E2,
    const float* __restrict__ stepsPtr, int stepIdx) {
    __shared__ uint2 Wsm[32 * 132];
    __shared__ uint2 Xsm[32 * 36];

    const int tid = threadIdx.x;
    const int wid = tid >> 5;
    const int lane = tid & 31;
    const int rg = lane >> 2;
    const int l3 = lane & 3;
    const int bn = blockIdx.x * 32;
    const int bm = blockIdx.y * 128;
    const int mloc = wid * 16 + rg;
    const int KpTot = (K + 1) >> 1;
    const int nCh = (KpTot + 31) >> 5;

    float acc[4][4];
#pragma unroll
    for (int nt = 0; nt < 4; nt++)
#pragma unroll
        for (int i = 0; i < 4; i++) acc[nt][i] = 0.f;

    for (int ch = 0; ch < nCh; ch++) {
        int kp0 = ch * 32;
#pragma unroll
        for (int i = 0; i < 16; i++) {
            int e = i * 256 + tid;
            int m = e & 127, kp = e >> 7;
            int kpg = kp0 + kp, gm = bm + m;
            uint32_t hi = 0, lo = 0;
            if (kpg < KpTot && gm < Mp) {
                size_t off = (size_t)kpg * Mp + gm;
                hi = Wp[off];
                lo = Wp[PS + off];
            }
            Wsm[kp * 132 + m] = make_uint2(hi, lo);
        }
#pragma unroll
        for (int i = 0; i < 4; i++) {
            int e = i * 256 + tid;
            int n = e & 31, kp = e >> 5;
            int kpg = kp0 + kp, gn = bn + n;
            float f0 = 0.f, f1 = 0.f;
            int k0 = 2 * kpg;
            if (gn < N && k0 < K) {
                f0 = X[(size_t)k0 * N + gn];
                if (k0 + 1 < K) f1 = X[(size_t)(k0 + 1) * N + gn];
            }
            uint32_t lo;
            uint32_t hi = pack_split(f0, f1, lo);
            Xsm[kp * 36 + n] = make_uint2(hi, lo);
        }
        __syncthreads();
#pragma unroll
        for (int c = 0; c < 4; c++) {
            int kl = c * 8 + l3;
            uint2 A0 = Wsm[kl * 132 + mloc];
            uint2 A1 = Wsm[kl * 132 + mloc + 8];
            uint2 A2 = Wsm[(kl + 4) * 132 + mloc];
            uint2 A3 = Wsm[(kl + 4) * 132 + mloc + 8];
#pragma unroll
            for (int nt = 0; nt < 4; nt++) {
                uint2 B0 = Xsm[kl * 36 + nt * 8 + rg];
                uint2 B1 = Xsm[(kl + 4) * 36 + nt * 8 + rg];
                HMMA16816(acc[nt], A0.x, A1.x, A2.x, A3.x, B0.x, B1.x);
                HMMA16816(acc[nt], A0.x, A1.x, A2.x, A3.x, B0.y, B1.y);
                HMMA16816(acc[nt], A0.y, A1.y, A2.y, A3.y, B0.x, B1.x);
            }
        }
        __syncthreads();
    }

    float step = (stepsPtr != nullptr) ? stepsPtr[stepIdx] : 0.f;
    int gml = bm + mloc;
#pragma unroll
    for (int nt = 0; nt < 4; nt++) {
        int gn0 = bn + nt * 8 + (l3 << 1);
#pragma unroll
        for (int half = 0; half < 2; half++) {
            int gm = gml + half * 8;
            if (gm >= M) continue;
#pragma unroll
            for (int q = 0; q < 2; q++) {
                int col = gn0 + q;
                if (col >= N) continue;
                size_t idx = (size_t)gm * N + col;
                float v = acc[nt][half * 2 + q];
                float o;
                if (EPI == 0)      o = v;
                else if (EPI == 1) o = E1[idx] - v;
                else if (EPI == 2) o = step * v + E1[idx];
                else               o = E1[idx] - step * v + E2[idx];
                C[idx] = o;
            }
        }
    }
}

// ---------------- conv weight pre-pack: uint4 fragments --------------------------
// set 0..5 -> full layout (2304 uint4): e = (c*4+l3)*32 + oc
//   value = (hi[kpA], hi[kpB], lo[kpA], lo[kpB]), kpA = c*8+l3, kpB = kpA+4
// set 6,7 -> compact conv4 (576 uint4): e = (c*4+l3)*8 + oc
__global__ void prep_weights4(const float* __restrict__ dw2, const float* __restrict__ dw3,
                              const float* __restrict__ dw4, const float* __restrict__ bw2,
                              const float* __restrict__ bw3, const float* __restrict__ bw4,
                              uint4* __restrict__ outF, uint4* __restrict__ outC) {
    int set = blockIdx.x, n = blockIdx.y;
    const float* wt; int coutr;
    switch (set) {
        case 0: wt = dw2 + (size_t)n * 32 * 32 * 9; coutr = 32; break;
        case 1: wt = dw3 + (size_t)n * 32 * 32 * 9; coutr = 32; break;
        case 2: wt = dw4 + (size_t)n * 32 * 9;      coutr = 1;  break;
        case 3: wt = bw2 + (size_t)n * 32 * 32 * 9; coutr = 32; break;
        case 4: wt = bw3 + (size_t)n * 32 * 32 * 9; coutr = 32; break;
        case 5: wt = bw4 + (size_t)n * 32 * 9;      coutr = 1;  break;
        case 6: wt = dw4 + (size_t)n * 32 * 9;      coutr = 1;  break;
        default: wt = bw4 + (size_t)n * 32 * 9;     coutr = 1;  break;
    }
    auto wval = [&](int kp, int oc, uint32_t& hi, uint32_t& lo) {
        int k0 = 2 * kp;
        int tap = k0 >> 5, ic = k0 & 31;
        float w0 = 0.f, w1 = 0.f;
        if (oc < coutr) {
            w0 = wt[(oc * 32 + ic) * 9 + tap];
            w1 = wt[(oc * 32 + ic + 1) * 9 + tap];
        }
        hi = pack_split(w0, w1, lo);
    };
    if (set < 6) {
        uint4* o = outF + ((size_t)n * 6 + set) * 2304;
        for (int e = threadIdx.x; e < 2304; e += 256) {
            int c = e >> 7, l3 = (e >> 5) & 3, oc = e & 31;
            int kpA = c * 8 + l3;
            uint32_t hA, lA, hB, lB;
            wval(kpA, oc, hA, lA);
            wval(kpA + 4, oc, hB, lB);
            o[e] = make_uint4(hA, hB, lA, lB);
        }
    } else {
        uint4* o = outC + ((size_t)n * 2 + (set - 6)) * 576;
        for (int e = threadIdx.x; e < 576; e += 256) {
            int c = e >> 5, l3 = (e >> 3) & 3, oc = e & 7;
            int kpA = c * 8 + l3;
            uint32_t hA, lA, hB, lB;
            wval(kpA, oc, hA, lA);
            wval(kpA + 4, oc, hB, lB);
            o[e] = make_uint4(hA, hB, lA, lB);
        }
    }
}

__device__ __forceinline__ int ximg_idx(int s, int gy, int gx) {
    int h = gy / 33, i = gy % 33, l = gx / 33, j = gx % 33;
    return (i * 33 + j) * NCOL + l * (NH * NS) + h * NS + s;
}

// smem weight loaders: full stride 34, compact stride 10 (conflict-free LDS.128)
#define WSF_BYTES (72 * 34 * 16)   // 39168
#define WSC_BYTES (72 * 10 * 16)   // 11520
__device__ __forceinline__ void load_w4(const uint4* __restrict__ wp,
                                        uint4* __restrict__ ws, int tid) {
#pragma unroll
    for (int i = 0; i < 9; i++) {
        int e = i * 256 + tid;
        ws[(e >> 5) * 34 + (e & 31)] = wp[e];
    }
}
__device__ __forceinline__ void load_w4c(const uint4* __restrict__ wp,
                                         uint4* __restrict__ ws, int tid) {
#pragma unroll
    for (int i = 0; i < 3; i++) {
        int e = i * 256 + tid;
        if (e < 576) ws[(e >> 3) * 10 + (e & 7)] = wp[e];
    }
}

// ============ fused conv1+conv2 via HMMA =========================================
template<int MODE>
__global__ void __launch_bounds__(256)
conv12_hmma(const float* __restrict__ xin,
            const float* __restrict__ w1g,
            const float* __restrict__ b1g,
            const uint4* __restrict__ wpack,
            const float* __restrict__ bias2,
            uint32_t* __restrict__ out) {
    extern __shared__ char smem[];
    constexpr int PSTR = (MODE == 0) ? 248 : 184;
    constexpr int WROW = (MODE == 0) ? 35 : 10;
    constexpr int NPOS = (MODE == 0) ? 245 : 180;
    constexpr int RW   = (MODE == 0) ? 37 : 12;
    constexpr int RAWN = (MODE == 0) ? 9 * 37 : 20 * 12;
    uint4* ws = (uint4*)smem;
    uint32_t* hhi = (uint32_t*)(smem + WSF_BYTES);
    float* raw = (float*)(smem + WSF_BYTES + 16 * PSTR * 4);
    float* w1s = raw + ((RAWN + 3) & ~3);

    const int tid = threadIdx.x;
    const int wid = tid >> 5;
    const int lane = tid & 31;
    const int rg = lane >> 2;
    const int l3 = lane & 3;
    const int kq = l3 * 2;

    int n_img, p0 = 0, y_first = 0, y0t = 0, x0t = 0;
    if (MODE == 0) {
        n_img = blockIdx.x / 9;
        p0 = (blockIdx.x % 9) * 128;
        y_first = p0 / 33;
    } else {
        int b = blockIdx.x;
        int tx = b % 33; b /= 33;
        int ty = b % 17; b /= 17;
        n_img = b; y0t = ty * 16; x0t = tx * 8;
    }

    load_w4(wpack, ws, tid);
    for (int e = tid; e < 320; e += 256)
        w1s[e] = (e < 288) ? w1g[e] : b1g[e - 288];
    if (MODE == 0) {
        for (int e = tid; e < RAWN; e += 256) {
            int ry = e / RW, rx = e % RW;
            int gy = y_first - 2 + ry, gx = rx - 2;
            bool ok = (gy >= 0) && (gy < 33) && (gx >= 0) && (gx < 33);
            raw[e] = ok ? xin[(gy * 33 + gx) * NCOL + n_img] : 0.f;
        }
    } else {
        for (int e = tid; e < RAWN; e += 256) {
            int ry = e / RW, rx = e % RW;
            int gy = y0t - 2 + ry, gx = x0t - 2 + rx;
            bool ok = (gy >= 0) && (gy < HP) && (gx >= 0) && (gx < HP);
            raw[e] = ok ? xin[ximg_idx(n_img, gy, gx)] : 0.f;
        }
    }
    __syncthreads();

    if (tid < NPOS) {
        int hy = tid / WROW, hx = tid % WROW;
        int gy, gx, GHW;
        if (MODE == 0) { gy = y_first - 1 + hy; gx = hx - 1; GHW = 33; }
        else           { gy = y0t - 1 + hy;     gx = x0t - 1 + hx; GHW = HP; }
        bool valid = (gy >= 0) && (gy < GHW) && (gx >= 0) && (gx < ((MODE == 0) ? 33 : HP));
        float c1[32];
        if (valid) {
            float t0 = raw[hy * RW + hx],     t1 = raw[hy * RW + hx + 1],     t2 = raw[hy * RW + hx + 2];
            float t3 = raw[(hy+1) * RW + hx], t4 = raw[(hy+1) * RW + hx + 1], t5 = raw[(hy+1) * RW + hx + 2];
            float t6 = raw[(hy+2) * RW + hx], t7 = raw[(hy+2) * RW + hx + 1], t8 = raw[(hy+2) * RW + hx + 2];
#pragma unroll
            for (int oc = 0; oc < 32; oc++) {
                const float* w = w1s + oc * 9;
                float s = w1s[288 + oc];
                s += t0*w[0] + t1*w[1] + t2*w[2]
                   + t3*w[3] + t4*w[4] + t5*w[5]
                   + t6*w[6] + t7*w[7] + t8*w[8];
                c1[oc] = fmaxf(s, 0.f);
            }
        } else {
#pragma unroll
            for (int oc = 0; oc < 32; oc++) c1[oc] = 0.f;
        }
#pragma unroll
        for (int p = 0; p < 16; p++)
            hhi[p * PSTR + tid] = pack2(c1[2*p], c1[2*p+1]);
    }
    __syncthreads();

    int m_lo = wid * 16 + rg;
    int m_hi = m_lo + 8;
    int base_lo, base_hi;
    if (MODE == 0) {
        int pl = p0 + m_lo, ph = p0 + m_hi;
        int yl = pl / 33, yh = ph / 33;
        base_lo = (pl < BBSZ) ? (yl - y_first) * 35 + (pl - yl * 33) : 0;
        base_hi = (ph < BBSZ) ? (yh - y_first) * 35 + (ph - yh * 33) : 0;
    } else {
        base_lo = (m_lo >> 3) * 10 + (m_lo & 7);
        base_hi = (m_hi >> 3) * 10 + (m_hi & 7);
    }
    const uint32_t* phi_lo = hhi + l3 * PSTR + base_lo;
    const uint32_t* phi_hi = hhi + l3 * PSTR + base_hi;

    float acc[4][4];
#pragma unroll
    for (int nt = 0; nt < 4; nt++)
#pragma unroll
        for (int i = 0; i < 4; i++) acc[nt][i] = 0.f;

#pragma unroll
    for (int t = 0; t < 9; t++) {
        const int toff = (t / 3) * WROW + (t % 3);
#pragma unroll
        for (int e2 = 0; e2 < 2; e2++) {
            const int c = 2 * t + e2;
            const int pb = e2 * 8 * PSTR + toff;
            uint32_t a0h = phi_lo[pb];
            uint32_t a1h = phi_hi[pb];
            uint32_t a2h = phi_lo[pb + 4 * PSTR];
            uint32_t a3h = phi_hi[pb + 4 * PSTR];
            const int row = (c * 4 + l3) * 34 + rg;
#pragma unroll
            for (int nt = 0; nt < 4; nt++) {
                uint4 B = ws[row + nt * 8];
                HMMA16816(acc[nt], a0h, a1h, a2h, a3h, B.x, B.y);
                HMMA16816(acc[nt], a0h, a1h, a2h, a3h, B.z, B.w);
            }
        }
    }

#pragma unroll
    for (int nt = 0; nt < 4; nt++) {
        int oc = nt * 8 + kq;
        int p2 = nt * 4 + l3;
        float b0 = bias2[oc], b1 = bias2[oc + 1];
        uint32_t h0 = pack2(fmaxf(acc[nt][0] + b0, 0.f), fmaxf(acc[nt][1] + b1, 0.f));
        uint32_t h1 = pack2(fmaxf(acc[nt][2] + b0, 0.f), fmaxf(acc[nt][3] + b1, 0.f));
        if (MODE == 0) {
            int pl = p0 + m_lo, ph = p0 + m_hi;
            if (pl < BBSZ) out[(size_t)(n_img * 16 + p2) * BBSZ + pl] = h0;
            if (ph < BBSZ) out[(size_t)(n_img * 16 + p2) * BBSZ + ph] = h1;
        } else {
            int oyl = y0t + (m_lo >> 3), oxl = x0t + (m_lo & 7);
            int oyh = y0t + (m_hi >> 3), oxh = x0t + (m_hi & 7);
            if (oyl < HP) out[((size_t)(n_img * 16 + p2) * HP + oyl) * HP + oxl] = h0;
            if (oyh < HP) out[((size_t)(n_img * 16 + p2) * HP + oyh) * HP + oxh] = h1;
        }
    }
}

// ---------------- HMMA conv on packed planes ------------------------------------
// OUTM 0: packed planes + bias + relu ; 1: 1ch col-major ; 3: X -= D
template<int MODE, int OUTM>
__global__ void __launch_bounds__(256)
conv_hmma_kernel(const uint32_t* __restrict__ in,
                 const uint4* __restrict__ wpack,
                 const float* __restrict__ bias,
                 void* __restrict__ outv) {
    extern __shared__ char smem[];
    constexpr int NT = (OUTM == 0) ? 4 : 1;
    constexpr int WB = (NT == 4) ? WSF_BYTES : WSC_BYTES;
    uint4* ws = (uint4*)smem;
    constexpr int PSTR = (MODE == 0) ? 248 : 184;
    constexpr int WROW = (MODE == 0) ? 35 : 10;
    constexpr int NPOS = (MODE == 0) ? 245 : 180;
    uint32_t* hhi = (uint32_t*)(smem + WB);

    const int tid = threadIdx.x;
    const int wid = tid >> 5;
    const int lane = tid & 31;
    const int rg = lane >> 2;
    const int l3 = lane & 3;
    const int kq = l3 * 2;

    int n_img, p0 = 0, y_first = 0, y0t = 0, x0t = 0;
    if (MODE == 0) {
        n_img = blockIdx.x / 9;
        p0 = (blockIdx.x % 9) * 128;
        y_first = p0 / 33;
    } else {
        int b = blockIdx.x;
        int tx = b % 33; b /= 33;
        int ty = b % 17; b /= 17;
        n_img = b; y0t = ty * 16; x0t = tx * 8;
    }

    if (NT == 4) load_w4(wpack, ws, tid);
    else         load_w4c(wpack, ws, tid);

    if (MODE == 0) {
        for (int e = tid; e < 16 * NPOS; e += 256) {
            int pair = e / NPOS, pos = e % NPOS;
            int row = pos / 35, xp = pos % 35;
            int gy = y_first - 1 + row, gx = xp - 1;
            bool ok = (gy >= 0) && (gy < 33) && (xp >= 1) && (xp < 34);
            uint32_t v = ok ? in[(size_t)(n_img * 16 + pair) * BBSZ + gy * 33 + gx] : 0u;
            hhi[pair * PSTR + pos] = v;
        }
    } else {
        for (int e = tid; e < 16 * NPOS; e += 256) {
            int pair = e / NPOS, pos = e % NPOS;
            int row = pos / 10, xp = pos % 10;
            int gy = y0t - 1 + row, gx = x0t - 1 + xp;
            bool ok = (gy >= 0) && (gy < HP) && (gx >= 0) && (gx < HP);
            uint32_t v = ok ? in[((size_t)(n_img * 16 + pair) * HP + gy) * HP + gx] : 0u;
            hhi[pair * PSTR + pos] = v;
        }
    }
    __syncthreads();

    int m_lo = wid * 16 + rg;
    int m_hi = m_lo + 8;
    int base_lo, base_hi;
    if (MODE == 0) {
        int pl = p0 + m_lo, ph = p0 + m_hi;
        int yl = pl / 33, yh = ph / 33;
        base_lo = (pl < BBSZ) ? (yl - y_first) * 35 + (pl - yl * 33) : 0;
        base_hi = (ph < BBSZ) ? (yh - y_first) * 35 + (ph - yh * 33) : 0;
    } else {
        base_lo = (m_lo >> 3) * 10 + (m_lo & 7);
        base_hi = (m_hi >> 3) * 10 + (m_hi & 7);
    }
    const uint32_t* phi_lo = hhi + l3 * PSTR + base_lo;
    const uint32_t* phi_hi = hhi + l3 * PSTR + base_hi;

    float acc[NT][4];
#pragma unroll
    for (int nt = 0; nt < NT; nt++)
#pragma unroll
        for (int i = 0; i < 4; i++) acc[nt][i] = 0.f;

#pragma unroll
    for (int t = 0; t < 9; t++) {
        const int toff = (t / 3) * WROW + (t % 3);
#pragma unroll
        for (int e2 = 0; e2 < 2; e2++) {
            const int c = 2 * t + e2;
            const int pb = e2 * 8 * PSTR + toff;
            uint32_t a0h = phi_lo[pb];
            uint32_t a1h = phi_hi[pb];
            uint32_t a2h = phi_lo[pb + 4 * PSTR];
            uint32_t a3h = phi_hi[pb + 4 * PSTR];
            if (NT == 4) {
                const int row = (c * 4 + l3) * 34 + rg;
#pragma unroll
                for (int nt = 0; nt < NT; nt++) {
                    uint4 B = ws[row + nt * 8];
                    HMMA16816(acc[nt], a0h, a1h, a2h, a3h, B.x, B.y);
                    HMMA16816(acc[nt], a0h, a1h, a2h, a3h, B.z, B.w);
                }
            } else {
                uint4 B = ws[(c * 4 + l3) * 10 + rg];
                HMMA16816(acc[0], a0h, a1h, a2h, a3h, B.x, B.y);
                HMMA16816(acc[0], a0h, a1h, a2h, a3h, B.z, B.w);
            }
        }
    }

    if (OUTM == 0) {
        uint32_t* out = (uint32_t*)outv;
#pragma unroll
        for (int nt = 0; nt < 4; nt++) {
            int oc = nt * 8 + kq;
            int p2 = nt * 4 + l3;
            float b0 = bias[oc], b1 = bias[oc + 1];
            uint32_t h0 = pack2(fmaxf(acc[nt][0] + b0, 0.f), fmaxf(acc[nt][1] + b1, 0.f));
            uint32_t h1 = pack2(fmaxf(acc[nt][2] + b0, 0.f), fmaxf(acc[nt][3] + b1, 0.f));
            if (MODE == 0) {
                int pl = p0 + m_lo, ph = p0 + m_hi;
                if (pl < BBSZ) out[(size_t)(n_img * 16 + p2) * BBSZ + pl] = h0;
                if (ph < BBSZ) out[(size_t)(n_img * 16 + p2) * BBSZ + ph] = h1;
            } else {
                int oyl = y0t + (m_lo >> 3), oxl = x0t + (m_lo & 7);
                int oyh = y0t + (m_hi >> 3), oxh = x0t + (m_hi & 7);
                if (oyl < HP) out[((size_t)(n_img * 16 + p2) * HP + oyl) * HP + oxl] = h0;
                if (oyh < HP) out[((size_t)(n_img * 16 + p2) * HP + oyh) * HP + oxh] = h1;
            }
        }
    } else if (OUTM == 1) {
        float* out = (float*)outv;
        if (l3 == 0) {
            int pl = p0 + m_lo, ph = p0 + m_hi;
            if (pl < BBSZ) out[(size_t)pl * NCOL + n_img] = acc[0][0];
            if (ph < BBSZ) out[(size_t)ph * NCOL + n_img] = acc[0][2];
        }
    } else {
        float* out = (float*)outv;
        if (l3 == 0) {
            int gyl = y0t + (m_lo >> 3), gxl = x0t + (m_lo & 7);
            int gyh = y0t + (m_hi >> 3), gxh = x0t + (m_hi & 7);
            if (gyl < HP) { int ix = ximg_idx(n_img, gyl, gxl); out[ix] -= acc[0][0]; }
            if (gyh < HP) { int ix = ximg_idx(n_img, gyh, gxh); out[ix] -= acc[0][2]; }
        }
    }
}

// ---------------- blockify / unblockify ------------------------------------------
__global__ void blockify_input_kernel(const float* __restrict__ in, float* __restrict__ Xb) {
    int idx = blockIdx.x * blockDim.x + threadIdx.x;
    if (idx >= BBSZ * NCOL) return;
    int r = idx / NCOL, n = idx % NCOL;
    int i = r / BQ, j = r % BQ;
    int l = n / (NH * NS), h = (n / NS) % NH, s = n % NS;
    Xb[idx] = in[(s * HP + h * BQ + i) * HP + l * BQ + j];
}
__global__ void unblockify_kernel(const float* __restrict__ X, float* __restrict__ img) {
    int idx = blockIdx.x * blockDim.x + threadIdx.x;
    if (idx >= IMGPIX) return;
    int s = idx / (HP * HP);
    int rem = idx % (HP * HP);
    int R = rem / HP, C = rem % HP;
    int h = R / BQ, i = R % BQ, l = C / BQ, j = C % BQ;
    img[idx] = X[(i * BQ + j) * NCOL + (l * (NH * NS) + h * NS + s)];
}

// ---------------- host driver ------------------------------------------------------
extern "C" void kernel_launch(void* const* d_in, const int* in_sizes, int n_in,
                              void* d_out, int out_size) {
    const float* inputs = (const float*)d_in[0];
    const float* A      = (const float*)d_in[1];
    const float* Q      = (const float*)d_in[2];
    const float* steps  = (const float*)d_in[3];
    const float* den_w1 = (const float*)d_in[4];
    const float* den_b1 = (const float*)d_in[5];
    const float* den_w2 = (const float*)d_in[6];
    const float* den_b2 = (const float*)d_in[7];
    const float* den_w3 = (const float*)d_in[8];
    const float* den_b3 = (const float*)d_in[9];
    const float* den_w4 = (const float*)d_in[10];
    const float* deb_w1 = (const float*)d_in[11];
    const float* deb_b1 = (const float*)d_in[12];
    const float* deb_w2 = (const float*)d_in[13];
    const float* deb_b2 = (const float*)d_in[14];
    const float* deb_w3 = (const float*)d_in[15];
    const float* deb_b3 = (const float*)d_in[16];
    const float* deb_w4 = (const float*)d_in[17];
    int layers = in_sizes[3];

    float *pX, *pY, *pR, *pZ, *pN, *pAtA;
    uint32_t *pT1, *pT2, *pmA, *pmAT, *pmQ, *pmAtA;
    uint4 *pW4, *pW4c;
    cudaGetSymbolAddress((void**)&pX, g_X);
    cudaGetSymbolAddress((void**)&pY, g_y);
    cudaGetSymbolAddress((void**)&pR, g_r);
    cudaGetSymbolAddress((void**)&pZ, g_z);
    cudaGetSymbolAddress((void**)&pN, g_noise);
    cudaGetSymbolAddress((void**)&pAtA, g_AtA);
    cudaGetSymbolAddress((void**)&pT1, g_t1);
    cudaGetSymbolAddress((void**)&pT2, g_t2);
    cudaGetSymbolAddress((void**)&pW4, g_wpack4);
    cudaGetSymbolAddress((void**)&pW4c, g_wpack4c);
    cudaGetSymbolAddress((void**)&pmA, g_mA);
    cudaGetSymbolAddress((void**)&pmAT, g_mAT);
    cudaGetSymbolAddress((void**)&pmQ, g_mQ);
    cudaGetSymbolAddress((void**)&pmAtA, g_mAtA);

    const int EW = 256;
    const int EG = (IMGPIX + EW - 1) / EW;

    const int SM0 = WSF_BYTES + 16 * 248 * 4;               // 55040
    const int SM1 = WSF_BYTES + 16 * 184 * 4;               // 50944
    const int SM0C = WSC_BYTES + 16 * 248 * 4;              // 27392
    const int SM1C = WSC_BYTES + 16 * 184 * 4;              // 23296
    const int SM12_0 = SM0 + ((9 * 37 + 3) & ~3) * 4 + 320 * 4;   // 57664
    const int SM12_1 = SM1 + ((20 * 12 + 3) & ~3) * 4 + 320 * 4;  // 53184
    cudaFuncSetAttribute(conv12_hmma<0>, cudaFuncAttributeMaxDynamicSharedMemorySize, SM12_0);
    cudaFuncSetAttribute(conv12_hmma<1>, cudaFuncAttributeMaxDynamicSharedMemorySize, SM12_1);
    cudaFuncSetAttribute(conv_hmma_kernel<0,0>, cudaFuncAttributeMaxDynamicSharedMemorySize, SM0);
    cudaFuncSetAttribute(conv_hmma_kernel<0,1>, cudaFuncAttributeMaxDynamicSharedMemorySize, SM0C);
    cudaFuncSetAttribute(conv_hmma_kernel<1,0>, cudaFuncAttributeMaxDynamicSharedMemorySize, SM1);
    cudaFuncSetAttribute(conv_hmma_kernel<1,3>, cudaFuncAttributeMaxDynamicSharedMemorySize, SM1C);

    const int G0 = NCOL * 9;
    const int G1 = 8 * 17 * 33;

    const int PS_A   = 545 * 272;
    const int PS_ATQ = 136 * 1092;
    const int PS_AtA = 545 * 1092;

    prep_weights4<<<dim3(8, layers), 256>>>(den_w2, den_w3, den_w4,
                                            deb_w2, deb_w3, deb_w4, pW4, pW4c);
    blockify_input_kernel<<<EG, EW>>>(inputs, pZ);
    prep_mat<<<580, 256>>>(A, 1089, 0, 272, 1089, 272, pmA);
    prep_mat<<<580, 256>>>(A, 1089, 1, 1089, 272, 1092, pmAT);
    prep_mat<<<580, 256>>>(Q, 272, 0, 1089, 272, 1092, pmQ);
    hgemm<0><<<dim3(16, 3), 256>>>(pmA, PS_A, 272, pZ, pY, 272, 512, 1089,
                                   nullptr, nullptr, nullptr, 0);
    hgemm<0><<<dim3(16, 9), 256>>>(pmQ, PS_ATQ, 1092, pY, pX, 1089, 512, 272,
                                   nullptr, nullptr, nullptr, 0);
    hgemm<0><<<dim3(35, 9), 256>>>(pmAT, PS_ATQ, 1092, A, pAtA, 1089, 1089, 272,
                                   nullptr, nullptr, nullptr, 0);
    prep_mat<<<2325, 256>>>(pAtA, 1089, 0, 1089, 1089, 1092, pmAtA);

    for (int n = 0; n < layers; n++) {
        const uint4* wf = pW4 + (size_t)(n * 6) * 2304;
        const uint4* wc = pW4c + (size_t)(n * 2) * 576;
        hgemm<1><<<dim3(16, 3), 256>>>(pmA, PS_A, 272, pX, pR, 272, 512, 1089,
                                       pY, nullptr, nullptr, 0);
        hgemm<2><<<dim3(16, 9), 256>>>(pmAT, PS_ATQ, 1092, pR, pZ, 1089, 512, 272,
                                       pX, nullptr, steps, n);
        conv12_hmma<0><<<G0, 256, SM12_0>>>(pX, den_w1 + (size_t)n * 32 * 9,
                                            den_b1 + n * 32, wf + 0 * 2304,
                                            den_b2 + n * 32, pT1);
        conv_hmma_kernel<0,0><<<G0, 256, SM0>>>(pT1, wf + 1 * 2304, den_b3 + n * 32, pT2);
        conv_hmma_kernel<0,1><<<G0, 256, SM0C>>>(pT2, wc + 0 * 576, nullptr, pN);
        hgemm<3><<<dim3(16, 9), 256>>>(pmAtA, PS_AtA, 1092, pN, pX, 1089, 512, 1089,
                                       pZ, pN, steps, n);
        conv12_hmma<1><<<G1, 256, SM12_1>>>(pX, deb_w1 + (size_t)n * 32 * 9,
                                            deb_b1 + n * 32, wf + 3 * 2304,
                                            deb_b2 + n * 32, pT1);
        conv_hmma_kernel<1,0><<<G1, 256, SM1>>>(pT1, wf + 4 * 2304, deb_b3 + n * 32, pT2);
        conv_hmma_kernel<1,3><<<G1, 256, SM1C>>>(pT2, wc + 1 * 576, nullptr, pX);
    }

    unblockify_kernel<<<EG, EW>>>(pX, (float*)d_out);
}